// round 6
// baseline (speedup 1.0000x reference)
#include <cuda_runtime.h>
#include <math.h>

// ---------------- problem constants ----------------
#define DIMC   512
#define NHEADS 16
#define HD     32
#define NTOK   64
#define BWIN   1024
#define NWIN   64
#define CPBH   512
#define NROWS  (BWIN * NTOK)          /* 65536 */
#define QKVC   (3 * DIMC)             /* 1536  */

// ---------------- device scratch (no allocs allowed) ----------------
__device__ float g_qkv[NROWS * QKVC];         // 402 MB
__device__ float g_attn[NROWS * DIMC];        // 134 MB
__device__ float g_bias_table[225 * NHEADS];
__device__ float g_rpb[NHEADS * NTOK * NTOK];
__device__ float g_qkv_bias[QKVC];

// ---------------- tiny setup kernels ----------------
__global__ void k_make_qkv_bias(const float* __restrict__ qb,
                                const float* __restrict__ vb) {
    int i = blockIdx.x * blockDim.x + threadIdx.x;
    if (i < QKVC) {
        float v = 0.f;
        if (i < DIMC)            v = qb[i];
        else if (i >= 2 * DIMC)  v = vb[i - 2 * DIMC];
        g_qkv_bias[i] = v;
    }
}

__device__ __forceinline__ float cpb_coord(int u) {
    // t = u/7*8 ; sign(t)*log2(|t|+1)/log2(8)
    float t = (float)u * (8.0f / 7.0f);
    float s = (t > 0.f) ? 1.f : ((t < 0.f) ? -1.f : 0.f);
    return s * log2f(fabsf(t) + 1.0f) * (1.0f / 3.0f);
}

// one block per table entry m (225); 512 threads; 16 warps -> 16 heads
__global__ void k_cpb(const float* __restrict__ w1, const float* __restrict__ b1,
                      const float* __restrict__ w2) {
    __shared__ float hid[CPBH];
    int m = blockIdx.x;
    int k = threadIdx.x;
    float c0 = cpb_coord(m % 15 - 7);   // table[m][0] = g(m%15 - 7)
    float c1 = cpb_coord(m / 15 - 7);   // table[m][1] = g(m/15 - 7)
    hid[k] = fmaxf(fmaf(c0, w1[k], fmaf(c1, w1[CPBH + k], b1[k])), 0.f);
    __syncthreads();
    int warp = k >> 5, lane = k & 31;
    float s = 0.f;
    for (int kk = lane; kk < CPBH; kk += 32)
        s = fmaf(hid[kk], w2[kk * NHEADS + warp], s);
#pragma unroll
    for (int o = 16; o > 0; o >>= 1) s += __shfl_xor_sync(0xffffffffu, s, o);
    if (lane == 0) g_bias_table[m * NHEADS + warp] = s;
}

// rpb[h][p][q] = 16*sigmoid(bias_table[idx(p,q)][h])
__global__ void k_rpb() {
    int id = blockIdx.x * blockDim.x + threadIdx.x;   // 65536 total
    int h = id >> 12;
    int p = (id >> 6) & 63;
    int q = id & 63;
    int idx = (((p & 7) - (q & 7)) + 7) * 15 + (((p >> 3) - (q >> 3)) + 7);
    float v = g_bias_table[idx * NHEADS + h];
    g_rpb[id] = 16.0f / (1.0f + expf(-v));
}

// ---------------- fp32 SGEMM: C[M,N] = A[M,K] @ B[K,N] + bias[N] ----------------
#define BM 128
#define BN 128
#define BK 16

__global__ __launch_bounds__(256) void sgemm_bias(
    const float* __restrict__ A, const float* __restrict__ B,
    const float* __restrict__ bias, float* __restrict__ C,
    int M, int N, int K) {
    __shared__ float As[BK][BM];   // A transposed tile
    __shared__ float Bs[BK][BN];

    const int tid  = threadIdx.x;
    const int row0 = blockIdx.y * BM;
    const int col0 = blockIdx.x * BN;
    const int tr = (tid >> 4) << 3;   // 0..120
    const int tc = (tid & 15) << 3;   // 0..120

    float acc[8][8];
#pragma unroll
    for (int i = 0; i < 8; i++)
#pragma unroll
        for (int j = 0; j < 8; j++) acc[i][j] = 0.f;

    for (int k0 = 0; k0 < K; k0 += BK) {
#pragma unroll
        for (int l = 0; l < 2; l++) {
            int id = tid + (l << 8);                 // 0..511
            int ar = id >> 2, ak = (id & 3) << 2;    // A: row, k-offset
            float4 av = *(const float4*)(A + (size_t)(row0 + ar) * K + (k0 + ak));
            As[ak + 0][ar] = av.x; As[ak + 1][ar] = av.y;
            As[ak + 2][ar] = av.z; As[ak + 3][ar] = av.w;
            int bk = id >> 5, bc = (id & 31) << 2;   // B: k-row, col-offset
            *(float4*)(&Bs[bk][bc]) =
                *(const float4*)(B + (size_t)(k0 + bk) * N + (col0 + bc));
        }
        __syncthreads();
#pragma unroll
        for (int kk = 0; kk < BK; kk++) {
            float4 a0 = *(const float4*)(&As[kk][tr]);
            float4 a1 = *(const float4*)(&As[kk][tr + 4]);
            float4 b0 = *(const float4*)(&Bs[kk][tc]);
            float4 b1 = *(const float4*)(&Bs[kk][tc + 4]);
            float a[8] = {a0.x, a0.y, a0.z, a0.w, a1.x, a1.y, a1.z, a1.w};
            float b[8] = {b0.x, b0.y, b0.z, b0.w, b1.x, b1.y, b1.z, b1.w};
#pragma unroll
            for (int i = 0; i < 8; i++)
#pragma unroll
                for (int j = 0; j < 8; j++)
                    acc[i][j] = fmaf(a[i], b[j], acc[i][j]);
        }
        __syncthreads();
    }

    float4 bia0 = *(const float4*)(bias + col0 + tc);
    float4 bia1 = *(const float4*)(bias + col0 + tc + 4);
#pragma unroll
    for (int i = 0; i < 8; i++) {
        size_t r = (size_t)(row0 + tr + i) * N + (col0 + tc);
        float4 o0, o1;
        o0.x = acc[i][0] + bia0.x; o0.y = acc[i][1] + bia0.y;
        o0.z = acc[i][2] + bia0.z; o0.w = acc[i][3] + bia0.w;
        o1.x = acc[i][4] + bia1.x; o1.y = acc[i][5] + bia1.y;
        o1.z = acc[i][6] + bia1.z; o1.w = acc[i][7] + bia1.w;
        *(float4*)(C + r)     = o0;
        *(float4*)(C + r + 4) = o1;
    }
}

// ---------------- fused per-(window, head) attention ----------------
// grid = (16 heads, 1024 windows), 128 threads
__global__ __launch_bounds__(128) void k_attn(const float* __restrict__ mask,
                                              const float* __restrict__ logit_scale) {
    const int h = blockIdx.x;
    const int b = blockIdx.y;
    __shared__ float qnT[32][68];   // [k][token], padded
    __shared__ float knT[32][68];
    __shared__ float vv[64][32];    // [token][d]
    __shared__ float S[64][68];     // logits / probs, padded

    const int tid = threadIdx.x;
    const float* base = g_qkv + (size_t)b * NTOK * QKVC + h * HD;

    // load q,k transposed (for conflict-free dot products), v row-major
    for (int t = tid; t < 64 * 8; t += 128) {
        int r = t >> 3, c = (t & 7) << 2;
        const float* row = base + (size_t)r * QKVC;
        float4 qv = *(const float4*)(row + c);
        float4 kv = *(const float4*)(row + DIMC + c);
        float4 vx = *(const float4*)(row + 2 * DIMC + c);
        qnT[c + 0][r] = qv.x; qnT[c + 1][r] = qv.y;
        qnT[c + 2][r] = qv.z; qnT[c + 3][r] = qv.w;
        knT[c + 0][r] = kv.x; knT[c + 1][r] = kv.y;
        knT[c + 2][r] = kv.z; knT[c + 3][r] = kv.w;
        *(float4*)(&vv[r][c]) = vx;
    }
    __syncthreads();

    // L2-normalize rows; fold logit scale into q
    {
        float scale = expf(fminf(logit_scale[h], 4.6051701860f)); // ln(100)
        int r = tid & 63;
        bool isq = tid < 64;
        float s = 0.f;
#pragma unroll
        for (int c = 0; c < 32; c++) {
            float xv = isq ? qnT[c][r] : knT[c][r];
            s = fmaf(xv, xv, s);
        }
        float inv = rsqrtf(s);
        if (isq) inv *= scale;
#pragma unroll
        for (int c = 0; c < 32; c++) {
            if (isq) qnT[c][r] *= inv; else knT[c][r] *= inv;
        }
    }
    __syncthreads();

    // S[p][q] = qn . kn + rpb[h] + mask[b%64]   (8x4 register tile per thread)
    {
        const int trw = (tid >> 4) << 3;   // 0..56
        const int tcl = (tid & 15) << 2;   // 0..60
        float acc[8][4];
#pragma unroll
        for (int i = 0; i < 8; i++)
#pragma unroll
            for (int j = 0; j < 4; j++) acc[i][j] = 0.f;
#pragma unroll
        for (int k = 0; k < 32; k++) {
            float4 a0 = *(const float4*)(&qnT[k][trw]);
            float4 a1 = *(const float4*)(&qnT[k][trw + 4]);
            float4 bq = *(const float4*)(&knT[k][tcl]);
            float a[8] = {a0.x, a0.y, a0.z, a0.w, a1.x, a1.y, a1.z, a1.w};
            float bb[4] = {bq.x, bq.y, bq.z, bq.w};
#pragma unroll
            for (int i = 0; i < 8; i++)
#pragma unroll
                for (int j = 0; j < 4; j++)
                    acc[i][j] = fmaf(a[i], bb[j], acc[i][j]);
        }
        const float* mrow = mask + (size_t)(b & (NWIN - 1)) * NTOK * NTOK;
        const float* rrow = g_rpb + (size_t)h * NTOK * NTOK;
#pragma unroll
        for (int i = 0; i < 8; i++) {
            int p = trw + i;
            float4 rb = *(const float4*)(rrow + p * 64 + tcl);
            float4 mk = *(const float4*)(mrow + p * 64 + tcl);
            float4 o;
            o.x = acc[i][0] + rb.x + mk.x;
            o.y = acc[i][1] + rb.y + mk.y;
            o.z = acc[i][2] + rb.z + mk.z;
            o.w = acc[i][3] + rb.w + mk.w;
            *(float4*)(&S[p][tcl]) = o;
        }
    }
    __syncthreads();

    // row softmax (one thread per row)
    if (tid < 64) {
        int i = tid;
        float m = -1e30f;
#pragma unroll 8
        for (int j = 0; j < 64; j++) m = fmaxf(m, S[i][j]);
        float sum = 0.f;
#pragma unroll 8
        for (int j = 0; j < 64; j++) {
            float e = expf(S[i][j] - m);
            S[i][j] = e;
            sum += e;
        }
        float inv = 1.0f / sum;
#pragma unroll 8
        for (int j = 0; j < 64; j++) S[i][j] *= inv;
    }
    __syncthreads();

    // O = S @ V   (4x4 register tile per thread), write to g_attn[(b,n),(h,d)]
    {
        const int i0 = (tid >> 3) << 2;   // 0..60
        const int d0 = (tid & 7) << 2;    // 0..28
        float o[4][4];
#pragma unroll
        for (int i = 0; i < 4; i++)
#pragma unroll
            for (int d = 0; d < 4; d++) o[i][d] = 0.f;
#pragma unroll 4
        for (int j = 0; j < 64; j++) {
            float4 vj = *(const float4*)(&vv[j][d0]);
#pragma unroll
            for (int i = 0; i < 4; i++) {
                float sv = S[i0 + i][j];
                o[i][0] = fmaf(sv, vj.x, o[i][0]);
                o[i][1] = fmaf(sv, vj.y, o[i][1]);
                o[i][2] = fmaf(sv, vj.z, o[i][2]);
                o[i][3] = fmaf(sv, vj.w, o[i][3]);
            }
        }
#pragma unroll
        for (int i = 0; i < 4; i++) {
            float4 ov = make_float4(o[i][0], o[i][1], o[i][2], o[i][3]);
            *(float4*)(g_attn + (size_t)(b * NTOK + i0 + i) * DIMC + h * HD + d0) = ov;
        }
    }
}

// ---------------- launcher ----------------
extern "C" void kernel_launch(void* const* d_in, const int* in_sizes, int n_in,
                              void* d_out, int out_size) {
    (void)in_sizes; (void)n_in; (void)out_size;
    const float* x           = (const float*)d_in[0];
    const float* mask        = (const float*)d_in[1];
    const float* qkv_w       = (const float*)d_in[2];
    const float* q_bias      = (const float*)d_in[3];
    const float* v_bias      = (const float*)d_in[4];
    const float* logit_scale = (const float*)d_in[5];
    const float* cpb_w1      = (const float*)d_in[6];
    const float* cpb_b1      = (const float*)d_in[7];
    const float* cpb_w2      = (const float*)d_in[8];
    const float* proj_w      = (const float*)d_in[9];
    const float* proj_b      = (const float*)d_in[10];
    float* out = (float*)d_out;

    float *p_qkv, *p_attn, *p_qkvb;
    cudaGetSymbolAddress((void**)&p_qkv,  g_qkv);
    cudaGetSymbolAddress((void**)&p_attn, g_attn);
    cudaGetSymbolAddress((void**)&p_qkvb, g_qkv_bias);

    k_make_qkv_bias<<<3, 512>>>(q_bias, v_bias);
    k_cpb<<<225, CPBH>>>(cpb_w1, cpb_b1, cpb_w2);
    k_rpb<<<64, 1024>>>();

    // QKV: (65536 x 1536) = x (65536 x 512) @ qkv_w (512 x 1536) + bias
    sgemm_bias<<<dim3(QKVC / BN, NROWS / BM), 256>>>(
        x, qkv_w, p_qkvb, p_qkv, NROWS, QKVC, DIMC);

    // fused attention
    k_attn<<<dim3(NHEADS, BWIN), 128>>>(mask, logit_scale);

    // proj: out (65536 x 512) = attn (65536 x 512) @ proj_w (512 x 512) + proj_b
    sgemm_bias<<<dim3(DIMC / BN, NROWS / BM), 256>>>(
        p_attn, proj_w, proj_b, out, NROWS, DIMC, DIMC);
}

// round 9
// speedup vs baseline: 1.9885x; 1.9885x over previous
#include <cuda_runtime.h>
#include <cuda_bf16.h>
#include <cstdint>
#include <math.h>

// ---------------- problem constants ----------------
#define DIMC   512
#define NHEADS 16
#define HD     32
#define NTOK   64
#define BWIN   1024
#define NWIN   64
#define CPBH   512
#define NROWS  (BWIN * NTOK)          /* 65536 */
#define QKVC   (3 * DIMC)             /* 1536  */

// ---------------- device scratch (no allocs allowed) ----------------
__device__ float g_qkv[NROWS * QKVC];                 // 402 MB (fp32 for attention)
__device__ __nv_bfloat16 g_x_hi[NROWS * DIMC];
__device__ __nv_bfloat16 g_x_lo[NROWS * DIMC];
__device__ __nv_bfloat16 g_attn_hi[NROWS * DIMC];
__device__ __nv_bfloat16 g_attn_lo[NROWS * DIMC];
__device__ __nv_bfloat16 g_wqkv_hi[QKVC * DIMC];      // [N=1536, K=512] transposed
__device__ __nv_bfloat16 g_wqkv_lo[QKVC * DIMC];
__device__ __nv_bfloat16 g_wproj_hi[DIMC * DIMC];     // [N=512, K=512] transposed
__device__ __nv_bfloat16 g_wproj_lo[DIMC * DIMC];
__device__ float g_bias_table[225 * NHEADS];
__device__ float g_rpb[NHEADS * NTOK * NTOK];
__device__ float g_qkv_bias[QKVC];

// ---------------- mma.sync helpers (arch-agnostic PTX) ----------------
#define LDSM4(R, addr)                                                        \
    asm volatile("ldmatrix.sync.aligned.m8n8.x4.shared.b16 {%0,%1,%2,%3},[%4];" \
                 : "=r"((R)[0]), "=r"((R)[1]), "=r"((R)[2]), "=r"((R)[3])     \
                 : "r"(addr))
#define LDSM2(R, addr)                                                        \
    asm volatile("ldmatrix.sync.aligned.m8n8.x2.shared.b16 {%0,%1},[%2];"     \
                 : "=r"((R)[0]), "=r"((R)[1]) : "r"(addr))
#define MMA16816(D, A, B)                                                     \
    asm volatile("mma.sync.aligned.m16n8k16.row.col.f32.bf16.bf16.f32 "       \
                 "{%0,%1,%2,%3},{%4,%5,%6,%7},{%8,%9},{%0,%1,%2,%3};"         \
                 : "+f"((D)[0]), "+f"((D)[1]), "+f"((D)[2]), "+f"((D)[3])     \
                 : "r"((A)[0]), "r"((A)[1]), "r"((A)[2]), "r"((A)[3]),        \
                   "r"((B)[0]), "r"((B)[1]))

__device__ __forceinline__ uint32_t smem_u32(const void* p) {
    uint32_t a;
    asm("{ .reg .u64 t; cvta.to.shared.u64 t, %1; cvt.u32.u64 %0, t; }" : "=r"(a) : "l"(p));
    return a;
}

// ---------------- setup kernels ----------------
__global__ void k_make_qkv_bias(const float* __restrict__ qb,
                                const float* __restrict__ vb) {
    int i = blockIdx.x * blockDim.x + threadIdx.x;
    if (i < QKVC) {
        float v = 0.f;
        if (i < DIMC)            v = qb[i];
        else if (i >= 2 * DIMC)  v = vb[i - 2 * DIMC];
        g_qkv_bias[i] = v;
    }
}

__device__ __forceinline__ float cpb_coord(int u) {
    float t = (float)u * (8.0f / 7.0f);
    float s = (t > 0.f) ? 1.f : ((t < 0.f) ? -1.f : 0.f);
    return s * log2f(fabsf(t) + 1.0f) * (1.0f / 3.0f);
}

__global__ void k_cpb(const float* __restrict__ w1, const float* __restrict__ b1,
                      const float* __restrict__ w2) {
    __shared__ float hid[CPBH];
    int m = blockIdx.x;
    int k = threadIdx.x;
    float c0 = cpb_coord(m % 15 - 7);
    float c1 = cpb_coord(m / 15 - 7);
    hid[k] = fmaxf(fmaf(c0, w1[k], fmaf(c1, w1[CPBH + k], b1[k])), 0.f);
    __syncthreads();
    int warp = k >> 5, lane = k & 31;
    float s = 0.f;
    for (int kk = lane; kk < CPBH; kk += 32)
        s = fmaf(hid[kk], w2[kk * NHEADS + warp], s);
#pragma unroll
    for (int o = 16; o > 0; o >>= 1) s += __shfl_xor_sync(0xffffffffu, s, o);
    if (lane == 0) g_bias_table[m * NHEADS + warp] = s;
}

__global__ void k_rpb() {
    int id = blockIdx.x * blockDim.x + threadIdx.x;
    int h = id >> 12;
    int p = (id >> 6) & 63;
    int q = id & 63;
    int idx = (((p & 7) - (q & 7)) + 7) * 15 + (((p >> 3) - (q >> 3)) + 7);
    float v = g_bias_table[idx * NHEADS + h];
    g_rpb[id] = 16.0f / (1.0f + expf(-v));
}

// split fp32 -> (hi bf16, lo bf16), vectorized by 4
__global__ void k_split(const float* __restrict__ s, __nv_bfloat16* __restrict__ hi,
                        __nv_bfloat16* __restrict__ lo, int n4) {
    int i = blockIdx.x * blockDim.x + threadIdx.x;
    if (i < n4) {
        float4 v = *(const float4*)(s + i * 4);
        __nv_bfloat16 h0 = __float2bfloat16(v.x);
        __nv_bfloat16 h1 = __float2bfloat16(v.y);
        __nv_bfloat16 h2 = __float2bfloat16(v.z);
        __nv_bfloat16 h3 = __float2bfloat16(v.w);
        __nv_bfloat162 hh0, hh1, ll0, ll1;
        hh0.x = h0; hh0.y = h1; hh1.x = h2; hh1.y = h3;
        ll0.x = __float2bfloat16(v.x - __bfloat162float(h0));
        ll0.y = __float2bfloat16(v.y - __bfloat162float(h1));
        ll1.x = __float2bfloat16(v.z - __bfloat162float(h2));
        ll1.y = __float2bfloat16(v.w - __bfloat162float(h3));
        *(__nv_bfloat162*)(hi + i * 4)     = hh0;
        *(__nv_bfloat162*)(hi + i * 4 + 2) = hh1;
        *(__nv_bfloat162*)(lo + i * 4)     = ll0;
        *(__nv_bfloat162*)(lo + i * 4 + 2) = ll1;
    }
}

// transpose + split weights: w [K,N] fp32 -> hi/lo [N,K] bf16
__global__ void k_split_w_t(const float* __restrict__ w, __nv_bfloat16* __restrict__ hi,
                            __nv_bfloat16* __restrict__ lo, int K, int N) {
    int i = blockIdx.x * blockDim.x + threadIdx.x;
    if (i < K * N) {
        int n = i / K, k = i - n * K;
        float x = w[(size_t)k * N + n];
        __nv_bfloat16 h = __float2bfloat16(x);
        hi[i] = h;
        lo[i] = __float2bfloat16(x - __bfloat162float(h));
    }
}

// ---------------- split-bf16 HMMA GEMM ----------------
// C[M,N] = (Ah+Al)(Bh+Bl)^T (lo*lo dropped) + bias
// A* [M,K] bf16 row-major, B* [N,K] bf16 row-major. 128x128x32 tile, 256 thr.
// smem: 4 tiles of [128][32] bf16, XOR-swizzled 16B chunks: c16 ^= (r>>1)&3.
__global__ __launch_bounds__(256) void gemm_mma(
    const __nv_bfloat16* __restrict__ Ahi, const __nv_bfloat16* __restrict__ Alo,
    const __nv_bfloat16* __restrict__ Bhi, const __nv_bfloat16* __restrict__ Blo,
    const float* __restrict__ bias, float* __restrict__ C,
    int M, int N, int K) {
    __shared__ __nv_bfloat16 sm[4][128][32];     // Ah, Al, Bh, Bl : 32 KB

    const int tid  = threadIdx.x;
    const int lane = tid & 31;
    const int warp = tid >> 5;
    const int wm = (warp >> 2) << 6;             // 0 / 64
    const int wn = (warp & 3) << 5;              // 0,32,64,96
    const int row0 = blockIdx.y * 128;
    const int col0 = blockIdx.x * 128;

    const __nv_bfloat16* srcA_h = Ahi + (size_t)row0 * K;
    const __nv_bfloat16* srcA_l = Alo + (size_t)row0 * K;
    const __nv_bfloat16* srcB_h = Bhi + (size_t)col0 * K;
    const __nv_bfloat16* srcB_l = Blo + (size_t)col0 * K;

    // ldmatrix smem byte offsets (per fragment, per k-half)
    uint32_t baseS[4];
#pragma unroll
    for (int a = 0; a < 4; a++) baseS[a] = smem_u32(&sm[a][0][0]);
    uint32_t offA[4][2], offB[4][2];
#pragma unroll
    for (int mf = 0; mf < 4; mf++) {
        int r = wm + (mf << 4) + (lane & 15);
#pragma unroll
        for (int k2 = 0; k2 < 2; k2++) {
            int c16 = (lane >> 4) + (k2 << 1);
            offA[mf][k2] = (uint32_t)((r << 6) + (((c16 ^ ((r >> 1) & 3))) << 4));
        }
    }
#pragma unroll
    for (int nf = 0; nf < 4; nf++) {
        int r = wn + (nf << 3) + (lane & 7);
#pragma unroll
        for (int k2 = 0; k2 < 2; k2++) {
            int c16 = ((lane >> 3) & 1) + (k2 << 1);
            offB[nf][k2] = (uint32_t)((r << 6) + (((c16 ^ ((r >> 1) & 3))) << 4));
        }
    }

    float acc[4][4][4];
#pragma unroll
    for (int mf = 0; mf < 4; mf++)
#pragma unroll
        for (int nf = 0; nf < 4; nf++)
#pragma unroll
            for (int e = 0; e < 4; e++) acc[mf][nf][e] = 0.f;

    // global-load assignment: per array, per half: r = id>>2, c16 = id&3
    const int r_g  = tid >> 2;
    const int r_g2 = (tid + 256) >> 2;
    const int c_g  = tid & 3;
    const int sw1  = (c_g ^ ((r_g  >> 1) & 3)) << 3;   // swizzled element col
    const int sw2  = (c_g ^ ((r_g2 >> 1) & 3)) << 3;

    const int nchunks = K >> 5;
    uint4 pf[8];
    // prologue: prefetch chunk 0
    {
        const __nv_bfloat16* s0[4] = {srcA_h, srcA_l, srcB_h, srcB_l};
#pragma unroll
        for (int a = 0; a < 4; a++) {
            pf[a * 2 + 0] = *(const uint4*)(s0[a] + (size_t)r_g  * K + (c_g << 3));
            pf[a * 2 + 1] = *(const uint4*)(s0[a] + (size_t)r_g2 * K + (c_g << 3));
        }
    }

    for (int kc = 0; kc < nchunks; kc++) {
#pragma unroll
        for (int a = 0; a < 4; a++) {
            *(uint4*)(&sm[a][r_g][sw1])  = pf[a * 2 + 0];
            *(uint4*)(&sm[a][r_g2][sw2]) = pf[a * 2 + 1];
        }
        __syncthreads();

        if (kc + 1 < nchunks) {
            const int k0 = (kc + 1) << 5;
            const __nv_bfloat16* s0[4] = {srcA_h, srcA_l, srcB_h, srcB_l};
#pragma unroll
            for (int a = 0; a < 4; a++) {
                pf[a * 2 + 0] = *(const uint4*)(s0[a] + (size_t)r_g  * K + k0 + (c_g << 3));
                pf[a * 2 + 1] = *(const uint4*)(s0[a] + (size_t)r_g2 * K + k0 + (c_g << 3));
            }
        }

#pragma unroll
        for (int k2 = 0; k2 < 2; k2++) {
            uint32_t ah[4][4], al[4][4], bh[4][2], bl[4][2];
#pragma unroll
            for (int mf = 0; mf < 4; mf++) {
                LDSM4(ah[mf], baseS[0] + offA[mf][k2]);
                LDSM4(al[mf], baseS[1] + offA[mf][k2]);
            }
#pragma unroll
            for (int nf = 0; nf < 4; nf++) {
                LDSM2(bh[nf], baseS[2] + offB[nf][k2]);
                LDSM2(bl[nf], baseS[3] + offB[nf][k2]);
            }
#pragma unroll
            for (int mf = 0; mf < 4; mf++)
#pragma unroll
                for (int nf = 0; nf < 4; nf++) {
                    MMA16816(acc[mf][nf], ah[mf], bh[nf]);
                    MMA16816(acc[mf][nf], ah[mf], bl[nf]);
                    MMA16816(acc[mf][nf], al[mf], bh[nf]);
                }
        }
        __syncthreads();
    }

    // epilogue: C-fragment -> gmem with bias (float2, coalesced per quad)
    const int qr = lane >> 2;
    const int qc = (lane & 3) << 1;
#pragma unroll
    for (int mf = 0; mf < 4; mf++) {
#pragma unroll
        for (int nf = 0; nf < 4; nf++) {
            int row = row0 + wm + (mf << 4) + qr;
            int col = col0 + wn + (nf << 3) + qc;
            float2 bi = *(const float2*)(bias + col);
            float2 v0, v1;
            v0.x = acc[mf][nf][0] + bi.x; v0.y = acc[mf][nf][1] + bi.y;
            v1.x = acc[mf][nf][2] + bi.x; v1.y = acc[mf][nf][3] + bi.y;
            *(float2*)(C + (size_t)row * N + col)       = v0;
            *(float2*)(C + (size_t)(row + 8) * N + col) = v1;
        }
    }
}

// ---------------- fused per-(window, head) attention (fp32) ----------------
// writes output directly as (hi, lo) bf16 for the proj GEMM
__global__ __launch_bounds__(128) void k_attn(const float* __restrict__ mask,
                                              const float* __restrict__ logit_scale) {
    const int h = blockIdx.x;
    const int b = blockIdx.y;
    __shared__ float qnT[32][68];
    __shared__ float knT[32][68];
    __shared__ float vv[64][32];
    __shared__ float S[64][68];

    const int tid = threadIdx.x;
    const float* base = g_qkv + (size_t)b * NTOK * QKVC + h * HD;

    for (int t = tid; t < 64 * 8; t += 128) {
        int r = t >> 3, c = (t & 7) << 2;
        const float* row = base + (size_t)r * QKVC;
        float4 qv = *(const float4*)(row + c);
        float4 kv = *(const float4*)(row + DIMC + c);
        float4 vx = *(const float4*)(row + 2 * DIMC + c);
        qnT[c + 0][r] = qv.x; qnT[c + 1][r] = qv.y;
        qnT[c + 2][r] = qv.z; qnT[c + 3][r] = qv.w;
        knT[c + 0][r] = kv.x; knT[c + 1][r] = kv.y;
        knT[c + 2][r] = kv.z; knT[c + 3][r] = kv.w;
        *(float4*)(&vv[r][c]) = vx;
    }
    __syncthreads();

    {
        float scale = expf(fminf(logit_scale[h], 4.6051701860f));
        int r = tid & 63;
        bool isq = tid < 64;
        float s = 0.f;
#pragma unroll
        for (int c = 0; c < 32; c++) {
            float xv = isq ? qnT[c][r] : knT[c][r];
            s = fmaf(xv, xv, s);
        }
        float inv = rsqrtf(s);
        if (isq) inv *= scale;
#pragma unroll
        for (int c = 0; c < 32; c++) {
            if (isq) qnT[c][r] *= inv; else knT[c][r] *= inv;
        }
    }
    __syncthreads();

    {
        const int trw = (tid >> 4) << 3;
        const int tcl = (tid & 15) << 2;
        float acc[8][4];
#pragma unroll
        for (int i = 0; i < 8; i++)
#pragma unroll
            for (int j = 0; j < 4; j++) acc[i][j] = 0.f;
#pragma unroll
        for (int k = 0; k < 32; k++) {
            float4 a0 = *(const float4*)(&qnT[k][trw]);
            float4 a1 = *(const float4*)(&qnT[k][trw + 4]);
            float4 bq = *(const float4*)(&knT[k][tcl]);
            float a[8] = {a0.x, a0.y, a0.z, a0.w, a1.x, a1.y, a1.z, a1.w};
            float bb[4] = {bq.x, bq.y, bq.z, bq.w};
#pragma unroll
            for (int i = 0; i < 8; i++)
#pragma unroll
                for (int j = 0; j < 4; j++)
                    acc[i][j] = fmaf(a[i], bb[j], acc[i][j]);
        }
        const float* mrow = mask + (size_t)(b & (NWIN - 1)) * NTOK * NTOK;
        const float* rrow = g_rpb + (size_t)h * NTOK * NTOK;
#pragma unroll
        for (int i = 0; i < 8; i++) {
            int p = trw + i;
            float4 rb = *(const float4*)(rrow + p * 64 + tcl);
            float4 mk = *(const float4*)(mrow + p * 64 + tcl);
            float4 o;
            o.x = acc[i][0] + rb.x + mk.x;
            o.y = acc[i][1] + rb.y + mk.y;
            o.z = acc[i][2] + rb.z + mk.z;
            o.w = acc[i][3] + rb.w + mk.w;
            *(float4*)(&S[p][tcl]) = o;
        }
    }
    __syncthreads();

    if (tid < 64) {
        int i = tid;
        float m = -1e30f;
#pragma unroll 8
        for (int j = 0; j < 64; j++) m = fmaxf(m, S[i][j]);
        float sum = 0.f;
#pragma unroll 8
        for (int j = 0; j < 64; j++) {
            float e = expf(S[i][j] - m);
            S[i][j] = e;
            sum += e;
        }
        float inv = 1.0f / sum;
#pragma unroll 8
        for (int j = 0; j < 64; j++) S[i][j] *= inv;
    }
    __syncthreads();

    {
        const int i0 = (tid >> 3) << 2;
        const int d0 = (tid & 7) << 2;
        float o[4][4];
#pragma unroll
        for (int i = 0; i < 4; i++)
#pragma unroll
            for (int d = 0; d < 4; d++) o[i][d] = 0.f;
#pragma unroll 4
        for (int j = 0; j < 64; j++) {
            float4 vj = *(const float4*)(&vv[j][d0]);
#pragma unroll
            for (int i = 0; i < 4; i++) {
                float sv = S[i0 + i][j];
                o[i][0] = fmaf(sv, vj.x, o[i][0]);
                o[i][1] = fmaf(sv, vj.y, o[i][1]);
                o[i][2] = fmaf(sv, vj.z, o[i][2]);
                o[i][3] = fmaf(sv, vj.w, o[i][3]);
            }
        }
#pragma unroll
        for (int i = 0; i < 4; i++) {
            size_t idx = (size_t)(b * NTOK + i0 + i) * DIMC + h * HD + d0;
            __nv_bfloat162 hh0, hh1, ll0, ll1;
            hh0.x = __float2bfloat16(o[i][0]);
            hh0.y = __float2bfloat16(o[i][1]);
            hh1.x = __float2bfloat16(o[i][2]);
            hh1.y = __float2bfloat16(o[i][3]);
            ll0.x = __float2bfloat16(o[i][0] - __bfloat162float(hh0.x));
            ll0.y = __float2bfloat16(o[i][1] - __bfloat162float(hh0.y));
            ll1.x = __float2bfloat16(o[i][2] - __bfloat162float(hh1.x));
            ll1.y = __float2bfloat16(o[i][3] - __bfloat162float(hh1.y));
            *(__nv_bfloat162*)(g_attn_hi + idx)     = hh0;
            *(__nv_bfloat162*)(g_attn_hi + idx + 2) = hh1;
            *(__nv_bfloat162*)(g_attn_lo + idx)     = ll0;
            *(__nv_bfloat162*)(g_attn_lo + idx + 2) = ll1;
        }
    }
}

// ---------------- launcher ----------------
extern "C" void kernel_launch(void* const* d_in, const int* in_sizes, int n_in,
                              void* d_out, int out_size) {
    (void)in_sizes; (void)n_in; (void)out_size;
    const float* x           = (const float*)d_in[0];
    const float* mask        = (const float*)d_in[1];
    const float* qkv_w       = (const float*)d_in[2];
    const float* q_bias      = (const float*)d_in[3];
    const float* v_bias      = (const float*)d_in[4];
    const float* logit_scale = (const float*)d_in[5];
    const float* cpb_w1      = (const float*)d_in[6];
    const float* cpb_b1      = (const float*)d_in[7];
    const float* cpb_w2      = (const float*)d_in[8];
    const float* proj_w      = (const float*)d_in[9];
    const float* proj_b      = (const float*)d_in[10];
    float* out = (float*)d_out;

    float *p_qkv, *p_qkvb;
    __nv_bfloat16 *p_xh, *p_xl, *p_ah, *p_al, *p_wqh, *p_wql, *p_wph, *p_wpl;
    cudaGetSymbolAddress((void**)&p_qkv,  g_qkv);
    cudaGetSymbolAddress((void**)&p_qkvb, g_qkv_bias);
    cudaGetSymbolAddress((void**)&p_xh,   g_x_hi);
    cudaGetSymbolAddress((void**)&p_xl,   g_x_lo);
    cudaGetSymbolAddress((void**)&p_ah,   g_attn_hi);
    cudaGetSymbolAddress((void**)&p_al,   g_attn_lo);
    cudaGetSymbolAddress((void**)&p_wqh,  g_wqkv_hi);
    cudaGetSymbolAddress((void**)&p_wql,  g_wqkv_lo);
    cudaGetSymbolAddress((void**)&p_wph,  g_wproj_hi);
    cudaGetSymbolAddress((void**)&p_wpl,  g_wproj_lo);

    k_make_qkv_bias<<<3, 512>>>(q_bias, v_bias);
    k_cpb<<<225, CPBH>>>(cpb_w1, cpb_b1, cpb_w2);
    k_rpb<<<64, 1024>>>();

    // split activations + weights to (hi, lo) bf16
    k_split<<<(NROWS * DIMC / 4 + 255) / 256, 256>>>(x, p_xh, p_xl, NROWS * DIMC / 4);
    k_split_w_t<<<(QKVC * DIMC + 255) / 256, 256>>>(qkv_w, p_wqh, p_wql, DIMC, QKVC);
    k_split_w_t<<<(DIMC * DIMC + 255) / 256, 256>>>(proj_w, p_wph, p_wpl, DIMC, DIMC);

    // QKV: (65536 x 1536) split-bf16 HMMA
    gemm_mma<<<dim3(QKVC / 128, NROWS / 128), 256>>>(
        p_xh, p_xl, p_wqh, p_wql, p_qkvb, p_qkv, NROWS, QKVC, DIMC);

    // fused attention (fp32 compute, bf16 hi/lo output)
    k_attn<<<dim3(NHEADS, BWIN), 128>>>(mask, logit_scale);

    // proj: (65536 x 512) split-bf16 HMMA -> d_out
    gemm_mma<<<dim3(DIMC / 128, NROWS / 128), 256>>>(
        p_ah, p_al, p_wph, p_wpl, proj_b, out, NROWS, DIMC, DIMC);
}

// round 10
// speedup vs baseline: 2.1142x; 1.0632x over previous
#include <cuda_runtime.h>
#include <cuda_bf16.h>
#include <cstdint>
#include <math.h>

// ---------------- problem constants ----------------
#define DIMC   512
#define NHEADS 16
#define HD     32
#define NTOK   64
#define BWIN   1024
#define NWIN   64
#define CPBH   512
#define NROWS  (BWIN * NTOK)          /* 65536 */
#define QKVC   (3 * DIMC)             /* 1536  */

// ---------------- device scratch (no allocs allowed) ----------------
__device__ float g_qkv[NROWS * QKVC];                 // fp32 qkv for attention
__device__ __nv_bfloat16 g_x_hi[NROWS * DIMC];
__device__ __nv_bfloat16 g_x_lo[NROWS * DIMC];
__device__ __nv_bfloat16 g_attn_hi[NROWS * DIMC];
__device__ __nv_bfloat16 g_attn_lo[NROWS * DIMC];
__device__ __nv_bfloat16 g_wqkv_hi[QKVC * DIMC];      // [N=1536, K=512] transposed
__device__ __nv_bfloat16 g_wqkv_lo[QKVC * DIMC];
__device__ __nv_bfloat16 g_wproj_hi[DIMC * DIMC];     // [N=512, K=512] transposed
__device__ __nv_bfloat16 g_wproj_lo[DIMC * DIMC];
__device__ float g_bias_table[225 * NHEADS];
__device__ float g_rpb[NHEADS * NTOK * NTOK];
__device__ float g_qkv_bias[QKVC];

// ---------------- mma.sync helpers (arch-agnostic PTX) ----------------
#define LDSM4(R, addr)                                                        \
    asm volatile("ldmatrix.sync.aligned.m8n8.x4.shared.b16 {%0,%1,%2,%3},[%4];" \
                 : "=r"((R)[0]), "=r"((R)[1]), "=r"((R)[2]), "=r"((R)[3])     \
                 : "r"(addr))
#define LDSM2(R, addr)                                                        \
    asm volatile("ldmatrix.sync.aligned.m8n8.x2.shared.b16 {%0,%1},[%2];"     \
                 : "=r"((R)[0]), "=r"((R)[1]) : "r"(addr))
#define MMA16816(D, A, B)                                                     \
    asm volatile("mma.sync.aligned.m16n8k16.row.col.f32.bf16.bf16.f32 "       \
                 "{%0,%1,%2,%3},{%4,%5,%6,%7},{%8,%9},{%0,%1,%2,%3};"         \
                 : "+f"((D)[0]), "+f"((D)[1]), "+f"((D)[2]), "+f"((D)[3])     \
                 : "r"((A)[0]), "r"((A)[1]), "r"((A)[2]), "r"((A)[3]),        \
                   "r"((B)[0]), "r"((B)[1]))
#define CP16(dst, src)                                                        \
    asm volatile("cp.async.cg.shared.global [%0],[%1],16;" :: "r"(dst), "l"(src))
#define CPCOMMIT() asm volatile("cp.async.commit_group;")
#define CPWAIT(n)  asm volatile("cp.async.wait_group %0;" :: "n"(n))

__device__ __forceinline__ uint32_t smem_u32(const void* p) {
    uint32_t a;
    asm("{ .reg .u64 t; cvta.to.shared.u64 t, %1; cvt.u32.u64 %0, t; }" : "=r"(a) : "l"(p));
    return a;
}

// split 8 fp32 -> 8 bf16 hi + 8 bf16 lo (16B each)
__device__ __forceinline__ void pack8(const float* v, uint4& hi, uint4& lo) {
    __nv_bfloat162 h[4], l[4];
#pragma unroll
    for (int e = 0; e < 4; e++) {
        h[e].x = __float2bfloat16(v[2 * e]);
        h[e].y = __float2bfloat16(v[2 * e + 1]);
        l[e].x = __float2bfloat16(v[2 * e]     - __bfloat162float(h[e].x));
        l[e].y = __float2bfloat16(v[2 * e + 1] - __bfloat162float(h[e].y));
    }
    hi = *(uint4*)h;
    lo = *(uint4*)l;
}

// ---------------- setup kernels ----------------
__global__ void k_make_qkv_bias(const float* __restrict__ qb,
                                const float* __restrict__ vb) {
    int i = blockIdx.x * blockDim.x + threadIdx.x;
    if (i < QKVC) {
        float v = 0.f;
        if (i < DIMC)            v = qb[i];
        else if (i >= 2 * DIMC)  v = vb[i - 2 * DIMC];
        g_qkv_bias[i] = v;
    }
}

__device__ __forceinline__ float cpb_coord(int u) {
    float t = (float)u * (8.0f / 7.0f);
    float s = (t > 0.f) ? 1.f : ((t < 0.f) ? -1.f : 0.f);
    return s * log2f(fabsf(t) + 1.0f) * (1.0f / 3.0f);
}

__global__ void k_cpb(const float* __restrict__ w1, const float* __restrict__ b1,
                      const float* __restrict__ w2) {
    __shared__ float hid[CPBH];
    int m = blockIdx.x;
    int k = threadIdx.x;
    float c0 = cpb_coord(m % 15 - 7);
    float c1 = cpb_coord(m / 15 - 7);
    hid[k] = fmaxf(fmaf(c0, w1[k], fmaf(c1, w1[CPBH + k], b1[k])), 0.f);
    __syncthreads();
    int warp = k >> 5, lane = k & 31;
    float s = 0.f;
    for (int kk = lane; kk < CPBH; kk += 32)
        s = fmaf(hid[kk], w2[kk * NHEADS + warp], s);
#pragma unroll
    for (int o = 16; o > 0; o >>= 1) s += __shfl_xor_sync(0xffffffffu, s, o);
    if (lane == 0) g_bias_table[m * NHEADS + warp] = s;
}

__global__ void k_rpb() {
    int id = blockIdx.x * blockDim.x + threadIdx.x;
    int h = id >> 12;
    int p = (id >> 6) & 63;
    int q = id & 63;
    int idx = (((p & 7) - (q & 7)) + 7) * 15 + (((p >> 3) - (q >> 3)) + 7);
    float v = g_bias_table[idx * NHEADS + h];
    g_rpb[id] = 16.0f / (1.0f + expf(-v));
}

// split fp32 -> (hi bf16, lo bf16), vectorized by 4
__global__ void k_split(const float* __restrict__ s, __nv_bfloat16* __restrict__ hi,
                        __nv_bfloat16* __restrict__ lo, int n4) {
    int i = blockIdx.x * blockDim.x + threadIdx.x;
    if (i < n4) {
        float4 v = *(const float4*)(s + i * 4);
        __nv_bfloat16 h0 = __float2bfloat16(v.x);
        __nv_bfloat16 h1 = __float2bfloat16(v.y);
        __nv_bfloat16 h2 = __float2bfloat16(v.z);
        __nv_bfloat16 h3 = __float2bfloat16(v.w);
        __nv_bfloat162 hh0, hh1, ll0, ll1;
        hh0.x = h0; hh0.y = h1; hh1.x = h2; hh1.y = h3;
        ll0.x = __float2bfloat16(v.x - __bfloat162float(h0));
        ll0.y = __float2bfloat16(v.y - __bfloat162float(h1));
        ll1.x = __float2bfloat16(v.z - __bfloat162float(h2));
        ll1.y = __float2bfloat16(v.w - __bfloat162float(h3));
        *(__nv_bfloat162*)(hi + i * 4)     = hh0;
        *(__nv_bfloat162*)(hi + i * 4 + 2) = hh1;
        *(__nv_bfloat162*)(lo + i * 4)     = ll0;
        *(__nv_bfloat162*)(lo + i * 4 + 2) = ll1;
    }
}

// transpose + split weights: w [K,N] fp32 -> hi/lo [N,K] bf16
__global__ void k_split_w_t(const float* __restrict__ w, __nv_bfloat16* __restrict__ hi,
                            __nv_bfloat16* __restrict__ lo, int K, int N) {
    int i = blockIdx.x * blockDim.x + threadIdx.x;
    if (i < K * N) {
        int n = i / K, k = i - n * K;
        float x = w[(size_t)k * N + n];
        __nv_bfloat16 h = __float2bfloat16(x);
        hi[i] = h;
        lo[i] = __float2bfloat16(x - __bfloat162float(h));
    }
}

// ---------------- split-bf16 HMMA GEMM, cp.async double-buffered ----------------
// C[M,N] = (Ah+Al)(Bh+Bl)^T (lo*lo dropped) + bias
// A* [M,K] bf16 row-major, B* [N,K] bf16 row-major. 128x128x32 tile, 256 thr.
// dyn smem: 2 stages x 4 arrays x [128][32]bf16 (8KB) = 64KB
#define GSMEM (2 * 4 * 8192)

__global__ __launch_bounds__(256) void gemm_mma(
    const __nv_bfloat16* __restrict__ Ahi, const __nv_bfloat16* __restrict__ Alo,
    const __nv_bfloat16* __restrict__ Bhi, const __nv_bfloat16* __restrict__ Blo,
    const float* __restrict__ bias, float* __restrict__ C,
    int M, int N, int K) {
    extern __shared__ char gsm[];
    const uint32_t sb = smem_u32(gsm);

    const int tid  = threadIdx.x;
    const int lane = tid & 31;
    const int warp = tid >> 5;
    const int wm = (warp >> 2) << 6;             // 0 / 64
    const int wn = (warp & 3) << 5;              // 0,32,64,96
    const int row0 = blockIdx.y * 128;
    const int col0 = blockIdx.x * 128;

    const __nv_bfloat16* src[4] = {Ahi + (size_t)row0 * K, Alo + (size_t)row0 * K,
                                   Bhi + (size_t)col0 * K, Blo + (size_t)col0 * K};

    // cp.async destinations (two rows per array per thread)
    const int r_g  = tid >> 2;
    const int r_g2 = r_g + 64;
    const int c_g  = tid & 3;
    const uint32_t dst1 = (uint32_t)((r_g  << 6) + ((c_g ^ ((r_g  >> 1) & 3)) << 4));
    const uint32_t dst2 = (uint32_t)((r_g2 << 6) + ((c_g ^ ((r_g2 >> 1) & 3)) << 4));

    // ldmatrix offsets within one tile
    uint32_t offA[4][2], offB[4][2];
#pragma unroll
    for (int mf = 0; mf < 4; mf++) {
        int r = wm + (mf << 4) + (lane & 15);
#pragma unroll
        for (int k2 = 0; k2 < 2; k2++) {
            int c16 = (lane >> 4) + (k2 << 1);
            offA[mf][k2] = (uint32_t)((r << 6) + ((c16 ^ ((r >> 1) & 3)) << 4));
        }
    }
#pragma unroll
    for (int nf = 0; nf < 4; nf++) {
        int r = wn + (nf << 3) + (lane & 7);
#pragma unroll
        for (int k2 = 0; k2 < 2; k2++) {
            int c16 = ((lane >> 3) & 1) + (k2 << 1);
            offB[nf][k2] = (uint32_t)((r << 6) + ((c16 ^ ((r >> 1) & 3)) << 4));
        }
    }

    float acc[4][4][4];
#pragma unroll
    for (int mf = 0; mf < 4; mf++)
#pragma unroll
        for (int nf = 0; nf < 4; nf++)
#pragma unroll
            for (int e = 0; e < 4; e++) acc[mf][nf][e] = 0.f;

    const int nchunks = K >> 5;

    // issue cp.async for (stage, kc)
    auto issue = [&](int stage, int kc) {
#pragma unroll
        for (int a = 0; a < 4; a++) {
            uint32_t base = sb + (uint32_t)(((stage << 2) + a) << 13);
            const char* g1 = (const char*)(src[a] + (size_t)r_g  * K + (kc << 5) + (c_g << 3));
            const char* g2 = (const char*)(src[a] + (size_t)r_g2 * K + (kc << 5) + (c_g << 3));
            CP16(base + dst1, g1);
            CP16(base + dst2, g2);
        }
        CPCOMMIT();
    };

    issue(0, 0);
    for (int kc = 0; kc < nchunks; kc++) {
        if (kc + 1 < nchunks) { issue((kc + 1) & 1, kc + 1); CPWAIT(1); }
        else                  { CPWAIT(0); }
        __syncthreads();

        const uint32_t st = sb + (uint32_t)((kc & 1) << 15);   // stage base (4 arrays x 8KB)
#pragma unroll
        for (int k2 = 0; k2 < 2; k2++) {
            uint32_t ah[4][4], al[4][4], bh[4][2], bl[4][2];
#pragma unroll
            for (int mf = 0; mf < 4; mf++) {
                LDSM4(ah[mf], st + offA[mf][k2]);
                LDSM4(al[mf], st + 8192 + offA[mf][k2]);
            }
#pragma unroll
            for (int nf = 0; nf < 4; nf++) {
                LDSM2(bh[nf], st + 16384 + offB[nf][k2]);
                LDSM2(bl[nf], st + 24576 + offB[nf][k2]);
            }
#pragma unroll
            for (int mf = 0; mf < 4; mf++)
#pragma unroll
                for (int nf = 0; nf < 4; nf++) {
                    MMA16816(acc[mf][nf], ah[mf], bh[nf]);
                    MMA16816(acc[mf][nf], ah[mf], bl[nf]);
                    MMA16816(acc[mf][nf], al[mf], bh[nf]);
                }
        }
        __syncthreads();
    }

    // epilogue: C-fragment -> gmem with bias
    const int qr = lane >> 2;
    const int qc = (lane & 3) << 1;
#pragma unroll
    for (int mf = 0; mf < 4; mf++) {
#pragma unroll
        for (int nf = 0; nf < 4; nf++) {
            int row = row0 + wm + (mf << 4) + qr;
            int col = col0 + wn + (nf << 3) + qc;
            float2 bi = *(const float2*)(bias + col);
            float2 v0, v1;
            v0.x = acc[mf][nf][0] + bi.x; v0.y = acc[mf][nf][1] + bi.y;
            v1.x = acc[mf][nf][2] + bi.x; v1.y = acc[mf][nf][3] + bi.y;
            *(float2*)(C + (size_t)row * N + col)       = v0;
            *(float2*)(C + (size_t)(row + 8) * N + col) = v1;
        }
    }
}

// ---------------- fused attention: split-bf16 HMMA per (window, head) ----------------
// dyn smem layout (bytes):
#define OQH 0
#define OQL 4096
#define OKH 8192
#define OKL 12288
#define OVH 16384
#define OVL 20480
#define OPH 24576
#define OPL 32768
#define OS  40960
#define OVV 24576                     /* fp32 V staging aliases PH/PL (used earlier) */
#define ATT_SMEM (40960 + 64 * 68 * 4)   /* 58368 */

__global__ __launch_bounds__(128) void k_attn(const float* __restrict__ mask,
                                              const float* __restrict__ logit_scale) {
    extern __shared__ char sm[];
    const int h = blockIdx.x;
    const int b = blockIdx.y;
    const int tid = threadIdx.x, lane = tid & 31, warp = tid >> 5;
    const uint32_t sbase = smem_u32(sm);

    // ---- stage V (fp32) : thread -> (token tid>>1, half of dims)
    {
        int tok = tid >> 1, half = (tid & 1) << 4;
        const float* vrow = g_qkv + (size_t)(b * NTOK + tok) * QKVC + 2 * DIMC + h * HD + half;
        float* dst = (float*)(sm + OVV) + tok * 33 + half;
#pragma unroll
        for (int i = 0; i < 4; i++) {
            float4 t = ((const float4*)vrow)[i];
            dst[4 * i + 0] = t.x; dst[4 * i + 1] = t.y;
            dst[4 * i + 2] = t.z; dst[4 * i + 3] = t.w;
        }
    }
    // ---- load q (t<64) or k row, normalize, fold scale, split hi/lo
    {
        int tok = tid & 63;
        bool isq = tid < 64;
        const float* row = g_qkv + (size_t)(b * NTOK + tok) * QKVC + (isq ? 0 : DIMC) + h * HD;
        float r[32];
#pragma unroll
        for (int i = 0; i < 8; i++) {
            float4 t = ((const float4*)row)[i];
            r[4 * i + 0] = t.x; r[4 * i + 1] = t.y; r[4 * i + 2] = t.z; r[4 * i + 3] = t.w;
        }
        float ss = 0.f;
#pragma unroll
        for (int i = 0; i < 32; i++) ss = fmaf(r[i], r[i], ss);
        float inv = rsqrtf(ss);
        if (isq) inv *= expf(fminf(logit_scale[h], 4.6051701860f));
#pragma unroll
        for (int i = 0; i < 32; i++) r[i] *= inv;
        char* hb = sm + (isq ? OQH : OKH) + (tok << 6);
        char* lb = sm + (isq ? OQL : OKL) + (tok << 6);
        int swz = (tok >> 1) & 3;
#pragma unroll
        for (int c = 0; c < 4; c++) {
            uint4 hi, lo;
            pack8(r + 8 * c, hi, lo);
            *(uint4*)(hb + ((c ^ swz) << 4)) = hi;
            *(uint4*)(lb + ((c ^ swz) << 4)) = lo;
        }
    }
    __syncthreads();

    // ---- transpose V: [64 tok][32 d] fp32 -> Vt [32 d][64 tok] bf16 hi/lo
    {
        int d = tid >> 2, jc = (tid & 3) << 4;
        const float* vv = (const float*)(sm + OVV);
        int swz = d & 7;
#pragma unroll
        for (int c2 = 0; c2 < 2; c2++) {
            float t[8];
#pragma unroll
            for (int e = 0; e < 8; e++) t[e] = vv[(jc + c2 * 8 + e) * 33 + d];
            uint4 hi, lo;
            pack8(t, hi, lo);
            int c = (jc >> 3) + c2;
            *(uint4*)(sm + OVH + (d << 7) + ((c ^ swz) << 4)) = hi;
            *(uint4*)(sm + OVL + (d << 7) + ((c ^ swz) << 4)) = lo;
        }
    }

    // ---- S = qn kn^T : warp w -> rows 16w..16w+15, fp32 accum
    {
        uint32_t ah[2][4], al[2][4];
        int ra = (warp << 4) + (lane & 15);
        int ca = lane >> 4;
        int swa = (ra >> 1) & 3;
#pragma unroll
        for (int k2 = 0; k2 < 2; k2++) {
            uint32_t off = (uint32_t)((ra << 6) + (((ca + (k2 << 1)) ^ swa) << 4));
            LDSM4(ah[k2], sbase + OQH + off);
            LDSM4(al[k2], sbase + OQL + off);
        }
        float* S = (float*)(sm + OS);
        int qr = lane >> 2, qc = (lane & 3) << 1;
#pragma unroll
        for (int nf = 0; nf < 8; nf++) {
            float acc[4] = {0.f, 0.f, 0.f, 0.f};
            int rb = (nf << 3) + (lane & 7);
            int swb = (rb >> 1) & 3;
#pragma unroll
            for (int k2 = 0; k2 < 2; k2++) {
                uint32_t off = (uint32_t)((rb << 6) +
                    (((((lane >> 3) & 1) + (k2 << 1)) ^ swb) << 4));
                uint32_t bh[2], bl[2];
                LDSM2(bh, sbase + OKH + off);
                LDSM2(bl, sbase + OKL + off);
                MMA16816(acc, ah[k2], bh);
                MMA16816(acc, ah[k2], bl);
                MMA16816(acc, al[k2], bh);
            }
            int row = (warp << 4) + qr, col = (nf << 3) + qc;
            *(float2*)(S + row * 68 + col)       = make_float2(acc[0], acc[1]);
            *(float2*)(S + (row + 8) * 68 + col) = make_float2(acc[2], acc[3]);
        }
    }
    __syncthreads();

    // ---- softmax row r (+rpb+mask), write P hi/lo bf16
    if (tid < 64) {
        int r = tid;
        float* Sp = (float*)(sm + OS) + r * 68;
        const float* mrow = mask + (size_t)(b & (NWIN - 1)) * NTOK * NTOK + r * 64;
        const float* rrow = g_rpb + (size_t)h * NTOK * NTOK + r * 64;
        float p[64];
        float mx = -1e30f;
#pragma unroll
        for (int j = 0; j < 64; j += 4) {
            float4 s4 = *(float4*)(Sp + j);
            float4 rb = *(const float4*)(rrow + j);
            float4 mk = *(const float4*)(mrow + j);
            p[j + 0] = s4.x + rb.x + mk.x;
            p[j + 1] = s4.y + rb.y + mk.y;
            p[j + 2] = s4.z + rb.z + mk.z;
            p[j + 3] = s4.w + rb.w + mk.w;
            mx = fmaxf(mx, fmaxf(fmaxf(p[j], p[j + 1]), fmaxf(p[j + 2], p[j + 3])));
        }
        float sum = 0.f;
#pragma unroll
        for (int j = 0; j < 64; j++) { p[j] = expf(p[j] - mx); sum += p[j]; }
        float inv = 1.0f / sum;
#pragma unroll
        for (int j = 0; j < 64; j++) p[j] *= inv;
        int swz = r & 7;
#pragma unroll
        for (int c = 0; c < 8; c++) {
            uint4 hi, lo;
            pack8(p + 8 * c, hi, lo);
            *(uint4*)(sm + OPH + (r << 7) + ((c ^ swz) << 4)) = hi;
            *(uint4*)(sm + OPL + (r << 7) + ((c ^ swz) << 4)) = lo;
        }
    }
    __syncthreads();

    // ---- O = P V : warp w -> rows 16w..16w+15, N=32, K=64
    {
        float acc[4][4];
#pragma unroll
        for (int nf = 0; nf < 4; nf++)
#pragma unroll
            for (int e = 0; e < 4; e++) acc[nf][e] = 0.f;
        int ra = (warp << 4) + (lane & 15);
        int ca = lane >> 4;
        int swa = ra & 7;
#pragma unroll
        for (int ks = 0; ks < 4; ks++) {
            uint32_t offp = (uint32_t)((ra << 7) + (((ca + (ks << 1)) ^ swa) << 4));
            uint32_t ph[4], pl[4];
            LDSM4(ph, sbase + OPH + offp);
            LDSM4(pl, sbase + OPL + offp);
#pragma unroll
            for (int nf = 0; nf < 4; nf++) {
                int rv = (nf << 3) + (lane & 7);
                int swv = rv & 7;
                uint32_t offv = (uint32_t)((rv << 7) +
                    (((((lane >> 3) & 1) + (ks << 1)) ^ swv) << 4));
                uint32_t vh[2], vl[2];
                LDSM2(vh, sbase + OVH + offv);
                LDSM2(vl, sbase + OVL + offv);
                MMA16816(acc[nf], ph, vh);
                MMA16816(acc[nf], ph, vl);
                MMA16816(acc[nf], pl, vh);
            }
        }
        // epilogue: fragments -> g_attn hi/lo bf16
        int qr = lane >> 2, qc = (lane & 3) << 1;
#pragma unroll
        for (int nf = 0; nf < 4; nf++) {
#pragma unroll
            for (int e = 0; e < 2; e++) {
                int row = (warp << 4) + qr + (e << 3);
                int col = (nf << 3) + qc;
                float v0 = acc[nf][e * 2], v1 = acc[nf][e * 2 + 1];
                size_t idx = (size_t)(b * NTOK + row) * DIMC + h * HD + col;
                __nv_bfloat162 hh, ll;
                hh.x = __float2bfloat16(v0);
                hh.y = __float2bfloat16(v1);
                ll.x = __float2bfloat16(v0 - __bfloat162float(hh.x));
                ll.y = __float2bfloat16(v1 - __bfloat162float(hh.y));
                *(__nv_bfloat162*)(g_attn_hi + idx) = hh;
                *(__nv_bfloat162*)(g_attn_lo + idx) = ll;
            }
        }
    }
}

// ---------------- launcher ----------------
extern "C" void kernel_launch(void* const* d_in, const int* in_sizes, int n_in,
                              void* d_out, int out_size) {
    (void)in_sizes; (void)n_in; (void)out_size;
    const float* x           = (const float*)d_in[0];
    const float* mask        = (const float*)d_in[1];
    const float* qkv_w       = (const float*)d_in[2];
    const float* q_bias      = (const float*)d_in[3];
    const float* v_bias      = (const float*)d_in[4];
    const float* logit_scale = (const float*)d_in[5];
    const float* cpb_w1      = (const float*)d_in[6];
    const float* cpb_b1      = (const float*)d_in[7];
    const float* cpb_w2      = (const float*)d_in[8];
    const float* proj_w      = (const float*)d_in[9];
    const float* proj_b      = (const float*)d_in[10];
    float* out = (float*)d_out;

    float *p_qkv, *p_qkvb;
    __nv_bfloat16 *p_xh, *p_xl, *p_ah, *p_al, *p_wqh, *p_wql, *p_wph, *p_wpl;
    cudaGetSymbolAddress((void**)&p_qkv,  g_qkv);
    cudaGetSymbolAddress((void**)&p_qkvb, g_qkv_bias);
    cudaGetSymbolAddress((void**)&p_xh,   g_x_hi);
    cudaGetSymbolAddress((void**)&p_xl,   g_x_lo);
    cudaGetSymbolAddress((void**)&p_ah,   g_attn_hi);
    cudaGetSymbolAddress((void**)&p_al,   g_attn_lo);
    cudaGetSymbolAddress((void**)&p_wqh,  g_wqkv_hi);
    cudaGetSymbolAddress((void**)&p_wql,  g_wqkv_lo);
    cudaGetSymbolAddress((void**)&p_wph,  g_wproj_hi);
    cudaGetSymbolAddress((void**)&p_wpl,  g_wproj_lo);

    cudaFuncSetAttribute(gemm_mma, cudaFuncAttributeMaxDynamicSharedMemorySize, GSMEM);
    cudaFuncSetAttribute(k_attn,   cudaFuncAttributeMaxDynamicSharedMemorySize, ATT_SMEM);

    k_make_qkv_bias<<<3, 512>>>(q_bias, v_bias);
    k_cpb<<<225, CPBH>>>(cpb_w1, cpb_b1, cpb_w2);
    k_rpb<<<64, 1024>>>();

    // split activations + weights to (hi, lo) bf16
    k_split<<<(NROWS * DIMC / 4 + 255) / 256, 256>>>(x, p_xh, p_xl, NROWS * DIMC / 4);
    k_split_w_t<<<(QKVC * DIMC + 255) / 256, 256>>>(qkv_w, p_wqh, p_wql, DIMC, QKVC);
    k_split_w_t<<<(DIMC * DIMC + 255) / 256, 256>>>(proj_w, p_wph, p_wpl, DIMC, DIMC);

    // QKV: (65536 x 1536) split-bf16 HMMA, cp.async pipelined
    gemm_mma<<<dim3(QKVC / 128, NROWS / 128), 256, GSMEM>>>(
        p_xh, p_xl, p_wqh, p_wql, p_qkvb, p_qkv, NROWS, QKVC, DIMC);

    // fused attention (HMMA S & O, fp32 softmax), emits hi/lo bf16
    k_attn<<<dim3(NHEADS, BWIN), 128, ATT_SMEM>>>(mask, logit_scale);

    // proj: (65536 x 512) split-bf16 HMMA -> d_out
    gemm_mma<<<dim3(DIMC / 128, NROWS / 128), 256, GSMEM>>>(
        p_ah, p_al, p_wph, p_wpl, proj_b, out, NROWS, DIMC, DIMC);
}

// round 11
// speedup vs baseline: 2.5954x; 1.2276x over previous
#include <cuda_runtime.h>
#include <cuda_bf16.h>
#include <cuda_fp16.h>
#include <cstdint>
#include <math.h>

// ---------------- problem constants ----------------
#define DIMC   512
#define NHEADS 16
#define HD     32
#define NTOK   64
#define BWIN   1024
#define NWIN   64
#define CPBH   512
#define NROWS  (BWIN * NTOK)          /* 65536 */
#define QKVC   (3 * DIMC)             /* 1536  */

// ---------------- device scratch (no allocs allowed) ----------------
__device__ float g_qkv[NROWS * QKVC];                 // fp32 qkv for attention
__device__ __half g_x_hi[NROWS * DIMC];
__device__ __half g_x_lo[NROWS * DIMC];
__device__ __half g_attn_hi[NROWS * DIMC];
__device__ __half g_attn_lo[NROWS * DIMC];
__device__ __half g_wqkv[QKVC * DIMC];                // [N=1536, K=512] transposed, fp16
__device__ __half g_wproj[DIMC * DIMC];               // [N=512, K=512] transposed, fp16
__device__ float g_bias_table[225 * NHEADS];
__device__ float g_rpb[NHEADS * NTOK * NTOK];
__device__ float g_qkv_bias[QKVC];

// ---------------- mma.sync helpers (arch-agnostic PTX) ----------------
#define LDSM4(R, addr)                                                        \
    asm volatile("ldmatrix.sync.aligned.m8n8.x4.shared.b16 {%0,%1,%2,%3},[%4];" \
                 : "=r"((R)[0]), "=r"((R)[1]), "=r"((R)[2]), "=r"((R)[3])     \
                 : "r"(addr))
#define LDSM2(R, addr)                                                        \
    asm volatile("ldmatrix.sync.aligned.m8n8.x2.shared.b16 {%0,%1},[%2];"     \
                 : "=r"((R)[0]), "=r"((R)[1]) : "r"(addr))
#define MMA16816(D, A, B)                                                     \
    asm volatile("mma.sync.aligned.m16n8k16.row.col.f32.bf16.bf16.f32 "       \
                 "{%0,%1,%2,%3},{%4,%5,%6,%7},{%8,%9},{%0,%1,%2,%3};"         \
                 : "+f"((D)[0]), "+f"((D)[1]), "+f"((D)[2]), "+f"((D)[3])     \
                 : "r"((A)[0]), "r"((A)[1]), "r"((A)[2]), "r"((A)[3]),        \
                   "r"((B)[0]), "r"((B)[1]))
#define MMAH16816(D, A, B)                                                    \
    asm volatile("mma.sync.aligned.m16n8k16.row.col.f32.f16.f16.f32 "         \
                 "{%0,%1,%2,%3},{%4,%5,%6,%7},{%8,%9},{%0,%1,%2,%3};"         \
                 : "+f"((D)[0]), "+f"((D)[1]), "+f"((D)[2]), "+f"((D)[3])     \
                 : "r"((A)[0]), "r"((A)[1]), "r"((A)[2]), "r"((A)[3]),        \
                   "r"((B)[0]), "r"((B)[1]))
#define CP16(dst, src)                                                        \
    asm volatile("cp.async.cg.shared.global [%0],[%1],16;" :: "r"(dst), "l"(src))
#define CPCOMMIT() asm volatile("cp.async.commit_group;")
#define CPWAIT(n)  asm volatile("cp.async.wait_group %0;" :: "n"(n))

__device__ __forceinline__ uint32_t smem_u32(const void* p) {
    uint32_t a;
    asm("{ .reg .u64 t; cvta.to.shared.u64 t, %1; cvt.u32.u64 %0, t; }" : "=r"(a) : "l"(p));
    return a;
}

// split 8 fp32 -> 8 bf16 hi + 8 bf16 lo (16B each)  [attention internal]
__device__ __forceinline__ void pack8(const float* v, uint4& hi, uint4& lo) {
    __nv_bfloat162 h[4], l[4];
#pragma unroll
    for (int e = 0; e < 4; e++) {
        h[e].x = __float2bfloat16(v[2 * e]);
        h[e].y = __float2bfloat16(v[2 * e + 1]);
        l[e].x = __float2bfloat16(v[2 * e]     - __bfloat162float(h[e].x));
        l[e].y = __float2bfloat16(v[2 * e + 1] - __bfloat162float(h[e].y));
    }
    hi = *(uint4*)h;
    lo = *(uint4*)l;
}

// ---------------- setup kernels ----------------
__global__ void k_make_qkv_bias(const float* __restrict__ qb,
                                const float* __restrict__ vb) {
    int i = blockIdx.x * blockDim.x + threadIdx.x;
    if (i < QKVC) {
        float v = 0.f;
        if (i < DIMC)            v = qb[i];
        else if (i >= 2 * DIMC)  v = vb[i - 2 * DIMC];
        g_qkv_bias[i] = v;
    }
}

__device__ __forceinline__ float cpb_coord(int u) {
    float t = (float)u * (8.0f / 7.0f);
    float s = (t > 0.f) ? 1.f : ((t < 0.f) ? -1.f : 0.f);
    return s * log2f(fabsf(t) + 1.0f) * (1.0f / 3.0f);
}

__global__ void k_cpb(const float* __restrict__ w1, const float* __restrict__ b1,
                      const float* __restrict__ w2) {
    __shared__ float hid[CPBH];
    int m = blockIdx.x;
    int k = threadIdx.x;
    float c0 = cpb_coord(m % 15 - 7);
    float c1 = cpb_coord(m / 15 - 7);
    hid[k] = fmaxf(fmaf(c0, w1[k], fmaf(c1, w1[CPBH + k], b1[k])), 0.f);
    __syncthreads();
    int warp = k >> 5, lane = k & 31;
    float s = 0.f;
    for (int kk = lane; kk < CPBH; kk += 32)
        s = fmaf(hid[kk], w2[kk * NHEADS + warp], s);
#pragma unroll
    for (int o = 16; o > 0; o >>= 1) s += __shfl_xor_sync(0xffffffffu, s, o);
    if (lane == 0) g_bias_table[m * NHEADS + warp] = s;
}

__global__ void k_rpb() {
    int id = blockIdx.x * blockDim.x + threadIdx.x;
    int h = id >> 12;
    int p = (id >> 6) & 63;
    int q = id & 63;
    int idx = (((p & 7) - (q & 7)) + 7) * 15 + (((p >> 3) - (q >> 3)) + 7);
    float v = g_bias_table[idx * NHEADS + h];
    g_rpb[id] = 16.0f / (1.0f + expf(-v));
}

// split fp32 -> (hi fp16, lo fp16), vectorized by 4
__global__ void k_split(const float* __restrict__ s, __half* __restrict__ hi,
                        __half* __restrict__ lo, int n4) {
    int i = blockIdx.x * blockDim.x + threadIdx.x;
    if (i < n4) {
        float4 v = *(const float4*)(s + i * 4);
        __half h0 = __float2half_rn(v.x);
        __half h1 = __float2half_rn(v.y);
        __half h2 = __float2half_rn(v.z);
        __half h3 = __float2half_rn(v.w);
        __half2 hh0, hh1, ll0, ll1;
        hh0.x = h0; hh0.y = h1; hh1.x = h2; hh1.y = h3;
        ll0.x = __float2half_rn(v.x - __half2float(h0));
        ll0.y = __float2half_rn(v.y - __half2float(h1));
        ll1.x = __float2half_rn(v.z - __half2float(h2));
        ll1.y = __float2half_rn(v.w - __half2float(h3));
        *(__half2*)(hi + i * 4)     = hh0;
        *(__half2*)(hi + i * 4 + 2) = hh1;
        *(__half2*)(lo + i * 4)     = ll0;
        *(__half2*)(lo + i * 4 + 2) = ll1;
    }
}

// transpose weights to single fp16: w [K,N] fp32 -> [N,K] fp16
__global__ void k_w_t(const float* __restrict__ w, __half* __restrict__ o,
                      int K, int N) {
    int i = blockIdx.x * blockDim.x + threadIdx.x;
    if (i < K * N) {
        int n = i / K, k = i - n * K;
        o[i] = __float2half_rn(w[(size_t)k * N + n]);
    }
}

// ---------------- split-fp16 HMMA GEMM, cp.async double-buffered ----------------
// C[M,N] = (Ah+Al) @ B^T + bias ; A hi/lo [M,K] fp16, B [N,K] fp16 (single).
// 128x128x32 tile, 256 thr. dyn smem: 2 stages x 3 arrays x 8KB = 48KB
#define GSMEM (2 * 3 * 8192)

__global__ __launch_bounds__(256) void gemm_mma(
    const __half* __restrict__ Ahi, const __half* __restrict__ Alo,
    const __half* __restrict__ B,
    const float* __restrict__ bias, float* __restrict__ C,
    int M, int N, int K) {
    extern __shared__ char gsm[];
    const uint32_t sb = smem_u32(gsm);

    const int tid  = threadIdx.x;
    const int lane = tid & 31;
    const int warp = tid >> 5;
    const int wm = (warp >> 2) << 6;             // 0 / 64
    const int wn = (warp & 3) << 5;              // 0,32,64,96
    const int row0 = blockIdx.y * 128;
    const int col0 = blockIdx.x * 128;

    const __half* src[3] = {Ahi + (size_t)row0 * K, Alo + (size_t)row0 * K,
                            B + (size_t)col0 * K};

    // cp.async destinations (two rows per array per thread)
    const int r_g  = tid >> 2;
    const int r_g2 = r_g + 64;
    const int c_g  = tid & 3;
    const uint32_t dst1 = (uint32_t)((r_g  << 6) + ((c_g ^ ((r_g  >> 1) & 3)) << 4));
    const uint32_t dst2 = (uint32_t)((r_g2 << 6) + ((c_g ^ ((r_g2 >> 1) & 3)) << 4));

    // ldmatrix offsets within one tile
    uint32_t offA[4][2], offB[4][2];
#pragma unroll
    for (int mf = 0; mf < 4; mf++) {
        int r = wm + (mf << 4) + (lane & 15);
#pragma unroll
        for (int k2 = 0; k2 < 2; k2++) {
            int c16 = (lane >> 4) + (k2 << 1);
            offA[mf][k2] = (uint32_t)((r << 6) + ((c16 ^ ((r >> 1) & 3)) << 4));
        }
    }
#pragma unroll
    for (int nf = 0; nf < 4; nf++) {
        int r = wn + (nf << 3) + (lane & 7);
#pragma unroll
        for (int k2 = 0; k2 < 2; k2++) {
            int c16 = ((lane >> 3) & 1) + (k2 << 1);
            offB[nf][k2] = (uint32_t)((r << 6) + ((c16 ^ ((r >> 1) & 3)) << 4));
        }
    }

    float acc[4][4][4];
#pragma unroll
    for (int mf = 0; mf < 4; mf++)
#pragma unroll
        for (int nf = 0; nf < 4; nf++)
#pragma unroll
            for (int e = 0; e < 4; e++) acc[mf][nf][e] = 0.f;

    const int nchunks = K >> 5;

    auto issue = [&](int stage, int kc) {
#pragma unroll
        for (int a = 0; a < 3; a++) {
            uint32_t base = sb + (uint32_t)((stage * 3 + a) << 13);
            const char* g1 = (const char*)(src[a] + (size_t)r_g  * K + (kc << 5) + (c_g << 3));
            const char* g2 = (const char*)(src[a] + (size_t)r_g2 * K + (kc << 5) + (c_g << 3));
            CP16(base + dst1, g1);
            CP16(base + dst2, g2);
        }
        CPCOMMIT();
    };

    issue(0, 0);
    for (int kc = 0; kc < nchunks; kc++) {
        if (kc + 1 < nchunks) { issue((kc + 1) & 1, kc + 1); CPWAIT(1); }
        else                  { CPWAIT(0); }
        __syncthreads();

        const uint32_t st = sb + (uint32_t)((kc & 1) * 24576);
#pragma unroll
        for (int k2 = 0; k2 < 2; k2++) {
            uint32_t ah[4][4], al[4][4], bh[4][2];
#pragma unroll
            for (int mf = 0; mf < 4; mf++) {
                LDSM4(ah[mf], st + offA[mf][k2]);
                LDSM4(al[mf], st + 8192 + offA[mf][k2]);
            }
#pragma unroll
            for (int nf = 0; nf < 4; nf++)
                LDSM2(bh[nf], st + 16384 + offB[nf][k2]);
#pragma unroll
            for (int mf = 0; mf < 4; mf++)
#pragma unroll
                for (int nf = 0; nf < 4; nf++) {
                    MMAH16816(acc[mf][nf], ah[mf], bh[nf]);
                    MMAH16816(acc[mf][nf], al[mf], bh[nf]);
                }
        }
        __syncthreads();
    }

    // epilogue: C-fragment -> gmem with bias
    const int qr = lane >> 2;
    const int qc = (lane & 3) << 1;
#pragma unroll
    for (int mf = 0; mf < 4; mf++) {
#pragma unroll
        for (int nf = 0; nf < 4; nf++) {
            int row = row0 + wm + (mf << 4) + qr;
            int col = col0 + wn + (nf << 3) + qc;
            float2 bi = *(const float2*)(bias + col);
            float2 v0, v1;
            v0.x = acc[mf][nf][0] + bi.x; v0.y = acc[mf][nf][1] + bi.y;
            v1.x = acc[mf][nf][2] + bi.x; v1.y = acc[mf][nf][3] + bi.y;
            *(float2*)(C + (size_t)row * N + col)       = v0;
            *(float2*)(C + (size_t)(row + 8) * N + col) = v1;
        }
    }
}

// ---------------- fused attention: split-bf16 HMMA per (window, head) ----------------
// dyn smem layout (bytes):
#define OQH 0
#define OQL 4096
#define OKH 8192
#define OKL 12288
#define OVH 16384
#define OVL 20480
#define OPH 24576
#define OPL 32768
#define OS  40960
#define OVV 24576                     /* fp32 V staging aliases PH/PL (used earlier) */
#define ATT_SMEM (40960 + 64 * 68 * 4)   /* 58368 */

__global__ __launch_bounds__(128) void k_attn(const float* __restrict__ mask,
                                              const float* __restrict__ logit_scale) {
    extern __shared__ char sm[];
    const int h = blockIdx.x;
    const int b = blockIdx.y;
    const int tid = threadIdx.x, lane = tid & 31, warp = tid >> 5;
    const uint32_t sbase = smem_u32(sm);

    // ---- stage V (fp32)
    {
        int tok = tid >> 1, half = (tid & 1) << 4;
        const float* vrow = g_qkv + (size_t)(b * NTOK + tok) * QKVC + 2 * DIMC + h * HD + half;
        float* dst = (float*)(sm + OVV) + tok * 33 + half;
#pragma unroll
        for (int i = 0; i < 4; i++) {
            float4 t = ((const float4*)vrow)[i];
            dst[4 * i + 0] = t.x; dst[4 * i + 1] = t.y;
            dst[4 * i + 2] = t.z; dst[4 * i + 3] = t.w;
        }
    }
    // ---- load q (t<64) or k row, normalize, fold scale, split hi/lo
    {
        int tok = tid & 63;
        bool isq = tid < 64;
        const float* row = g_qkv + (size_t)(b * NTOK + tok) * QKVC + (isq ? 0 : DIMC) + h * HD;
        float r[32];
#pragma unroll
        for (int i = 0; i < 8; i++) {
            float4 t = ((const float4*)row)[i];
            r[4 * i + 0] = t.x; r[4 * i + 1] = t.y; r[4 * i + 2] = t.z; r[4 * i + 3] = t.w;
        }
        float ss = 0.f;
#pragma unroll
        for (int i = 0; i < 32; i++) ss = fmaf(r[i], r[i], ss);
        float inv = rsqrtf(ss);
        if (isq) inv *= expf(fminf(logit_scale[h], 4.6051701860f));
#pragma unroll
        for (int i = 0; i < 32; i++) r[i] *= inv;
        char* hb = sm + (isq ? OQH : OKH) + (tok << 6);
        char* lb = sm + (isq ? OQL : OKL) + (tok << 6);
        int swz = (tok >> 1) & 3;
#pragma unroll
        for (int c = 0; c < 4; c++) {
            uint4 hi, lo;
            pack8(r + 8 * c, hi, lo);
            *(uint4*)(hb + ((c ^ swz) << 4)) = hi;
            *(uint4*)(lb + ((c ^ swz) << 4)) = lo;
        }
    }
    __syncthreads();

    // ---- transpose V: [64 tok][32 d] fp32 -> Vt [32 d][64 tok] bf16 hi/lo
    {
        int d = tid >> 2, jc = (tid & 3) << 4;
        const float* vv = (const float*)(sm + OVV);
        int swz = d & 7;
#pragma unroll
        for (int c2 = 0; c2 < 2; c2++) {
            float t[8];
#pragma unroll
            for (int e = 0; e < 8; e++) t[e] = vv[(jc + c2 * 8 + e) * 33 + d];
            uint4 hi, lo;
            pack8(t, hi, lo);
            int c = (jc >> 3) + c2;
            *(uint4*)(sm + OVH + (d << 7) + ((c ^ swz) << 4)) = hi;
            *(uint4*)(sm + OVL + (d << 7) + ((c ^ swz) << 4)) = lo;
        }
    }

    // ---- S = qn kn^T
    {
        uint32_t ah[2][4], al[2][4];
        int ra = (warp << 4) + (lane & 15);
        int ca = lane >> 4;
        int swa = (ra >> 1) & 3;
#pragma unroll
        for (int k2 = 0; k2 < 2; k2++) {
            uint32_t off = (uint32_t)((ra << 6) + (((ca + (k2 << 1)) ^ swa) << 4));
            LDSM4(ah[k2], sbase + OQH + off);
            LDSM4(al[k2], sbase + OQL + off);
        }
        float* S = (float*)(sm + OS);
        int qr = lane >> 2, qc = (lane & 3) << 1;
#pragma unroll
        for (int nf = 0; nf < 8; nf++) {
            float acc[4] = {0.f, 0.f, 0.f, 0.f};
            int rb = (nf << 3) + (lane & 7);
            int swb = (rb >> 1) & 3;
#pragma unroll
            for (int k2 = 0; k2 < 2; k2++) {
                uint32_t off = (uint32_t)((rb << 6) +
                    (((((lane >> 3) & 1) + (k2 << 1)) ^ swb) << 4));
                uint32_t bh[2], bl[2];
                LDSM2(bh, sbase + OKH + off);
                LDSM2(bl, sbase + OKL + off);
                MMA16816(acc, ah[k2], bh);
                MMA16816(acc, ah[k2], bl);
                MMA16816(acc, al[k2], bh);
            }
            int row = (warp << 4) + qr, col = (nf << 3) + qc;
            *(float2*)(S + row * 68 + col)       = make_float2(acc[0], acc[1]);
            *(float2*)(S + (row + 8) * 68 + col) = make_float2(acc[2], acc[3]);
        }
    }
    __syncthreads();

    // ---- softmax row r (+rpb+mask), write P hi/lo bf16
    if (tid < 64) {
        int r = tid;
        float* Sp = (float*)(sm + OS) + r * 68;
        const float* mrow = mask + (size_t)(b & (NWIN - 1)) * NTOK * NTOK + r * 64;
        const float* rrow = g_rpb + (size_t)h * NTOK * NTOK + r * 64;
        float p[64];
        float mx = -1e30f;
#pragma unroll
        for (int j = 0; j < 64; j += 4) {
            float4 s4 = *(float4*)(Sp + j);
            float4 rb = *(const float4*)(rrow + j);
            float4 mk = *(const float4*)(mrow + j);
            p[j + 0] = s4.x + rb.x + mk.x;
            p[j + 1] = s4.y + rb.y + mk.y;
            p[j + 2] = s4.z + rb.z + mk.z;
            p[j + 3] = s4.w + rb.w + mk.w;
            mx = fmaxf(mx, fmaxf(fmaxf(p[j], p[j + 1]), fmaxf(p[j + 2], p[j + 3])));
        }
        float sum = 0.f;
#pragma unroll
        for (int j = 0; j < 64; j++) { p[j] = expf(p[j] - mx); sum += p[j]; }
        float inv = 1.0f / sum;
#pragma unroll
        for (int j = 0; j < 64; j++) p[j] *= inv;
        int swz = r & 7;
#pragma unroll
        for (int c = 0; c < 8; c++) {
            uint4 hi, lo;
            pack8(p + 8 * c, hi, lo);
            *(uint4*)(sm + OPH + (r << 7) + ((c ^ swz) << 4)) = hi;
            *(uint4*)(sm + OPL + (r << 7) + ((c ^ swz) << 4)) = lo;
        }
    }
    __syncthreads();

    // ---- O = P V ; epilogue emits fp16 hi/lo for proj GEMM
    {
        float acc[4][4];
#pragma unroll
        for (int nf = 0; nf < 4; nf++)
#pragma unroll
            for (int e = 0; e < 4; e++) acc[nf][e] = 0.f;
        int ra = (warp << 4) + (lane & 15);
        int ca = lane >> 4;
        int swa = ra & 7;
#pragma unroll
        for (int ks = 0; ks < 4; ks++) {
            uint32_t offp = (uint32_t)((ra << 7) + (((ca + (ks << 1)) ^ swa) << 4));
            uint32_t ph[4], pl[4];
            LDSM4(ph, sbase + OPH + offp);
            LDSM4(pl, sbase + OPL + offp);
#pragma unroll
            for (int nf = 0; nf < 4; nf++) {
                int rv = (nf << 3) + (lane & 7);
                int swv = rv & 7;
                uint32_t offv = (uint32_t)((rv << 7) +
                    (((((lane >> 3) & 1) + (ks << 1)) ^ swv) << 4));
                uint32_t vh[2], vl[2];
                LDSM2(vh, sbase + OVH + offv);
                LDSM2(vl, sbase + OVL + offv);
                MMA16816(acc[nf], ph, vh);
                MMA16816(acc[nf], ph, vl);
                MMA16816(acc[nf], pl, vh);
            }
        }
        int qr = lane >> 2, qc = (lane & 3) << 1;
#pragma unroll
        for (int nf = 0; nf < 4; nf++) {
#pragma unroll
            for (int e = 0; e < 2; e++) {
                int row = (warp << 4) + qr + (e << 3);
                int col = (nf << 3) + qc;
                float v0 = acc[nf][e * 2], v1 = acc[nf][e * 2 + 1];
                size_t idx = (size_t)(b * NTOK + row) * DIMC + h * HD + col;
                __half2 hh, ll;
                hh.x = __float2half_rn(v0);
                hh.y = __float2half_rn(v1);
                ll.x = __float2half_rn(v0 - __half2float(hh.x));
                ll.y = __float2half_rn(v1 - __half2float(hh.y));
                *(__half2*)(g_attn_hi + idx) = hh;
                *(__half2*)(g_attn_lo + idx) = ll;
            }
        }
    }
}

// ---------------- launcher ----------------
extern "C" void kernel_launch(void* const* d_in, const int* in_sizes, int n_in,
                              void* d_out, int out_size) {
    (void)in_sizes; (void)n_in; (void)out_size;
    const float* x           = (const float*)d_in[0];
    const float* mask        = (const float*)d_in[1];
    const float* qkv_w       = (const float*)d_in[2];
    const float* q_bias      = (const float*)d_in[3];
    const float* v_bias      = (const float*)d_in[4];
    const float* logit_scale = (const float*)d_in[5];
    const float* cpb_w1      = (const float*)d_in[6];
    const float* cpb_b1      = (const float*)d_in[7];
    const float* cpb_w2      = (const float*)d_in[8];
    const float* proj_w      = (const float*)d_in[9];
    const float* proj_b      = (const float*)d_in[10];
    float* out = (float*)d_out;

    float *p_qkv, *p_qkvb;
    __half *p_xh, *p_xl, *p_ah, *p_al, *p_wq, *p_wp;
    cudaGetSymbolAddress((void**)&p_qkv,  g_qkv);
    cudaGetSymbolAddress((void**)&p_qkvb, g_qkv_bias);
    cudaGetSymbolAddress((void**)&p_xh,   g_x_hi);
    cudaGetSymbolAddress((void**)&p_xl,   g_x_lo);
    cudaGetSymbolAddress((void**)&p_ah,   g_attn_hi);
    cudaGetSymbolAddress((void**)&p_al,   g_attn_lo);
    cudaGetSymbolAddress((void**)&p_wq,   g_wqkv);
    cudaGetSymbolAddress((void**)&p_wp,   g_wproj);

    cudaFuncSetAttribute(gemm_mma, cudaFuncAttributeMaxDynamicSharedMemorySize, GSMEM);
    cudaFuncSetAttribute(k_attn,   cudaFuncAttributeMaxDynamicSharedMemorySize, ATT_SMEM);

    k_make_qkv_bias<<<3, 512>>>(q_bias, v_bias);
    k_cpb<<<225, CPBH>>>(cpb_w1, cpb_b1, cpb_w2);
    k_rpb<<<64, 1024>>>();

    // split activations; weights -> single fp16 transposed
    k_split<<<(NROWS * DIMC / 4 + 255) / 256, 256>>>(x, p_xh, p_xl, NROWS * DIMC / 4);
    k_w_t<<<(QKVC * DIMC + 255) / 256, 256>>>(qkv_w, p_wq, DIMC, QKVC);
    k_w_t<<<(DIMC * DIMC + 255) / 256, 256>>>(proj_w, p_wp, DIMC, DIMC);

    // QKV: (65536 x 1536) 2-product fp16 HMMA, cp.async pipelined
    gemm_mma<<<dim3(QKVC / 128, NROWS / 128), 256, GSMEM>>>(
        p_xh, p_xl, p_wq, p_qkvb, p_qkv, NROWS, QKVC, DIMC);

    // fused attention (HMMA S & O, fp32 softmax), emits fp16 hi/lo
    k_attn<<<dim3(NHEADS, BWIN), 128, ATT_SMEM>>>(mask, logit_scale);

    // proj: (65536 x 512) 2-product fp16 HMMA -> d_out
    gemm_mma<<<dim3(DIMC / 128, NROWS / 128), 256, GSMEM>>>(
        p_ah, p_al, p_wp, proj_b, out, NROWS, DIMC, DIMC);
}

// round 13
// speedup vs baseline: 2.8619x; 1.1027x over previous
#include <cuda_runtime.h>
#include <cuda_bf16.h>
#include <cuda_fp16.h>
#include <cstdint>
#include <math.h>

// ---------------- problem constants ----------------
#define DIMC   512
#define NHEADS 16
#define HD     32
#define NTOK   64
#define BWIN   1024
#define NWIN   64
#define CPBH   512
#define NROWS  (BWIN * NTOK)          /* 65536 */
#define QKVC   (3 * DIMC)             /* 1536  */

// ---------------- device scratch (no allocs allowed) ----------------
__device__ __nv_bfloat16 g_q_hi[NROWS * DIMC];   // normalized*scale q, bf16 hi/lo
__device__ __nv_bfloat16 g_q_lo[NROWS * DIMC];
__device__ __nv_bfloat16 g_k_hi[NROWS * DIMC];   // normalized k
__device__ __nv_bfloat16 g_k_lo[NROWS * DIMC];
__device__ float g_v[NROWS * DIMC];              // v fp32
__device__ __half g_x_hi[NROWS * DIMC];
__device__ __half g_x_lo[NROWS * DIMC];
__device__ __half g_attn_hi[NROWS * DIMC];
__device__ __half g_attn_lo[NROWS * DIMC];
__device__ __half g_wqkv[QKVC * DIMC];           // [N=1536, K=512] transposed, fp16
__device__ __half g_wproj[DIMC * DIMC];          // [N=512, K=512] transposed, fp16
__device__ float g_bias_table[225 * NHEADS];
__device__ float g_rpb[NHEADS * NTOK * NTOK];
__device__ float g_qkv_bias[QKVC];

// ---------------- mma.sync helpers (arch-agnostic PTX) ----------------
#define LDSM4(R, addr)                                                        \
    asm volatile("ldmatrix.sync.aligned.m8n8.x4.shared.b16 {%0,%1,%2,%3},[%4];" \
                 : "=r"((R)[0]), "=r"((R)[1]), "=r"((R)[2]), "=r"((R)[3])     \
                 : "r"(addr))
#define LDSM2(R, addr)                                                        \
    asm volatile("ldmatrix.sync.aligned.m8n8.x2.shared.b16 {%0,%1},[%2];"     \
                 : "=r"((R)[0]), "=r"((R)[1]) : "r"(addr))
#define MMA16816(D, A, B)                                                     \
    asm volatile("mma.sync.aligned.m16n8k16.row.col.f32.bf16.bf16.f32 "       \
                 "{%0,%1,%2,%3},{%4,%5,%6,%7},{%8,%9},{%0,%1,%2,%3};"         \
                 : "+f"((D)[0]), "+f"((D)[1]), "+f"((D)[2]), "+f"((D)[3])     \
                 : "r"((A)[0]), "r"((A)[1]), "r"((A)[2]), "r"((A)[3]),        \
                   "r"((B)[0]), "r"((B)[1]))
#define MMAH16816(D, A, B)                                                    \
    asm volatile("mma.sync.aligned.m16n8k16.row.col.f32.f16.f16.f32 "         \
                 "{%0,%1,%2,%3},{%4,%5,%6,%7},{%8,%9},{%0,%1,%2,%3};"         \
                 : "+f"((D)[0]), "+f"((D)[1]), "+f"((D)[2]), "+f"((D)[3])     \
                 : "r"((A)[0]), "r"((A)[1]), "r"((A)[2]), "r"((A)[3]),        \
                   "r"((B)[0]), "r"((B)[1]))
#define CP16(dst, src)                                                        \
    asm volatile("cp.async.cg.shared.global [%0],[%1],16;" :: "r"(dst), "l"(src))
#define CPCOMMIT() asm volatile("cp.async.commit_group;")
#define CPWAIT(n)  asm volatile("cp.async.wait_group %0;" :: "n"(n))

__device__ __forceinline__ uint32_t smem_u32(const void* p) {
    uint32_t a;
    asm("{ .reg .u64 t; cvta.to.shared.u64 t, %1; cvt.u32.u64 %0, t; }" : "=r"(a) : "l"(p));
    return a;
}

// split 8 fp32 -> 8 bf16 hi + 8 bf16 lo (16B each)
__device__ __forceinline__ void pack8(const float* v, uint4& hi, uint4& lo) {
    __nv_bfloat162 h[4], l[4];
#pragma unroll
    for (int e = 0; e < 4; e++) {
        h[e].x = __float2bfloat16(v[2 * e]);
        h[e].y = __float2bfloat16(v[2 * e + 1]);
        l[e].x = __float2bfloat16(v[2 * e]     - __bfloat162float(h[e].x));
        l[e].y = __float2bfloat16(v[2 * e + 1] - __bfloat162float(h[e].y));
    }
    hi = *(uint4*)h;
    lo = *(uint4*)l;
}

// ---------------- setup kernels ----------------
__global__ void k_make_qkv_bias(const float* __restrict__ qb,
                                const float* __restrict__ vb) {
    int i = blockIdx.x * blockDim.x + threadIdx.x;
    if (i < QKVC) {
        float v = 0.f;
        if (i < DIMC)            v = qb[i];
        else if (i >= 2 * DIMC)  v = vb[i - 2 * DIMC];
        g_qkv_bias[i] = v;
    }
}

__device__ __forceinline__ float cpb_coord(int u) {
    float t = (float)u * (8.0f / 7.0f);
    float s = (t > 0.f) ? 1.f : ((t < 0.f) ? -1.f : 0.f);
    return s * log2f(fabsf(t) + 1.0f) * (1.0f / 3.0f);
}

__global__ void k_cpb(const float* __restrict__ w1, const float* __restrict__ b1,
                      const float* __restrict__ w2) {
    __shared__ float hid[CPBH];
    int m = blockIdx.x;
    int k = threadIdx.x;
    float c0 = cpb_coord(m % 15 - 7);
    float c1 = cpb_coord(m / 15 - 7);
    hid[k] = fmaxf(fmaf(c0, w1[k], fmaf(c1, w1[CPBH + k], b1[k])), 0.f);
    __syncthreads();
    int warp = k >> 5, lane = k & 31;
    float s = 0.f;
    for (int kk = lane; kk < CPBH; kk += 32)
        s = fmaf(hid[kk], w2[kk * NHEADS + warp], s);
#pragma unroll
    for (int o = 16; o > 0; o >>= 1) s += __shfl_xor_sync(0xffffffffu, s, o);
    if (lane == 0) g_bias_table[m * NHEADS + warp] = s;
}

__global__ void k_rpb() {
    int id = blockIdx.x * blockDim.x + threadIdx.x;
    int h = id >> 12;
    int p = (id >> 6) & 63;
    int q = id & 63;
    int idx = (((p & 7) - (q & 7)) + 7) * 15 + (((p >> 3) - (q >> 3)) + 7);
    float v = g_bias_table[idx * NHEADS + h];
    g_rpb[id] = 16.0f / (1.0f + expf(-v));
}

// split fp32 -> (hi fp16, lo fp16), vectorized by 4
__global__ void k_split(const float* __restrict__ s, __half* __restrict__ hi,
                        __half* __restrict__ lo, int n4) {
    int i = blockIdx.x * blockDim.x + threadIdx.x;
    if (i < n4) {
        float4 v = *(const float4*)(s + i * 4);
        __half h0 = __float2half_rn(v.x);
        __half h1 = __float2half_rn(v.y);
        __half h2 = __float2half_rn(v.z);
        __half h3 = __float2half_rn(v.w);
        __half2 hh0, hh1, ll0, ll1;
        hh0.x = h0; hh0.y = h1; hh1.x = h2; hh1.y = h3;
        ll0.x = __float2half_rn(v.x - __half2float(h0));
        ll0.y = __float2half_rn(v.y - __half2float(h1));
        ll1.x = __float2half_rn(v.z - __half2float(h2));
        ll1.y = __float2half_rn(v.w - __half2float(h3));
        *(__half2*)(hi + i * 4)     = hh0;
        *(__half2*)(hi + i * 4 + 2) = hh1;
        *(__half2*)(lo + i * 4)     = ll0;
        *(__half2*)(lo + i * 4 + 2) = ll1;
    }
}

// transpose weights to single fp16: w [K,N] fp32 -> [N,K] fp16
__global__ void k_w_t(const float* __restrict__ w, __half* __restrict__ o,
                      int K, int N) {
    int i = blockIdx.x * blockDim.x + threadIdx.x;
    if (i < K * N) {
        int n = i / K, k = i - n * K;
        o[i] = __float2half_rn(w[(size_t)k * N + n]);
    }
}

// ---------------- split-fp16 HMMA GEMM, 3-stage cp.async ----------------
// C = (Ah+Al) @ B^T ; 128x128x32 tile, 256 thr, 3 stages x 3 arrays x 8KB = 72KB.
// fuse=1 (QKV): sections q/k normalized (+logit scale for q) -> bf16 hi/lo; v -> fp32.
#define GSMEM (3 * 3 * 8192)

__global__ __launch_bounds__(256) void gemm_mma(
    const __half* __restrict__ Ahi, const __half* __restrict__ Alo,
    const __half* __restrict__ B,
    const float* __restrict__ bias, float* __restrict__ C,
    __nv_bfloat16* __restrict__ qh, __nv_bfloat16* __restrict__ ql,
    __nv_bfloat16* __restrict__ kh, __nv_bfloat16* __restrict__ kl,
    float* __restrict__ vout, const float* __restrict__ lsc,
    int fuse, int M, int N, int K) {
    extern __shared__ char gsm[];
    const uint32_t sb = smem_u32(gsm);

    const int tid  = threadIdx.x;
    const int lane = tid & 31;
    const int warp = tid >> 5;
    const int wm = (warp >> 2) << 6;
    const int wn = (warp & 3) << 5;
    const int row0 = blockIdx.y * 128;
    const int col0 = blockIdx.x * 128;

    const __half* src[3] = {Ahi + (size_t)row0 * K, Alo + (size_t)row0 * K,
                            B + (size_t)col0 * K};

    const int r_g  = tid >> 2;
    const int r_g2 = r_g + 64;
    const int c_g  = tid & 3;
    const uint32_t dst1 = (uint32_t)((r_g  << 6) + ((c_g ^ ((r_g  >> 1) & 3)) << 4));
    const uint32_t dst2 = (uint32_t)((r_g2 << 6) + ((c_g ^ ((r_g2 >> 1) & 3)) << 4));

    uint32_t offA[4][2], offB[4][2];
#pragma unroll
    for (int mf = 0; mf < 4; mf++) {
        int r = wm + (mf << 4) + (lane & 15);
#pragma unroll
        for (int k2 = 0; k2 < 2; k2++) {
            int c16 = (lane >> 4) + (k2 << 1);
            offA[mf][k2] = (uint32_t)((r << 6) + ((c16 ^ ((r >> 1) & 3)) << 4));
        }
    }
#pragma unroll
    for (int nf = 0; nf < 4; nf++) {
        int r = wn + (nf << 3) + (lane & 7);
#pragma unroll
        for (int k2 = 0; k2 < 2; k2++) {
            int c16 = ((lane >> 3) & 1) + (k2 << 1);
            offB[nf][k2] = (uint32_t)((r << 6) + ((c16 ^ ((r >> 1) & 3)) << 4));
        }
    }

    float acc[4][4][4];
#pragma unroll
    for (int mf = 0; mf < 4; mf++)
#pragma unroll
        for (int nf = 0; nf < 4; nf++)
#pragma unroll
            for (int e = 0; e < 4; e++) acc[mf][nf][e] = 0.f;

    const int nchunks = K >> 5;     // 16

    auto issue = [&](int stage, int kc) {
#pragma unroll
        for (int a = 0; a < 3; a++) {
            uint32_t base = sb + (uint32_t)((stage * 3 + a) << 13);
            const char* g1 = (const char*)(src[a] + (size_t)r_g  * K + (kc << 5) + (c_g << 3));
            const char* g2 = (const char*)(src[a] + (size_t)r_g2 * K + (kc << 5) + (c_g << 3));
            CP16(base + dst1, g1);
            CP16(base + dst2, g2);
        }
        CPCOMMIT();
    };

    issue(0, 0);
    issue(1, 1);
    int stage = 0;
    for (int kc = 0; kc < nchunks; kc++) {
        if (kc == nchunks - 1) { CPWAIT(0); } else { CPWAIT(1); }
        __syncthreads();

        const uint32_t st = sb + (uint32_t)(stage * 24576);
#pragma unroll
        for (int k2 = 0; k2 < 2; k2++) {
            uint32_t ah[4][4], al[4][4], bh[4][2];
#pragma unroll
            for (int mf = 0; mf < 4; mf++) {
                LDSM4(ah[mf], st + offA[mf][k2]);
                LDSM4(al[mf], st + 8192 + offA[mf][k2]);
            }
#pragma unroll
            for (int nf = 0; nf < 4; nf++)
                LDSM2(bh[nf], st + 16384 + offB[nf][k2]);
#pragma unroll
            for (int mf = 0; mf < 4; mf++)
#pragma unroll
                for (int nf = 0; nf < 4; nf++) {
                    MMAH16816(acc[mf][nf], ah[mf], bh[nf]);
                    MMAH16816(acc[mf][nf], al[mf], bh[nf]);
                }
        }
        // chunk kc+2 -> stage (kc+2)%3 == (kc-1)%3, whose readers finished at
        // the barrier above (fixed stage rotation — was the R12 NaN bug)
        if (kc + 2 < nchunks) {
            int tgt = stage + 2;
            if (tgt >= 3) tgt -= 3;
            issue(tgt, kc + 2);
        }
        stage = (stage == 2) ? 0 : stage + 1;
    }

    const int qr = lane >> 2;
    const int qc = (lane & 3) << 1;

    // add bias into acc
#pragma unroll
    for (int nf = 0; nf < 4; nf++) {
        float2 bi = *(const float2*)(bias + col0 + wn + (nf << 3) + qc);
#pragma unroll
        for (int mf = 0; mf < 4; mf++) {
            acc[mf][nf][0] += bi.x; acc[mf][nf][1] += bi.y;
            acc[mf][nf][2] += bi.x; acc[mf][nf][3] += bi.y;
        }
    }

    if (!fuse) {
#pragma unroll
        for (int mf = 0; mf < 4; mf++)
#pragma unroll
            for (int nf = 0; nf < 4; nf++) {
                int row = row0 + wm + (mf << 4) + qr;
                int col = col0 + wn + (nf << 3) + qc;
                *(float2*)(C + (size_t)row * N + col) =
                    make_float2(acc[mf][nf][0], acc[mf][nf][1]);
                *(float2*)(C + (size_t)(row + 8) * N + col) =
                    make_float2(acc[mf][nf][2], acc[mf][nf][3]);
            }
        return;
    }

    const int sec = blockIdx.x >> 2;          // 0=q, 1=k, 2=v
    if (sec < 2) {
        float scale = 1.f;
        if (sec == 0) {
            int h = (col0 + wn) >> 5;          // warp covers exactly one head
            scale = expf(fminf(lsc[h], 4.6051701860f));
        }
#pragma unroll
        for (int mf = 0; mf < 4; mf++) {
#pragma unroll
            for (int e = 0; e < 2; e++) {
                float ss = 0.f;
#pragma unroll
                for (int nf = 0; nf < 4; nf++) {
                    float a0 = acc[mf][nf][e * 2], a1 = acc[mf][nf][e * 2 + 1];
                    ss = fmaf(a0, a0, fmaf(a1, a1, ss));
                }
                ss += __shfl_xor_sync(0xffffffffu, ss, 1);
                ss += __shfl_xor_sync(0xffffffffu, ss, 2);
                float inv = rsqrtf(ss) * scale;
                int row = row0 + wm + (mf << 4) + (e << 3) + qr;
#pragma unroll
                for (int nf = 0; nf < 4; nf++) {
                    int col = col0 + wn + (nf << 3) + qc - sec * 512;
                    float v0 = acc[mf][nf][e * 2] * inv;
                    float v1 = acc[mf][nf][e * 2 + 1] * inv;
                    __nv_bfloat162 hh, ll;
                    hh.x = __float2bfloat16(v0);
                    hh.y = __float2bfloat16(v1);
                    ll.x = __float2bfloat16(v0 - __bfloat162float(hh.x));
                    ll.y = __float2bfloat16(v1 - __bfloat162float(hh.y));
                    size_t idx = (size_t)row * DIMC + col;
                    if (sec == 0) {
                        *(__nv_bfloat162*)(qh + idx) = hh;
                        *(__nv_bfloat162*)(ql + idx) = ll;
                    } else {
                        *(__nv_bfloat162*)(kh + idx) = hh;
                        *(__nv_bfloat162*)(kl + idx) = ll;
                    }
                }
            }
        }
    } else {
#pragma unroll
        for (int mf = 0; mf < 4; mf++)
#pragma unroll
            for (int nf = 0; nf < 4; nf++) {
                int row = row0 + wm + (mf << 4) + qr;
                int col = col0 + wn + (nf << 3) + qc - 1024;
                *(float2*)(vout + (size_t)row * DIMC + col) =
                    make_float2(acc[mf][nf][0], acc[mf][nf][1]);
                *(float2*)(vout + (size_t)(row + 8) * DIMC + col) =
                    make_float2(acc[mf][nf][2], acc[mf][nf][3]);
            }
    }
}

// ---------------- fused attention: split-bf16 HMMA per (window, head) ----------------
#define OQH 0
#define OQL 4096
#define OKH 8192
#define OKL 12288
#define OVH 16384
#define OVL 20480
#define OPH 24576
#define OPL 32768
#define OS  40960
#define OVV 24576                     /* fp32 V staging (stride 36) aliases PH/PL */
#define ATT_SMEM (40960 + 64 * 68 * 4)   /* 58368 */

__global__ __launch_bounds__(128) void k_attn(const float* __restrict__ mask,
                                              const float* __restrict__ logit_scale) {
    extern __shared__ char sm[];
    const int h = blockIdx.x;
    const int b = blockIdx.y;
    const int tid = threadIdx.x, lane = tid & 31, warp = tid >> 5;
    const uint32_t sbase = smem_u32(sm);
    (void)logit_scale;

    const size_t rowbase = (size_t)(b * NTOK) * DIMC + (size_t)h * HD;

    // ---- cp.async: q/k (bf16 hi/lo, pre-normalized) into swizzled tiles
#pragma unroll
    for (int i = tid; i < 256; i += 128) {
        int tok = i >> 2, c = i & 3;
        int swz = (tok >> 1) & 3;
        uint32_t d = (uint32_t)((tok << 6) + ((c ^ swz) << 4));
        size_t g = rowbase + (size_t)tok * DIMC + (c << 3);
        CP16(sbase + OQH + d, (const char*)(g_q_hi + g));
        CP16(sbase + OQL + d, (const char*)(g_q_lo + g));
        CP16(sbase + OKH + d, (const char*)(g_k_hi + g));
        CP16(sbase + OKL + d, (const char*)(g_k_lo + g));
    }
    // ---- cp.async: V fp32 staged [tok][36 floats]
#pragma unroll
    for (int i = tid; i < 512; i += 128) {
        int tok = i >> 3, c = i & 7;
        CP16(sbase + OVV + tok * 144 + (c << 4),
             (const char*)(g_v + rowbase + (size_t)tok * DIMC + (c << 2)));
    }
    CPCOMMIT(); CPWAIT(0);
    __syncthreads();

    // ---- transpose V: [64 tok][32 d] fp32 -> Vt [32 d][64 tok] bf16 hi/lo
    {
        int d = tid >> 2, jc = (tid & 3) << 4;
        const float* vv = (const float*)(sm + OVV);
        int swz = d & 7;
#pragma unroll
        for (int c2 = 0; c2 < 2; c2++) {
            float t[8];
#pragma unroll
            for (int e = 0; e < 8; e++) t[e] = vv[(jc + c2 * 8 + e) * 36 + d];
            uint4 hi, lo;
            pack8(t, hi, lo);
            int c = (jc >> 3) + c2;
            *(uint4*)(sm + OVH + (d << 7) + ((c ^ swz) << 4)) = hi;
            *(uint4*)(sm + OVL + (d << 7) + ((c ^ swz) << 4)) = lo;
        }
    }

    // ---- S = qn kn^T
    {
        uint32_t ah[2][4], al[2][4];
        int ra = (warp << 4) + (lane & 15);
        int ca = lane >> 4;
        int swa = (ra >> 1) & 3;
#pragma unroll
        for (int k2 = 0; k2 < 2; k2++) {
            uint32_t off = (uint32_t)((ra << 6) + (((ca + (k2 << 1)) ^ swa) << 4));
            LDSM4(ah[k2], sbase + OQH + off);
            LDSM4(al[k2], sbase + OQL + off);
        }
        float* S = (float*)(sm + OS);
        int qr = lane >> 2, qc = (lane & 3) << 1;
#pragma unroll
        for (int nf = 0; nf < 8; nf++) {
            float acc[4] = {0.f, 0.f, 0.f, 0.f};
            int rb = (nf << 3) + (lane & 7);
            int swb = (rb >> 1) & 3;
#pragma unroll
            for (int k2 = 0; k2 < 2; k2++) {
                uint32_t off = (uint32_t)((rb << 6) +
                    (((((lane >> 3) & 1) + (k2 << 1)) ^ swb) << 4));
                uint32_t bh[2], bl[2];
                LDSM2(bh, sbase + OKH + off);
                LDSM2(bl, sbase + OKL + off);
                MMA16816(acc, ah[k2], bh);
                MMA16816(acc, ah[k2], bl);
                MMA16816(acc, al[k2], bh);
            }
            int row = (warp << 4) + qr, col = (nf << 3) + qc;
            *(float2*)(S + row * 68 + col)       = make_float2(acc[0], acc[1]);
            *(float2*)(S + (row + 8) * 68 + col) = make_float2(acc[2], acc[3]);
        }
    }
    __syncthreads();

    // ---- softmax row r (+rpb+mask), write P hi/lo bf16
    if (tid < 64) {
        int r = tid;
        float* Sp = (float*)(sm + OS) + r * 68;
        const float* mrow = mask + (size_t)(b & (NWIN - 1)) * NTOK * NTOK + r * 64;
        const float* rrow = g_rpb + (size_t)h * NTOK * NTOK + r * 64;
        float p[64];
        float mx = -1e30f;
#pragma unroll
        for (int j = 0; j < 64; j += 4) {
            float4 s4 = *(float4*)(Sp + j);
            float4 rb = *(const float4*)(rrow + j);
            float4 mk = *(const float4*)(mrow + j);
            p[j + 0] = s4.x + rb.x + mk.x;
            p[j + 1] = s4.y + rb.y + mk.y;
            p[j + 2] = s4.z + rb.z + mk.z;
            p[j + 3] = s4.w + rb.w + mk.w;
            mx = fmaxf(mx, fmaxf(fmaxf(p[j], p[j + 1]), fmaxf(p[j + 2], p[j + 3])));
        }
        float sum = 0.f;
#pragma unroll
        for (int j = 0; j < 64; j++) { p[j] = expf(p[j] - mx); sum += p[j]; }
        float inv = 1.0f / sum;
#pragma unroll
        for (int j = 0; j < 64; j++) p[j] *= inv;
        int swz = r & 7;
#pragma unroll
        for (int c = 0; c < 8; c++) {
            uint4 hi, lo;
            pack8(p + 8 * c, hi, lo);
            *(uint4*)(sm + OPH + (r << 7) + ((c ^ swz) << 4)) = hi;
            *(uint4*)(sm + OPL + (r << 7) + ((c ^ swz) << 4)) = lo;
        }
    }
    __syncthreads();

    // ---- O = P V ; epilogue emits fp16 hi/lo for proj GEMM
    {
        float acc[4][4];
#pragma unroll
        for (int nf = 0; nf < 4; nf++)
#pragma unroll
            for (int e = 0; e < 4; e++) acc[nf][e] = 0.f;
        int ra = (warp << 4) + (lane & 15);
        int ca = lane >> 4;
        int swa = ra & 7;
#pragma unroll
        for (int ks = 0; ks < 4; ks++) {
            uint32_t offp = (uint32_t)((ra << 7) + (((ca + (ks << 1)) ^ swa) << 4));
            uint32_t ph[4], pl[4];
            LDSM4(ph, sbase + OPH + offp);
            LDSM4(pl, sbase + OPL + offp);
#pragma unroll
            for (int nf = 0; nf < 4; nf++) {
                int rv = (nf << 3) + (lane & 7);
                int swv = rv & 7;
                uint32_t offv = (uint32_t)((rv << 7) +
                    (((((lane >> 3) & 1) + (ks << 1)) ^ swv) << 4));
                uint32_t vh[2], vl[2];
                LDSM2(vh, sbase + OVH + offv);
                LDSM2(vl, sbase + OVL + offv);
                MMA16816(acc[nf], ph, vh);
                MMA16816(acc[nf], ph, vl);
                MMA16816(acc[nf], pl, vh);
            }
        }
        int qr = lane >> 2, qc = (lane & 3) << 1;
#pragma unroll
        for (int nf = 0; nf < 4; nf++) {
#pragma unroll
            for (int e = 0; e < 2; e++) {
                int row = (warp << 4) + qr + (e << 3);
                int col = (nf << 3) + qc;
                float v0 = acc[nf][e * 2], v1 = acc[nf][e * 2 + 1];
                size_t idx = (size_t)(b * NTOK + row) * DIMC + h * HD + col;
                __half2 hh, ll;
                hh.x = __float2half_rn(v0);
                hh.y = __float2half_rn(v1);
                ll.x = __float2half_rn(v0 - __half2float(hh.x));
                ll.y = __float2half_rn(v1 - __half2float(hh.y));
                *(__half2*)(g_attn_hi + idx) = hh;
                *(__half2*)(g_attn_lo + idx) = ll;
            }
        }
    }
}

// ---------------- launcher ----------------
extern "C" void kernel_launch(void* const* d_in, const int* in_sizes, int n_in,
                              void* d_out, int out_size) {
    (void)in_sizes; (void)n_in; (void)out_size;
    const float* x           = (const float*)d_in[0];
    const float* mask        = (const float*)d_in[1];
    const float* qkv_w       = (const float*)d_in[2];
    const float* q_bias      = (const float*)d_in[3];
    const float* v_bias      = (const float*)d_in[4];
    const float* logit_scale = (const float*)d_in[5];
    const float* cpb_w1      = (const float*)d_in[6];
    const float* cpb_b1      = (const float*)d_in[7];
    const float* cpb_w2      = (const float*)d_in[8];
    const float* proj_w      = (const float*)d_in[9];
    const float* proj_b      = (const float*)d_in[10];
    float* out = (float*)d_out;

    float *p_qkvb, *p_v;
    __half *p_xh, *p_xl, *p_ah, *p_al, *p_wq, *p_wp;
    __nv_bfloat16 *p_qh, *p_ql, *p_kh, *p_kl;
    cudaGetSymbolAddress((void**)&p_qkvb, g_qkv_bias);
    cudaGetSymbolAddress((void**)&p_v,    g_v);
    cudaGetSymbolAddress((void**)&p_xh,   g_x_hi);
    cudaGetSymbolAddress((void**)&p_xl,   g_x_lo);
    cudaGetSymbolAddress((void**)&p_ah,   g_attn_hi);
    cudaGetSymbolAddress((void**)&p_al,   g_attn_lo);
    cudaGetSymbolAddress((void**)&p_wq,   g_wqkv);
    cudaGetSymbolAddress((void**)&p_wp,   g_wproj);
    cudaGetSymbolAddress((void**)&p_qh,   g_q_hi);
    cudaGetSymbolAddress((void**)&p_ql,   g_q_lo);
    cudaGetSymbolAddress((void**)&p_kh,   g_k_hi);
    cudaGetSymbolAddress((void**)&p_kl,   g_k_lo);

    cudaFuncSetAttribute(gemm_mma, cudaFuncAttributeMaxDynamicSharedMemorySize, GSMEM);
    cudaFuncSetAttribute(k_attn,   cudaFuncAttributeMaxDynamicSharedMemorySize, ATT_SMEM);

    k_make_qkv_bias<<<3, 512>>>(q_bias, v_bias);
    k_cpb<<<225, CPBH>>>(cpb_w1, cpb_b1, cpb_w2);
    k_rpb<<<64, 1024>>>();

    k_split<<<(NROWS * DIMC / 4 + 255) / 256, 256>>>(x, p_xh, p_xl, NROWS * DIMC / 4);
    k_w_t<<<(QKVC * DIMC + 255) / 256, 256>>>(qkv_w, p_wq, DIMC, QKVC);
    k_w_t<<<(DIMC * DIMC + 255) / 256, 256>>>(proj_w, p_wp, DIMC, DIMC);

    // QKV GEMM with fused normalize/scale epilogue
    gemm_mma<<<dim3(QKVC / 128, NROWS / 128), 256, GSMEM>>>(
        p_xh, p_xl, p_wq, p_qkvb, nullptr,
        p_qh, p_ql, p_kh, p_kl, p_v, logit_scale, 1, NROWS, QKVC, DIMC);

    // fused attention (HMMA S & O, fp32 softmax)
    k_attn<<<dim3(NHEADS, BWIN), 128, ATT_SMEM>>>(mask, logit_scale);

    // proj GEMM -> d_out
    gemm_mma<<<dim3(DIMC / 128, NROWS / 128), 256, GSMEM>>>(
        p_ah, p_al, p_wp, proj_b, out,
        nullptr, nullptr, nullptr, nullptr, nullptr, nullptr, 0, NROWS, DIMC, DIMC);
}

// round 14
// speedup vs baseline: 2.9505x; 1.0309x over previous
#include <cuda_runtime.h>
#include <cuda_bf16.h>
#include <cuda_fp16.h>
#include <cstdint>
#include <math.h>

// ---------------- problem constants ----------------
#define DIMC   512
#define NHEADS 16
#define HD     32
#define NTOK   64
#define BWIN   1024
#define NWIN   64
#define CPBH   512
#define NROWS  (BWIN * NTOK)          /* 65536 */
#define QKVC   (3 * DIMC)             /* 1536  */

// ---------------- device scratch (no allocs allowed) ----------------
__device__ __nv_bfloat16 g_q_hi[NROWS * DIMC];   // normalized*scale q, bf16 hi/lo
__device__ __nv_bfloat16 g_q_lo[NROWS * DIMC];
__device__ __nv_bfloat16 g_k_hi[NROWS * DIMC];   // normalized k
__device__ __nv_bfloat16 g_k_lo[NROWS * DIMC];
__device__ __half g_v[NROWS * DIMC];             // v fp16 (single)
__device__ __half g_x_hi[NROWS * DIMC];
__device__ __half g_x_lo[NROWS * DIMC];
__device__ __half g_attn_hi[NROWS * DIMC];
__device__ __half g_attn_lo[NROWS * DIMC];
__device__ __half g_wqkv[QKVC * DIMC];           // [N=1536, K=512] transposed, fp16
__device__ __half g_wproj[DIMC * DIMC];          // [N=512, K=512] transposed, fp16
__device__ float g_bias_table[225 * NHEADS];
__device__ float g_rpb[NHEADS * NTOK * NTOK];
__device__ float g_qkv_bias[QKVC];

// ---------------- mma.sync helpers (arch-agnostic PTX) ----------------
#define LDSM4(R, addr)                                                        \
    asm volatile("ldmatrix.sync.aligned.m8n8.x4.shared.b16 {%0,%1,%2,%3},[%4];" \
                 : "=r"((R)[0]), "=r"((R)[1]), "=r"((R)[2]), "=r"((R)[3])     \
                 : "r"(addr))
#define LDSM2(R, addr)                                                        \
    asm volatile("ldmatrix.sync.aligned.m8n8.x2.shared.b16 {%0,%1},[%2];"     \
                 : "=r"((R)[0]), "=r"((R)[1]) : "r"(addr))
#define MMA16816(D, A, B)                                                     \
    asm volatile("mma.sync.aligned.m16n8k16.row.col.f32.bf16.bf16.f32 "       \
                 "{%0,%1,%2,%3},{%4,%5,%6,%7},{%8,%9},{%0,%1,%2,%3};"         \
                 : "+f"((D)[0]), "+f"((D)[1]), "+f"((D)[2]), "+f"((D)[3])     \
                 : "r"((A)[0]), "r"((A)[1]), "r"((A)[2]), "r"((A)[3]),        \
                   "r"((B)[0]), "r"((B)[1]))
#define MMAH16816(D, A, B)                                                    \
    asm volatile("mma.sync.aligned.m16n8k16.row.col.f32.f16.f16.f32 "         \
                 "{%0,%1,%2,%3},{%4,%5,%6,%7},{%8,%9},{%0,%1,%2,%3};"         \
                 : "+f"((D)[0]), "+f"((D)[1]), "+f"((D)[2]), "+f"((D)[3])     \
                 : "r"((A)[0]), "r"((A)[1]), "r"((A)[2]), "r"((A)[3]),        \
                   "r"((B)[0]), "r"((B)[1]))
#define CP16(dst, src)                                                        \
    asm volatile("cp.async.cg.shared.global [%0],[%1],16;" :: "r"(dst), "l"(src))
#define CPCOMMIT() asm volatile("cp.async.commit_group;")
#define CPWAIT(n)  asm volatile("cp.async.wait_group %0;" :: "n"(n))

__device__ __forceinline__ uint32_t smem_u32(const void* p) {
    uint32_t a;
    asm("{ .reg .u64 t; cvta.to.shared.u64 t, %1; cvt.u32.u64 %0, t; }" : "=r"(a) : "l"(p));
    return a;
}

// split 8 fp32 -> 8 bf16 hi + 8 bf16 lo (16B each)
__device__ __forceinline__ void pack8(const float* v, uint4& hi, uint4& lo) {
    __nv_bfloat162 h[4], l[4];
#pragma unroll
    for (int e = 0; e < 4; e++) {
        h[e].x = __float2bfloat16(v[2 * e]);
        h[e].y = __float2bfloat16(v[2 * e + 1]);
        l[e].x = __float2bfloat16(v[2 * e]     - __bfloat162float(h[e].x));
        l[e].y = __float2bfloat16(v[2 * e + 1] - __bfloat162float(h[e].y));
    }
    hi = *(uint4*)h;
    lo = *(uint4*)l;
}

// split 8 fp32 -> 8 fp16 hi + 8 fp16 lo
__device__ __forceinline__ void pack8h(const float* v, uint4& hi, uint4& lo) {
    __half2 h[4], l[4];
#pragma unroll
    for (int e = 0; e < 4; e++) {
        h[e].x = __float2half_rn(v[2 * e]);
        h[e].y = __float2half_rn(v[2 * e + 1]);
        l[e].x = __float2half_rn(v[2 * e]     - __half2float(h[e].x));
        l[e].y = __float2half_rn(v[2 * e + 1] - __half2float(h[e].y));
    }
    hi = *(uint4*)h;
    lo = *(uint4*)l;
}

// ---------------- setup kernels ----------------
__global__ void k_make_qkv_bias(const float* __restrict__ qb,
                                const float* __restrict__ vb) {
    int i = blockIdx.x * blockDim.x + threadIdx.x;
    if (i < QKVC) {
        float v = 0.f;
        if (i < DIMC)            v = qb[i];
        else if (i >= 2 * DIMC)  v = vb[i - 2 * DIMC];
        g_qkv_bias[i] = v;
    }
}

__device__ __forceinline__ float cpb_coord(int u) {
    float t = (float)u * (8.0f / 7.0f);
    float s = (t > 0.f) ? 1.f : ((t < 0.f) ? -1.f : 0.f);
    return s * log2f(fabsf(t) + 1.0f) * (1.0f / 3.0f);
}

__global__ void k_cpb(const float* __restrict__ w1, const float* __restrict__ b1,
                      const float* __restrict__ w2) {
    __shared__ float hid[CPBH];
    int m = blockIdx.x;
    int k = threadIdx.x;
    float c0 = cpb_coord(m % 15 - 7);
    float c1 = cpb_coord(m / 15 - 7);
    hid[k] = fmaxf(fmaf(c0, w1[k], fmaf(c1, w1[CPBH + k], b1[k])), 0.f);
    __syncthreads();
    int warp = k >> 5, lane = k & 31;
    float s = 0.f;
    for (int kk = lane; kk < CPBH; kk += 32)
        s = fmaf(hid[kk], w2[kk * NHEADS + warp], s);
#pragma unroll
    for (int o = 16; o > 0; o >>= 1) s += __shfl_xor_sync(0xffffffffu, s, o);
    if (lane == 0) g_bias_table[m * NHEADS + warp] = s;
}

__global__ void k_rpb() {
    int id = blockIdx.x * blockDim.x + threadIdx.x;
    int h = id >> 12;
    int p = (id >> 6) & 63;
    int q = id & 63;
    int idx = (((p & 7) - (q & 7)) + 7) * 15 + (((p >> 3) - (q >> 3)) + 7);
    float v = g_bias_table[idx * NHEADS + h];
    g_rpb[id] = 16.0f / (1.0f + expf(-v));
}

// split fp32 -> (hi fp16, lo fp16), vectorized by 4
__global__ void k_split(const float* __restrict__ s, __half* __restrict__ hi,
                        __half* __restrict__ lo, int n4) {
    int i = blockIdx.x * blockDim.x + threadIdx.x;
    if (i < n4) {
        float4 v = *(const float4*)(s + i * 4);
        __half h0 = __float2half_rn(v.x);
        __half h1 = __float2half_rn(v.y);
        __half h2 = __float2half_rn(v.z);
        __half h3 = __float2half_rn(v.w);
        __half2 hh0, hh1, ll0, ll1;
        hh0.x = h0; hh0.y = h1; hh1.x = h2; hh1.y = h3;
        ll0.x = __float2half_rn(v.x - __half2float(h0));
        ll0.y = __float2half_rn(v.y - __half2float(h1));
        ll1.x = __float2half_rn(v.z - __half2float(h2));
        ll1.y = __float2half_rn(v.w - __half2float(h3));
        *(__half2*)(hi + i * 4)     = hh0;
        *(__half2*)(hi + i * 4 + 2) = hh1;
        *(__half2*)(lo + i * 4)     = ll0;
        *(__half2*)(lo + i * 4 + 2) = ll1;
    }
}

// transpose weights to single fp16: w [K,N] fp32 -> [N,K] fp16
__global__ void k_w_t(const float* __restrict__ w, __half* __restrict__ o,
                      int K, int N) {
    int i = blockIdx.x * blockDim.x + threadIdx.x;
    if (i < K * N) {
        int n = i / K, k = i - n * K;
        o[i] = __float2half_rn(w[(size_t)k * N + n]);
    }
}

// ---------------- split-fp16 HMMA GEMM, 3-stage cp.async ----------------
// C = (Ah+Al) @ B^T ; 128x128x32 tile, 256 thr, 3 stages x 3 arrays x 8KB = 72KB.
// fuse=1 (QKV): q/k normalized (+logit scale for q) -> bf16 hi/lo; v -> fp16.
#define GSMEM (3 * 3 * 8192)

__global__ __launch_bounds__(256) void gemm_mma(
    const __half* __restrict__ Ahi, const __half* __restrict__ Alo,
    const __half* __restrict__ B,
    const float* __restrict__ bias, float* __restrict__ C,
    __nv_bfloat16* __restrict__ qh, __nv_bfloat16* __restrict__ ql,
    __nv_bfloat16* __restrict__ kh, __nv_bfloat16* __restrict__ kl,
    __half* __restrict__ vout, const float* __restrict__ lsc,
    int fuse, int M, int N, int K) {
    extern __shared__ char gsm[];
    const uint32_t sb = smem_u32(gsm);

    const int tid  = threadIdx.x;
    const int lane = tid & 31;
    const int warp = tid >> 5;
    const int wm = (warp >> 2) << 6;
    const int wn = (warp & 3) << 5;
    const int row0 = blockIdx.y * 128;
    const int col0 = blockIdx.x * 128;

    const __half* src[3] = {Ahi + (size_t)row0 * K, Alo + (size_t)row0 * K,
                            B + (size_t)col0 * K};

    const int r_g  = tid >> 2;
    const int r_g2 = r_g + 64;
    const int c_g  = tid & 3;
    const uint32_t dst1 = (uint32_t)((r_g  << 6) + ((c_g ^ ((r_g  >> 1) & 3)) << 4));
    const uint32_t dst2 = (uint32_t)((r_g2 << 6) + ((c_g ^ ((r_g2 >> 1) & 3)) << 4));

    uint32_t offA[4][2], offB[4][2];
#pragma unroll
    for (int mf = 0; mf < 4; mf++) {
        int r = wm + (mf << 4) + (lane & 15);
#pragma unroll
        for (int k2 = 0; k2 < 2; k2++) {
            int c16 = (lane >> 4) + (k2 << 1);
            offA[mf][k2] = (uint32_t)((r << 6) + ((c16 ^ ((r >> 1) & 3)) << 4));
        }
    }
#pragma unroll
    for (int nf = 0; nf < 4; nf++) {
        int r = wn + (nf << 3) + (lane & 7);
#pragma unroll
        for (int k2 = 0; k2 < 2; k2++) {
            int c16 = ((lane >> 3) & 1) + (k2 << 1);
            offB[nf][k2] = (uint32_t)((r << 6) + ((c16 ^ ((r >> 1) & 3)) << 4));
        }
    }

    float acc[4][4][4];
#pragma unroll
    for (int mf = 0; mf < 4; mf++)
#pragma unroll
        for (int nf = 0; nf < 4; nf++)
#pragma unroll
            for (int e = 0; e < 4; e++) acc[mf][nf][e] = 0.f;

    const int nchunks = K >> 5;     // 16

    auto issue = [&](int stage, int kc) {
#pragma unroll
        for (int a = 0; a < 3; a++) {
            uint32_t base = sb + (uint32_t)((stage * 3 + a) << 13);
            const char* g1 = (const char*)(src[a] + (size_t)r_g  * K + (kc << 5) + (c_g << 3));
            const char* g2 = (const char*)(src[a] + (size_t)r_g2 * K + (kc << 5) + (c_g << 3));
            CP16(base + dst1, g1);
            CP16(base + dst2, g2);
        }
        CPCOMMIT();
    };

    issue(0, 0);
    issue(1, 1);
    int stage = 0;
    for (int kc = 0; kc < nchunks; kc++) {
        if (kc == nchunks - 1) { CPWAIT(0); } else { CPWAIT(1); }
        __syncthreads();

        const uint32_t st = sb + (uint32_t)(stage * 24576);
#pragma unroll
        for (int k2 = 0; k2 < 2; k2++) {
            uint32_t ah[4][4], al[4][4], bh[4][2];
#pragma unroll
            for (int mf = 0; mf < 4; mf++) {
                LDSM4(ah[mf], st + offA[mf][k2]);
                LDSM4(al[mf], st + 8192 + offA[mf][k2]);
            }
#pragma unroll
            for (int nf = 0; nf < 4; nf++)
                LDSM2(bh[nf], st + 16384 + offB[nf][k2]);
#pragma unroll
            for (int mf = 0; mf < 4; mf++)
#pragma unroll
                for (int nf = 0; nf < 4; nf++) {
                    MMAH16816(acc[mf][nf], ah[mf], bh[nf]);
                    MMAH16816(acc[mf][nf], al[mf], bh[nf]);
                }
        }
        if (kc + 2 < nchunks) {
            int tgt = stage + 2;
            if (tgt >= 3) tgt -= 3;
            issue(tgt, kc + 2);
        }
        stage = (stage == 2) ? 0 : stage + 1;
    }

    const int qr = lane >> 2;
    const int qc = (lane & 3) << 1;

#pragma unroll
    for (int nf = 0; nf < 4; nf++) {
        float2 bi = *(const float2*)(bias + col0 + wn + (nf << 3) + qc);
#pragma unroll
        for (int mf = 0; mf < 4; mf++) {
            acc[mf][nf][0] += bi.x; acc[mf][nf][1] += bi.y;
            acc[mf][nf][2] += bi.x; acc[mf][nf][3] += bi.y;
        }
    }

    if (!fuse) {
#pragma unroll
        for (int mf = 0; mf < 4; mf++)
#pragma unroll
            for (int nf = 0; nf < 4; nf++) {
                int row = row0 + wm + (mf << 4) + qr;
                int col = col0 + wn + (nf << 3) + qc;
                *(float2*)(C + (size_t)row * N + col) =
                    make_float2(acc[mf][nf][0], acc[mf][nf][1]);
                *(float2*)(C + (size_t)(row + 8) * N + col) =
                    make_float2(acc[mf][nf][2], acc[mf][nf][3]);
            }
        return;
    }

    const int sec = blockIdx.x >> 2;          // 0=q, 1=k, 2=v
    if (sec < 2) {
        float scale = 1.f;
        if (sec == 0) {
            int h = (col0 + wn) >> 5;          // warp covers exactly one head
            scale = expf(fminf(lsc[h], 4.6051701860f));
        }
#pragma unroll
        for (int mf = 0; mf < 4; mf++) {
#pragma unroll
            for (int e = 0; e < 2; e++) {
                float ss = 0.f;
#pragma unroll
                for (int nf = 0; nf < 4; nf++) {
                    float a0 = acc[mf][nf][e * 2], a1 = acc[mf][nf][e * 2 + 1];
                    ss = fmaf(a0, a0, fmaf(a1, a1, ss));
                }
                ss += __shfl_xor_sync(0xffffffffu, ss, 1);
                ss += __shfl_xor_sync(0xffffffffu, ss, 2);
                float inv = rsqrtf(ss) * scale;
                int row = row0 + wm + (mf << 4) + (e << 3) + qr;
#pragma unroll
                for (int nf = 0; nf < 4; nf++) {
                    int col = col0 + wn + (nf << 3) + qc - sec * 512;
                    float v0 = acc[mf][nf][e * 2] * inv;
                    float v1 = acc[mf][nf][e * 2 + 1] * inv;
                    __nv_bfloat162 hh, ll;
                    hh.x = __float2bfloat16(v0);
                    hh.y = __float2bfloat16(v1);
                    ll.x = __float2bfloat16(v0 - __bfloat162float(hh.x));
                    ll.y = __float2bfloat16(v1 - __bfloat162float(hh.y));
                    size_t idx = (size_t)row * DIMC + col;
                    if (sec == 0) {
                        *(__nv_bfloat162*)(qh + idx) = hh;
                        *(__nv_bfloat162*)(ql + idx) = ll;
                    } else {
                        *(__nv_bfloat162*)(kh + idx) = hh;
                        *(__nv_bfloat162*)(kl + idx) = ll;
                    }
                }
            }
        }
    } else {
#pragma unroll
        for (int mf = 0; mf < 4; mf++)
#pragma unroll
            for (int nf = 0; nf < 4; nf++) {
                int row = row0 + wm + (mf << 4) + qr;
                int col = col0 + wn + (nf << 3) + qc - 1024;
                __half2 a0, a1;
                a0.x = __float2half_rn(acc[mf][nf][0]);
                a0.y = __float2half_rn(acc[mf][nf][1]);
                a1.x = __float2half_rn(acc[mf][nf][2]);
                a1.y = __float2half_rn(acc[mf][nf][3]);
                *(__half2*)(vout + (size_t)row * DIMC + col)       = a0;
                *(__half2*)(vout + (size_t)(row + 8) * DIMC + col) = a1;
            }
    }
}

// ---------------- fused attention ----------------
// smem layout (bytes): QK tiles 16KB (aliased by P fp16 hi/lo after S-phase),
// Vt fp16 4KB, S fp32 17.4KB (V fp16 staging aliases S before S-phase).
#define OQH 0
#define OQL 4096
#define OKH 8192
#define OKL 12288
#define OPH 0                       /* alias QH/QL */
#define OPL 8192                    /* alias KH/KL */
#define OVT 16384                   /* Vt fp16 [32][64], 4KB */
#define OS  20480                   /* S fp32 64 x 68 */
#define OVV 20480                   /* V fp16 staging [64 tok][40 halves], aliases S */
#define ATT_SMEM (20480 + 64 * 68 * 4)   /* 37888 */

__global__ __launch_bounds__(128) void k_attn(const float* __restrict__ mask,
                                              const float* __restrict__ logit_scale) {
    extern __shared__ char sm[];
    const int h = blockIdx.x;
    const int b = blockIdx.y;
    const int tid = threadIdx.x, lane = tid & 31, warp = tid >> 5;
    const uint32_t sbase = smem_u32(sm);
    (void)logit_scale;

    const size_t rowbase = (size_t)(b * NTOK) * DIMC + (size_t)h * HD;

    // ---- cp.async: q/k (bf16 hi/lo, pre-normalized) into swizzled tiles
#pragma unroll
    for (int i = tid; i < 256; i += 128) {
        int tok = i >> 2, c = i & 3;
        int swz = (tok >> 1) & 3;
        uint32_t d = (uint32_t)((tok << 6) + ((c ^ swz) << 4));
        size_t g = rowbase + (size_t)tok * DIMC + (c << 3);
        CP16(sbase + OQH + d, (const char*)(g_q_hi + g));
        CP16(sbase + OQL + d, (const char*)(g_q_lo + g));
        CP16(sbase + OKH + d, (const char*)(g_k_hi + g));
        CP16(sbase + OKL + d, (const char*)(g_k_lo + g));
    }
    // ---- cp.async: V fp16 staged [tok][40 halves] (80B stride)
#pragma unroll
    for (int i = tid; i < 256; i += 128) {
        int tok = i >> 2, c = i & 3;
        CP16(sbase + OVV + tok * 80 + (c << 4),
             (const char*)(g_v + rowbase + (size_t)tok * DIMC + (c << 3)));
    }
    CPCOMMIT(); CPWAIT(0);
    __syncthreads();

    // ---- transpose V: [64 tok][32 d] fp16 -> Vt [32 d][64 tok] fp16
    {
        int d = tid >> 2, jc = (tid & 3) << 4;
        const __half* vv = (const __half*)(sm + OVV);
        int swz = d & 7;
#pragma unroll
        for (int c2 = 0; c2 < 2; c2++) {
            __half2 t[4];
#pragma unroll
            for (int e = 0; e < 4; e++) {
                t[e].x = vv[(jc + c2 * 8 + 2 * e) * 40 + d];
                t[e].y = vv[(jc + c2 * 8 + 2 * e + 1) * 40 + d];
            }
            int c = (jc >> 3) + c2;
            *(uint4*)(sm + OVT + (d << 7) + ((c ^ swz) << 4)) = *(uint4*)t;
        }
    }
    __syncthreads();    // staging reads done before S-phase overwrites OS

    // ---- S = qn kn^T (bf16 3-product)
    {
        uint32_t ah[2][4], al[2][4];
        int ra = (warp << 4) + (lane & 15);
        int ca = lane >> 4;
        int swa = (ra >> 1) & 3;
#pragma unroll
        for (int k2 = 0; k2 < 2; k2++) {
            uint32_t off = (uint32_t)((ra << 6) + (((ca + (k2 << 1)) ^ swa) << 4));
            LDSM4(ah[k2], sbase + OQH + off);
            LDSM4(al[k2], sbase + OQL + off);
        }
        float* S = (float*)(sm + OS);
        int qr = lane >> 2, qc = (lane & 3) << 1;
#pragma unroll
        for (int nf = 0; nf < 8; nf++) {
            float acc[4] = {0.f, 0.f, 0.f, 0.f};
            int rb = (nf << 3) + (lane & 7);
            int swb = (rb >> 1) & 3;
#pragma unroll
            for (int k2 = 0; k2 < 2; k2++) {
                uint32_t off = (uint32_t)((rb << 6) +
                    (((((lane >> 3) & 1) + (k2 << 1)) ^ swb) << 4));
                uint32_t bh[2], bl[2];
                LDSM2(bh, sbase + OKH + off);
                LDSM2(bl, sbase + OKL + off);
                MMA16816(acc, ah[k2], bh);
                MMA16816(acc, ah[k2], bl);
                MMA16816(acc, al[k2], bh);
            }
            int row = (warp << 4) + qr, col = (nf << 3) + qc;
            *(float2*)(S + row * 68 + col)       = make_float2(acc[0], acc[1]);
            *(float2*)(S + (row + 8) * 68 + col) = make_float2(acc[2], acc[3]);
        }
    }
    __syncthreads();

    // ---- softmax: 2 threads per row (halves combined via shfl), write P fp16 hi/lo
    {
        int r = tid >> 1;
        int hf = tid & 1;
        float* Sp = (float*)(sm + OS) + r * 68 + (hf << 5);
        const float* mrow = mask + (size_t)(b & (NWIN - 1)) * NTOK * NTOK + r * 64 + (hf << 5);
        const float* rrow = g_rpb + (size_t)h * NTOK * NTOK + r * 64 + (hf << 5);
        float p[32];
        float mx = -1e30f;
#pragma unroll
        for (int j = 0; j < 32; j += 4) {
            float4 s4 = *(float4*)(Sp + j);
            float4 rb = *(const float4*)(rrow + j);
            float4 mk = *(const float4*)(mrow + j);
            p[j + 0] = s4.x + rb.x + mk.x;
            p[j + 1] = s4.y + rb.y + mk.y;
            p[j + 2] = s4.z + rb.z + mk.z;
            p[j + 3] = s4.w + rb.w + mk.w;
            mx = fmaxf(mx, fmaxf(fmaxf(p[j], p[j + 1]), fmaxf(p[j + 2], p[j + 3])));
        }
        mx = fmaxf(mx, __shfl_xor_sync(0xffffffffu, mx, 1));
        float sum = 0.f;
#pragma unroll
        for (int j = 0; j < 32; j++) { p[j] = expf(p[j] - mx); sum += p[j]; }
        sum += __shfl_xor_sync(0xffffffffu, sum, 1);
        float inv = 1.0f / sum;
#pragma unroll
        for (int j = 0; j < 32; j++) p[j] *= inv;
        int swz = r & 7;
#pragma unroll
        for (int c2 = 0; c2 < 4; c2++) {
            int c = (hf << 2) + c2;
            uint4 hi, lo;
            pack8h(p + 8 * c2, hi, lo);
            *(uint4*)(sm + OPH + (r << 7) + ((c ^ swz) << 4)) = hi;
            *(uint4*)(sm + OPL + (r << 7) + ((c ^ swz) << 4)) = lo;
        }
    }
    __syncthreads();

    // ---- O = (Ph+Pl) Vh (fp16 2-product) ; emits fp16 hi/lo for proj
    {
        float acc[4][4];
#pragma unroll
        for (int nf = 0; nf < 4; nf++)
#pragma unroll
            for (int e = 0; e < 4; e++) acc[nf][e] = 0.f;
        int ra = (warp << 4) + (lane & 15);
        int ca = lane >> 4;
        int swa = ra & 7;
#pragma unroll
        for (int ks = 0; ks < 4; ks++) {
            uint32_t offp = (uint32_t)((ra << 7) + (((ca + (ks << 1)) ^ swa) << 4));
            uint32_t ph[4], pl[4];
            LDSM4(ph, sbase + OPH + offp);
            LDSM4(pl, sbase + OPL + offp);
#pragma unroll
            for (int nf = 0; nf < 4; nf++) {
                int rv = (nf << 3) + (lane & 7);
                int swv = rv & 7;
                uint32_t offv = (uint32_t)((rv << 7) +
                    (((((lane >> 3) & 1) + (ks << 1)) ^ swv) << 4));
                uint32_t vh[2];
                LDSM2(vh, sbase + OVT + offv);
                MMAH16816(acc[nf], ph, vh);
                MMAH16816(acc[nf], pl, vh);
            }
        }
        int qr = lane >> 2, qc = (lane & 3) << 1;
#pragma unroll
        for (int nf = 0; nf < 4; nf++) {
#pragma unroll
            for (int e = 0; e < 2; e++) {
                int row = (warp << 4) + qr + (e << 3);
                int col = (nf << 3) + qc;
                float v0 = acc[nf][e * 2], v1 = acc[nf][e * 2 + 1];
                size_t idx = (size_t)(b * NTOK + row) * DIMC + h * HD + col;
                __half2 hh, ll;
                hh.x = __float2half_rn(v0);
                hh.y = __float2half_rn(v1);
                ll.x = __float2half_rn(v0 - __half2float(hh.x));
                ll.y = __float2half_rn(v1 - __half2float(hh.y));
                *(__half2*)(g_attn_hi + idx) = hh;
                *(__half2*)(g_attn_lo + idx) = ll;
            }
        }
    }
}

// ---------------- launcher ----------------
extern "C" void kernel_launch(void* const* d_in, const int* in_sizes, int n_in,
                              void* d_out, int out_size) {
    (void)in_sizes; (void)n_in; (void)out_size;
    const float* x           = (const float*)d_in[0];
    const float* mask        = (const float*)d_in[1];
    const float* qkv_w       = (const float*)d_in[2];
    const float* q_bias      = (const float*)d_in[3];
    const float* v_bias      = (const float*)d_in[4];
    const float* logit_scale = (const float*)d_in[5];
    const float* cpb_w1      = (const float*)d_in[6];
    const float* cpb_b1      = (const float*)d_in[7];
    const float* cpb_w2      = (const float*)d_in[8];
    const float* proj_w      = (const float*)d_in[9];
    const float* proj_b      = (const float*)d_in[10];
    float* out = (float*)d_out;

    float* p_qkvb;
    __half *p_v, *p_xh, *p_xl, *p_ah, *p_al, *p_wq, *p_wp;
    __nv_bfloat16 *p_qh, *p_ql, *p_kh, *p_kl;
    cudaGetSymbolAddress((void**)&p_qkvb, g_qkv_bias);
    cudaGetSymbolAddress((void**)&p_v,    g_v);
    cudaGetSymbolAddress((void**)&p_xh,   g_x_hi);
    cudaGetSymbolAddress((void**)&p_xl,   g_x_lo);
    cudaGetSymbolAddress((void**)&p_ah,   g_attn_hi);
    cudaGetSymbolAddress((void**)&p_al,   g_attn_lo);
    cudaGetSymbolAddress((void**)&p_wq,   g_wqkv);
    cudaGetSymbolAddress((void**)&p_wp,   g_wproj);
    cudaGetSymbolAddress((void**)&p_qh,   g_q_hi);
    cudaGetSymbolAddress((void**)&p_ql,   g_q_lo);
    cudaGetSymbolAddress((void**)&p_kh,   g_k_hi);
    cudaGetSymbolAddress((void**)&p_kl,   g_k_lo);

    cudaFuncSetAttribute(gemm_mma, cudaFuncAttributeMaxDynamicSharedMemorySize, GSMEM);
    cudaFuncSetAttribute(k_attn,   cudaFuncAttributeMaxDynamicSharedMemorySize, ATT_SMEM);

    k_make_qkv_bias<<<3, 512>>>(q_bias, v_bias);
    k_cpb<<<225, CPBH>>>(cpb_w1, cpb_b1, cpb_w2);
    k_rpb<<<64, 1024>>>();

    k_split<<<(NROWS * DIMC / 4 + 255) / 256, 256>>>(x, p_xh, p_xl, NROWS * DIMC / 4);
    k_w_t<<<(QKVC * DIMC + 255) / 256, 256>>>(qkv_w, p_wq, DIMC, QKVC);
    k_w_t<<<(DIMC * DIMC + 255) / 256, 256>>>(proj_w, p_wp, DIMC, DIMC);

    // QKV GEMM with fused normalize/scale epilogue (v -> fp16)
    gemm_mma<<<dim3(QKVC / 128, NROWS / 128), 256, GSMEM>>>(
        p_xh, p_xl, p_wq, p_qkvb, nullptr,
        p_qh, p_ql, p_kh, p_kl, p_v, logit_scale, 1, NROWS, QKVC, DIMC);

    // fused attention (HMMA S & O, fp32 softmax)
    k_attn<<<dim3(NHEADS, BWIN), 128, ATT_SMEM>>>(mask, logit_scale);

    // proj GEMM -> d_out
    gemm_mma<<<dim3(DIMC / 128, NROWS / 128), 256, GSMEM>>>(
        p_ah, p_al, p_wp, proj_b, out,
        nullptr, nullptr, nullptr, nullptr, nullptr, nullptr, 0, NROWS, DIMC, DIMC);
}

// round 15
// speedup vs baseline: 4.4507x; 1.5085x over previous
#include <cuda_runtime.h>
#include <cuda_bf16.h>
#include <cuda_fp16.h>
#include <cstdint>
#include <math.h>

// ---------------- problem constants ----------------
#define DIMC   512
#define NHEADS 16
#define HD     32
#define NTOK   64
#define BWIN   1024
#define NWIN   64
#define CPBH   512
#define NROWS  (BWIN * NTOK)          /* 65536 */
#define QKVC   (3 * DIMC)             /* 1536  */

// ---------------- device scratch (no allocs allowed) ----------------
__device__ __nv_bfloat16 g_q_hi[NROWS * DIMC];   // normalized*scale q, bf16 hi/lo
__device__ __nv_bfloat16 g_q_lo[NROWS * DIMC];
__device__ __nv_bfloat16 g_k_hi[NROWS * DIMC];   // normalized k
__device__ __nv_bfloat16 g_k_lo[NROWS * DIMC];
__device__ __half g_v[NROWS * DIMC];             // v fp16 (single)
__device__ __half g_x[NROWS * DIMC];             // x fp16 (single)
__device__ __half g_attn[NROWS * DIMC];          // attention out fp16 (single)
__device__ __half g_wqkv[QKVC * DIMC];           // [N=1536, K=512] transposed, fp16
__device__ __half g_wproj[DIMC * DIMC];          // [N=512, K=512] transposed, fp16
__device__ float g_bias_table[225 * NHEADS];
__device__ float g_rpb[NHEADS * NTOK * NTOK];
__device__ float g_qkv_bias[QKVC];

// ---------------- mma.sync helpers (arch-agnostic PTX) ----------------
#define LDSM4(R, addr)                                                        \
    asm volatile("ldmatrix.sync.aligned.m8n8.x4.shared.b16 {%0,%1,%2,%3},[%4];" \
                 : "=r"((R)[0]), "=r"((R)[1]), "=r"((R)[2]), "=r"((R)[3])     \
                 : "r"(addr))
#define LDSM2(R, addr)                                                        \
    asm volatile("ldmatrix.sync.aligned.m8n8.x2.shared.b16 {%0,%1},[%2];"     \
                 : "=r"((R)[0]), "=r"((R)[1]) : "r"(addr))
#define MMA16816(D, A, B)                                                     \
    asm volatile("mma.sync.aligned.m16n8k16.row.col.f32.bf16.bf16.f32 "       \
                 "{%0,%1,%2,%3},{%4,%5,%6,%7},{%8,%9},{%0,%1,%2,%3};"         \
                 : "+f"((D)[0]), "+f"((D)[1]), "+f"((D)[2]), "+f"((D)[3])     \
                 : "r"((A)[0]), "r"((A)[1]), "r"((A)[2]), "r"((A)[3]),        \
                   "r"((B)[0]), "r"((B)[1]))
#define MMAH16816(D, A, B)                                                    \
    asm volatile("mma.sync.aligned.m16n8k16.row.col.f32.f16.f16.f32 "         \
                 "{%0,%1,%2,%3},{%4,%5,%6,%7},{%8,%9},{%0,%1,%2,%3};"         \
                 : "+f"((D)[0]), "+f"((D)[1]), "+f"((D)[2]), "+f"((D)[3])     \
                 : "r"((A)[0]), "r"((A)[1]), "r"((A)[2]), "r"((A)[3]),        \
                   "r"((B)[0]), "r"((B)[1]))
#define CP16(dst, src)                                                        \
    asm volatile("cp.async.cg.shared.global [%0],[%1],16;" :: "r"(dst), "l"(src))
#define CPCOMMIT() asm volatile("cp.async.commit_group;")
#define CPWAIT(n)  asm volatile("cp.async.wait_group %0;" :: "n"(n))

__device__ __forceinline__ uint32_t smem_u32(const void* p) {
    uint32_t a;
    asm("{ .reg .u64 t; cvta.to.shared.u64 t, %1; cvt.u32.u64 %0, t; }" : "=r"(a) : "l"(p));
    return a;
}

// split 8 fp32 -> 8 fp16 hi + 8 fp16 lo
__device__ __forceinline__ void pack8h(const float* v, uint4& hi, uint4& lo) {
    __half2 h[4], l[4];
#pragma unroll
    for (int e = 0; e < 4; e++) {
        h[e].x = __float2half_rn(v[2 * e]);
        h[e].y = __float2half_rn(v[2 * e + 1]);
        l[e].x = __float2half_rn(v[2 * e]     - __half2float(h[e].x));
        l[e].y = __float2half_rn(v[2 * e + 1] - __half2float(h[e].y));
    }
    hi = *(uint4*)h;
    lo = *(uint4*)l;
}

// ---------------- setup kernels ----------------
__global__ void k_make_qkv_bias(const float* __restrict__ qb,
                                const float* __restrict__ vb) {
    int i = blockIdx.x * blockDim.x + threadIdx.x;
    if (i < QKVC) {
        float v = 0.f;
        if (i < DIMC)            v = qb[i];
        else if (i >= 2 * DIMC)  v = vb[i - 2 * DIMC];
        g_qkv_bias[i] = v;
    }
}

__device__ __forceinline__ float cpb_coord(int u) {
    float t = (float)u * (8.0f / 7.0f);
    float s = (t > 0.f) ? 1.f : ((t < 0.f) ? -1.f : 0.f);
    return s * log2f(fabsf(t) + 1.0f) * (1.0f / 3.0f);
}

__global__ void k_cpb(const float* __restrict__ w1, const float* __restrict__ b1,
                      const float* __restrict__ w2) {
    __shared__ float hid[CPBH];
    int m = blockIdx.x;
    int k = threadIdx.x;
    float c0 = cpb_coord(m % 15 - 7);
    float c1 = cpb_coord(m / 15 - 7);
    hid[k] = fmaxf(fmaf(c0, w1[k], fmaf(c1, w1[CPBH + k], b1[k])), 0.f);
    __syncthreads();
    int warp = k >> 5, lane = k & 31;
    float s = 0.f;
    for (int kk = lane; kk < CPBH; kk += 32)
        s = fmaf(hid[kk], w2[kk * NHEADS + warp], s);
#pragma unroll
    for (int o = 16; o > 0; o >>= 1) s += __shfl_xor_sync(0xffffffffu, s, o);
    if (lane == 0) g_bias_table[m * NHEADS + warp] = s;
}

__global__ void k_rpb() {
    int id = blockIdx.x * blockDim.x + threadIdx.x;
    int h = id >> 12;
    int p = (id >> 6) & 63;
    int q = id & 63;
    int idx = (((p & 7) - (q & 7)) + 7) * 15 + (((p >> 3) - (q >> 3)) + 7);
    float v = g_bias_table[idx * NHEADS + h];
    g_rpb[id] = 16.0f / (1.0f + expf(-v));
}

// convert fp32 -> fp16, vectorized by 4
__global__ void k_cvt(const float* __restrict__ s, __half* __restrict__ o, int n4) {
    int i = blockIdx.x * blockDim.x + threadIdx.x;
    if (i < n4) {
        float4 v = *(const float4*)(s + i * 4);
        __half2 a, b;
        a.x = __float2half_rn(v.x); a.y = __float2half_rn(v.y);
        b.x = __float2half_rn(v.z); b.y = __float2half_rn(v.w);
        *(__half2*)(o + i * 4)     = a;
        *(__half2*)(o + i * 4 + 2) = b;
    }
}

// transpose weights to single fp16: w [K,N] fp32 -> [N,K] fp16
__global__ void k_w_t(const float* __restrict__ w, __half* __restrict__ o,
                      int K, int N) {
    int i = blockIdx.x * blockDim.x + threadIdx.x;
    if (i < K * N) {
        int n = i / K, k = i - n * K;
        o[i] = __float2half_rn(w[(size_t)k * N + n]);
    }
}

// ---------------- fp16 HMMA GEMM, 3-stage cp.async ----------------
// C = A @ B^T ; A [M,K] fp16, B [N,K] fp16. 128x128x32 tile, 256 thr.
// smem: 3 stages x 2 arrays x 8KB = 48KB.
// fuse=1 (QKV): q/k normalized (+logit scale for q) -> bf16 hi/lo; v -> fp16.
#define GSMEM (3 * 2 * 8192)

__global__ __launch_bounds__(256) void gemm_mma(
    const __half* __restrict__ A, const __half* __restrict__ B,
    const float* __restrict__ bias, float* __restrict__ C,
    __nv_bfloat16* __restrict__ qh, __nv_bfloat16* __restrict__ ql,
    __nv_bfloat16* __restrict__ kh, __nv_bfloat16* __restrict__ kl,
    __half* __restrict__ vout, const float* __restrict__ lsc,
    int fuse, int M, int N, int K) {
    extern __shared__ char gsm[];
    const uint32_t sb = smem_u32(gsm);

    const int tid  = threadIdx.x;
    const int lane = tid & 31;
    const int warp = tid >> 5;
    const int wm = (warp >> 2) << 6;
    const int wn = (warp & 3) << 5;
    const int row0 = blockIdx.y * 128;
    const int col0 = blockIdx.x * 128;

    const __half* src[2] = {A + (size_t)row0 * K, B + (size_t)col0 * K};

    const int r_g  = tid >> 2;
    const int r_g2 = r_g + 64;
    const int c_g  = tid & 3;
    const uint32_t dst1 = (uint32_t)((r_g  << 6) + ((c_g ^ ((r_g  >> 1) & 3)) << 4));
    const uint32_t dst2 = (uint32_t)((r_g2 << 6) + ((c_g ^ ((r_g2 >> 1) & 3)) << 4));

    uint32_t offA[4][2], offB[4][2];
#pragma unroll
    for (int mf = 0; mf < 4; mf++) {
        int r = wm + (mf << 4) + (lane & 15);
#pragma unroll
        for (int k2 = 0; k2 < 2; k2++) {
            int c16 = (lane >> 4) + (k2 << 1);
            offA[mf][k2] = (uint32_t)((r << 6) + ((c16 ^ ((r >> 1) & 3)) << 4));
        }
    }
#pragma unroll
    for (int nf = 0; nf < 4; nf++) {
        int r = wn + (nf << 3) + (lane & 7);
#pragma unroll
        for (int k2 = 0; k2 < 2; k2++) {
            int c16 = ((lane >> 3) & 1) + (k2 << 1);
            offB[nf][k2] = (uint32_t)((r << 6) + ((c16 ^ ((r >> 1) & 3)) << 4));
        }
    }

    float acc[4][4][4];
#pragma unroll
    for (int mf = 0; mf < 4; mf++)
#pragma unroll
        for (int nf = 0; nf < 4; nf++)
#pragma unroll
            for (int e = 0; e < 4; e++) acc[mf][nf][e] = 0.f;

    const int nchunks = K >> 5;     // 16

    auto issue = [&](int stage, int kc) {
#pragma unroll
        for (int a = 0; a < 2; a++) {
            uint32_t base = sb + (uint32_t)(((stage << 1) + a) << 13);
            const char* g1 = (const char*)(src[a] + (size_t)r_g  * K + (kc << 5) + (c_g << 3));
            const char* g2 = (const char*)(src[a] + (size_t)r_g2 * K + (kc << 5) + (c_g << 3));
            CP16(base + dst1, g1);
            CP16(base + dst2, g2);
        }
        CPCOMMIT();
    };

    issue(0, 0);
    issue(1, 1);
    int stage = 0;
    for (int kc = 0; kc < nchunks; kc++) {
        if (kc == nchunks - 1) { CPWAIT(0); } else { CPWAIT(1); }
        __syncthreads();

        const uint32_t st = sb + (uint32_t)(stage * 16384);
#pragma unroll
        for (int k2 = 0; k2 < 2; k2++) {
            uint32_t ah[4][4], bh[4][2];
#pragma unroll
            for (int mf = 0; mf < 4; mf++)
                LDSM4(ah[mf], st + offA[mf][k2]);
#pragma unroll
            for (int nf = 0; nf < 4; nf++)
                LDSM2(bh[nf], st + 8192 + offB[nf][k2]);
#pragma unroll
            for (int mf = 0; mf < 4; mf++)
#pragma unroll
                for (int nf = 0; nf < 4; nf++)
                    MMAH16816(acc[mf][nf], ah[mf], bh[nf]);
        }
        // chunk kc+2 -> stage (kc+2)%3 == (stage+2)%3 (validated rotation)
        if (kc + 2 < nchunks) {
            int tgt = stage + 2;
            if (tgt >= 3) tgt -= 3;
            issue(tgt, kc + 2);
        }
        stage = (stage == 2) ? 0 : stage + 1;
    }

    const int qr = lane >> 2;
    const int qc = (lane & 3) << 1;

#pragma unroll
    for (int nf = 0; nf < 4; nf++) {
        float2 bi = *(const float2*)(bias + col0 + wn + (nf << 3) + qc);
#pragma unroll
        for (int mf = 0; mf < 4; mf++) {
            acc[mf][nf][0] += bi.x; acc[mf][nf][1] += bi.y;
            acc[mf][nf][2] += bi.x; acc[mf][nf][3] += bi.y;
        }
    }

    if (!fuse) {
#pragma unroll
        for (int mf = 0; mf < 4; mf++)
#pragma unroll
            for (int nf = 0; nf < 4; nf++) {
                int row = row0 + wm + (mf << 4) + qr;
                int col = col0 + wn + (nf << 3) + qc;
                *(float2*)(C + (size_t)row * N + col) =
                    make_float2(acc[mf][nf][0], acc[mf][nf][1]);
                *(float2*)(C + (size_t)(row + 8) * N + col) =
                    make_float2(acc[mf][nf][2], acc[mf][nf][3]);
            }
        return;
    }

    const int sec = blockIdx.x >> 2;          // 0=q, 1=k, 2=v
    if (sec < 2) {
        float scale = 1.f;
        if (sec == 0) {
            int h = (col0 + wn) >> 5;          // warp covers exactly one head
            scale = expf(fminf(lsc[h], 4.6051701860f));
        }
#pragma unroll
        for (int mf = 0; mf < 4; mf++) {
#pragma unroll
            for (int e = 0; e < 2; e++) {
                float ss = 0.f;
#pragma unroll
                for (int nf = 0; nf < 4; nf++) {
                    float a0 = acc[mf][nf][e * 2], a1 = acc[mf][nf][e * 2 + 1];
                    ss = fmaf(a0, a0, fmaf(a1, a1, ss));
                }
                ss += __shfl_xor_sync(0xffffffffu, ss, 1);
                ss += __shfl_xor_sync(0xffffffffu, ss, 2);
                float inv = rsqrtf(ss) * scale;
                int row = row0 + wm + (mf << 4) + (e << 3) + qr;
#pragma unroll
                for (int nf = 0; nf < 4; nf++) {
                    int col = col0 + wn + (nf << 3) + qc - sec * 512;
                    float v0 = acc[mf][nf][e * 2] * inv;
                    float v1 = acc[mf][nf][e * 2 + 1] * inv;
                    __nv_bfloat162 hh, ll;
                    hh.x = __float2bfloat16(v0);
                    hh.y = __float2bfloat16(v1);
                    ll.x = __float2bfloat16(v0 - __bfloat162float(hh.x));
                    ll.y = __float2bfloat16(v1 - __bfloat162float(hh.y));
                    size_t idx = (size_t)row * DIMC + col;
                    if (sec == 0) {
                        *(__nv_bfloat162*)(qh + idx) = hh;
                        *(__nv_bfloat162*)(ql + idx) = ll;
                    } else {
                        *(__nv_bfloat162*)(kh + idx) = hh;
                        *(__nv_bfloat162*)(kl + idx) = ll;
                    }
                }
            }
        }
    } else {
#pragma unroll
        for (int mf = 0; mf < 4; mf++)
#pragma unroll
            for (int nf = 0; nf < 4; nf++) {
                int row = row0 + wm + (mf << 4) + qr;
                int col = col0 + wn + (nf << 3) + qc - 1024;
                __half2 a0, a1;
                a0.x = __float2half_rn(acc[mf][nf][0]);
                a0.y = __float2half_rn(acc[mf][nf][1]);
                a1.x = __float2half_rn(acc[mf][nf][2]);
                a1.y = __float2half_rn(acc[mf][nf][3]);
                *(__half2*)(vout + (size_t)row * DIMC + col)       = a0;
                *(__half2*)(vout + (size_t)(row + 8) * DIMC + col) = a1;
            }
    }
}

// ---------------- fused attention ----------------
// smem layout (bytes): QK tiles 16KB (aliased by P fp16 hi/lo after S-phase),
// Vt fp16 4KB, S fp32 17.4KB (V fp16 staging aliases S before S-phase).
#define OQH 0
#define OQL 4096
#define OKH 8192
#define OKL 12288
#define OPH 0                       /* alias QH/QL */
#define OPL 8192                    /* alias KH/KL */
#define OVT 16384                   /* Vt fp16 [32][64], 4KB */
#define OS  20480                   /* S fp32 64 x 68 */
#define OVV 20480                   /* V fp16 staging [64 tok][40 halves], aliases S */
#define ATT_SMEM (20480 + 64 * 68 * 4)   /* 37888 */

__global__ __launch_bounds__(128) void k_attn(const float* __restrict__ mask,
                                              const float* __restrict__ logit_scale) {
    extern __shared__ char sm[];
    const int h = blockIdx.x;
    const int b = blockIdx.y;
    const int tid = threadIdx.x, lane = tid & 31, warp = tid >> 5;
    const uint32_t sbase = smem_u32(sm);
    (void)logit_scale;

    const size_t rowbase = (size_t)(b * NTOK) * DIMC + (size_t)h * HD;

    // ---- cp.async: q/k (bf16 hi/lo, pre-normalized) into swizzled tiles
#pragma unroll
    for (int i = tid; i < 256; i += 128) {
        int tok = i >> 2, c = i & 3;
        int swz = (tok >> 1) & 3;
        uint32_t d = (uint32_t)((tok << 6) + ((c ^ swz) << 4));
        size_t g = rowbase + (size_t)tok * DIMC + (c << 3);
        CP16(sbase + OQH + d, (const char*)(g_q_hi + g));
        CP16(sbase + OQL + d, (const char*)(g_q_lo + g));
        CP16(sbase + OKH + d, (const char*)(g_k_hi + g));
        CP16(sbase + OKL + d, (const char*)(g_k_lo + g));
    }
    // ---- cp.async: V fp16 staged [tok][40 halves] (80B stride)
#pragma unroll
    for (int i = tid; i < 256; i += 128) {
        int tok = i >> 2, c = i & 3;
        CP16(sbase + OVV + tok * 80 + (c << 4),
             (const char*)(g_v + rowbase + (size_t)tok * DIMC + (c << 3)));
    }
    CPCOMMIT(); CPWAIT(0);
    __syncthreads();

    // ---- transpose V: [64 tok][32 d] fp16 -> Vt [32 d][64 tok] fp16
    {
        int d = tid >> 2, jc = (tid & 3) << 4;
        const __half* vv = (const __half*)(sm + OVV);
        int swz = d & 7;
#pragma unroll
        for (int c2 = 0; c2 < 2; c2++) {
            __half2 t[4];
#pragma unroll
            for (int e = 0; e < 4; e++) {
                t[e].x = vv[(jc + c2 * 8 + 2 * e) * 40 + d];
                t[e].y = vv[(jc + c2 * 8 + 2 * e + 1) * 40 + d];
            }
            int c = (jc >> 3) + c2;
            *(uint4*)(sm + OVT + (d << 7) + ((c ^ swz) << 4)) = *(uint4*)t;
        }
    }
    __syncthreads();    // staging reads done before S-phase overwrites OS

    // ---- S = qn kn^T (bf16 3-product)
    {
        uint32_t ah[2][4], al[2][4];
        int ra = (warp << 4) + (lane & 15);
        int ca = lane >> 4;
        int swa = (ra >> 1) & 3;
#pragma unroll
        for (int k2 = 0; k2 < 2; k2++) {
            uint32_t off = (uint32_t)((ra << 6) + (((ca + (k2 << 1)) ^ swa) << 4));
            LDSM4(ah[k2], sbase + OQH + off);
            LDSM4(al[k2], sbase + OQL + off);
        }
        float* S = (float*)(sm + OS);
        int qr = lane >> 2, qc = (lane & 3) << 1;
#pragma unroll
        for (int nf = 0; nf < 8; nf++) {
            float acc[4] = {0.f, 0.f, 0.f, 0.f};
            int rb = (nf << 3) + (lane & 7);
            int swb = (rb >> 1) & 3;
#pragma unroll
            for (int k2 = 0; k2 < 2; k2++) {
                uint32_t off = (uint32_t)((rb << 6) +
                    (((((lane >> 3) & 1) + (k2 << 1)) ^ swb) << 4));
                uint32_t bh[2], bl[2];
                LDSM2(bh, sbase + OKH + off);
                LDSM2(bl, sbase + OKL + off);
                MMA16816(acc, ah[k2], bh);
                MMA16816(acc, ah[k2], bl);
                MMA16816(acc, al[k2], bh);
            }
            int row = (warp << 4) + qr, col = (nf << 3) + qc;
            *(float2*)(S + row * 68 + col)       = make_float2(acc[0], acc[1]);
            *(float2*)(S + (row + 8) * 68 + col) = make_float2(acc[2], acc[3]);
        }
    }
    __syncthreads();

    // ---- softmax: 2 threads per row, write P fp16 hi/lo
    {
        int r = tid >> 1;
        int hf = tid & 1;
        float* Sp = (float*)(sm + OS) + r * 68 + (hf << 5);
        const float* mrow = mask + (size_t)(b & (NWIN - 1)) * NTOK * NTOK + r * 64 + (hf << 5);
        const float* rrow = g_rpb + (size_t)h * NTOK * NTOK + r * 64 + (hf << 5);
        float p[32];
        float mx = -1e30f;
#pragma unroll
        for (int j = 0; j < 32; j += 4) {
            float4 s4 = *(float4*)(Sp + j);
            float4 rb = *(const float4*)(rrow + j);
            float4 mk = *(const float4*)(mrow + j);
            p[j + 0] = s4.x + rb.x + mk.x;
            p[j + 1] = s4.y + rb.y + mk.y;
            p[j + 2] = s4.z + rb.z + mk.z;
            p[j + 3] = s4.w + rb.w + mk.w;
            mx = fmaxf(mx, fmaxf(fmaxf(p[j], p[j + 1]), fmaxf(p[j + 2], p[j + 3])));
        }
        mx = fmaxf(mx, __shfl_xor_sync(0xffffffffu, mx, 1));
        float sum = 0.f;
#pragma unroll
        for (int j = 0; j < 32; j++) { p[j] = expf(p[j] - mx); sum += p[j]; }
        sum += __shfl_xor_sync(0xffffffffu, sum, 1);
        float inv = 1.0f / sum;
#pragma unroll
        for (int j = 0; j < 32; j++) p[j] *= inv;
        int swz = r & 7;
#pragma unroll
        for (int c2 = 0; c2 < 4; c2++) {
            int c = (hf << 2) + c2;
            uint4 hi, lo;
            pack8h(p + 8 * c2, hi, lo);
            *(uint4*)(sm + OPH + (r << 7) + ((c ^ swz) << 4)) = hi;
            *(uint4*)(sm + OPL + (r << 7) + ((c ^ swz) << 4)) = lo;
        }
    }
    __syncthreads();

    // ---- O = (Ph+Pl) Vh (fp16 2-product) ; emits single fp16 for proj
    {
        float acc[4][4];
#pragma unroll
        for (int nf = 0; nf < 4; nf++)
#pragma unroll
            for (int e = 0; e < 4; e++) acc[nf][e] = 0.f;
        int ra = (warp << 4) + (lane & 15);
        int ca = lane >> 4;
        int swa = ra & 7;
#pragma unroll
        for (int ks = 0; ks < 4; ks++) {
            uint32_t offp = (uint32_t)((ra << 7) + (((ca + (ks << 1)) ^ swa) << 4));
            uint32_t ph[4], pl[4];
            LDSM4(ph, sbase + OPH + offp);
            LDSM4(pl, sbase + OPL + offp);
#pragma unroll
            for (int nf = 0; nf < 4; nf++) {
                int rv = (nf << 3) + (lane & 7);
                int swv = rv & 7;
                uint32_t offv = (uint32_t)((rv << 7) +
                    (((((lane >> 3) & 1) + (ks << 1)) ^ swv) << 4));
                uint32_t vh[2];
                LDSM2(vh, sbase + OVT + offv);
                MMAH16816(acc[nf], ph, vh);
                MMAH16816(acc[nf], pl, vh);
            }
        }
        int qr = lane >> 2, qc = (lane & 3) << 1;
#pragma unroll
        for (int nf = 0; nf < 4; nf++) {
#pragma unroll
            for (int e = 0; e < 2; e++) {
                int row = (warp << 4) + qr + (e << 3);
                int col = (nf << 3) + qc;
                size_t idx = (size_t)(b * NTOK + row) * DIMC + h * HD + col;
                __half2 hh;
                hh.x = __float2half_rn(acc[nf][e * 2]);
                hh.y = __float2half_rn(acc[nf][e * 2 + 1]);
                *(__half2*)(g_attn + idx) = hh;
            }
        }
    }
}

// ---------------- launcher ----------------
extern "C" void kernel_launch(void* const* d_in, const int* in_sizes, int n_in,
                              void* d_out, int out_size) {
    (void)in_sizes; (void)n_in; (void)out_size;
    const float* x           = (const float*)d_in[0];
    const float* mask        = (const float*)d_in[1];
    const float* qkv_w       = (const float*)d_in[2];
    const float* q_bias      = (const float*)d_in[3];
    const float* v_bias      = (const float*)d_in[4];
    const float* logit_scale = (const float*)d_in[5];
    const float* cpb_w1      = (const float*)d_in[6];
    const float* cpb_b1      = (const float*)d_in[7];
    const float* cpb_w2      = (const float*)d_in[8];
    const float* proj_w      = (const float*)d_in[9];
    const float* proj_b      = (const float*)d_in[10];
    float* out = (float*)d_out;

    float* p_qkvb;
    __half *p_v, *p_x, *p_attn, *p_wq, *p_wp;
    __nv_bfloat16 *p_qh, *p_ql, *p_kh, *p_kl;
    cudaGetSymbolAddress((void**)&p_qkvb, g_qkv_bias);
    cudaGetSymbolAddress((void**)&p_v,    g_v);
    cudaGetSymbolAddress((void**)&p_x,    g_x);
    cudaGetSymbolAddress((void**)&p_attn, g_attn);
    cudaGetSymbolAddress((void**)&p_wq,   g_wqkv);
    cudaGetSymbolAddress((void**)&p_wp,   g_wproj);
    cudaGetSymbolAddress((void**)&p_qh,   g_q_hi);
    cudaGetSymbolAddress((void**)&p_ql,   g_q_lo);
    cudaGetSymbolAddress((void**)&p_kh,   g_k_hi);
    cudaGetSymbolAddress((void**)&p_kl,   g_k_lo);

    cudaFuncSetAttribute(gemm_mma, cudaFuncAttributeMaxDynamicSharedMemorySize, GSMEM);
    cudaFuncSetAttribute(k_attn,   cudaFuncAttributeMaxDynamicSharedMemorySize, ATT_SMEM);

    k_make_qkv_bias<<<3, 512>>>(q_bias, v_bias);
    k_cpb<<<225, CPBH>>>(cpb_w1, cpb_b1, cpb_w2);
    k_rpb<<<64, 1024>>>();

    k_cvt<<<(NROWS * DIMC / 4 + 255) / 256, 256>>>(x, p_x, NROWS * DIMC / 4);
    k_w_t<<<(QKVC * DIMC + 255) / 256, 256>>>(qkv_w, p_wq, DIMC, QKVC);
    k_w_t<<<(DIMC * DIMC + 255) / 256, 256>>>(proj_w, p_wp, DIMC, DIMC);

    // QKV GEMM (1-product fp16) with fused normalize/scale epilogue
    gemm_mma<<<dim3(QKVC / 128, NROWS / 128), 256, GSMEM>>>(
        p_x, p_wq, p_qkvb, nullptr,
        p_qh, p_ql, p_kh, p_kl, p_v, logit_scale, 1, NROWS, QKVC, DIMC);

    // fused attention (HMMA S & O, fp32 softmax)
    k_attn<<<dim3(NHEADS, BWIN), 128, ATT_SMEM>>>(mask, logit_scale);

    // proj GEMM (1-product fp16) -> d_out
    gemm_mma<<<dim3(DIMC / 128, NROWS / 128), 256, GSMEM>>>(
        p_attn, p_wp, proj_b, out,
        nullptr, nullptr, nullptr, nullptr, nullptr, nullptr, 0, NROWS, DIMC, DIMC);
}

// round 16
// speedup vs baseline: 5.2292x; 1.1749x over previous
#include <cuda_runtime.h>
#include <cuda_bf16.h>
#include <cuda_fp16.h>
#include <cstdint>
#include <math.h>

// ---------------- problem constants ----------------
#define DIMC   512
#define NHEADS 16
#define HD     32
#define NTOK   64
#define BWIN   1024
#define NWIN   64
#define CPBH   512
#define NROWS  (BWIN * NTOK)          /* 65536 */
#define QKVC   (3 * DIMC)             /* 1536  */

// ---------------- device scratch (no allocs allowed) ----------------
__device__ __nv_bfloat16 g_q_hi[NROWS * DIMC];   // normalized*scale q, bf16 hi/lo
__device__ __nv_bfloat16 g_q_lo[NROWS * DIMC];
__device__ __nv_bfloat16 g_k_hi[NROWS * DIMC];   // normalized k
__device__ __nv_bfloat16 g_k_lo[NROWS * DIMC];
__device__ __half g_v[NROWS * DIMC];             // v fp16 (single)
__device__ __half g_x[NROWS * DIMC];             // x fp16 (single)
__device__ __half g_attn[NROWS * DIMC];          // attention out fp16 (single)
__device__ __half g_wqkv[QKVC * DIMC];           // [N=1536, K=512] transposed, fp16
__device__ __half g_wproj[DIMC * DIMC];          // [N=512, K=512] transposed, fp16
__device__ float g_bias_table[225 * NHEADS];
__device__ float g_rpb[NHEADS * NTOK * NTOK];
__device__ float g_qkv_bias[QKVC];

// ---------------- mma.sync helpers (arch-agnostic PTX) ----------------
#define LDSM4(R, addr)                                                        \
    asm volatile("ldmatrix.sync.aligned.m8n8.x4.shared.b16 {%0,%1,%2,%3},[%4];" \
                 : "=r"((R)[0]), "=r"((R)[1]), "=r"((R)[2]), "=r"((R)[3])     \
                 : "r"(addr))
#define LDSM2(R, addr)                                                        \
    asm volatile("ldmatrix.sync.aligned.m8n8.x2.shared.b16 {%0,%1},[%2];"     \
                 : "=r"((R)[0]), "=r"((R)[1]) : "r"(addr))
#define MMA16816(D, A, B)                                                     \
    asm volatile("mma.sync.aligned.m16n8k16.row.col.f32.bf16.bf16.f32 "       \
                 "{%0,%1,%2,%3},{%4,%5,%6,%7},{%8,%9},{%0,%1,%2,%3};"         \
                 : "+f"((D)[0]), "+f"((D)[1]), "+f"((D)[2]), "+f"((D)[3])     \
                 : "r"((A)[0]), "r"((A)[1]), "r"((A)[2]), "r"((A)[3]),        \
                   "r"((B)[0]), "r"((B)[1]))
#define MMAH16816(D, A, B)                                                    \
    asm volatile("mma.sync.aligned.m16n8k16.row.col.f32.f16.f16.f32 "         \
                 "{%0,%1,%2,%3},{%4,%5,%6,%7},{%8,%9},{%0,%1,%2,%3};"         \
                 : "+f"((D)[0]), "+f"((D)[1]), "+f"((D)[2]), "+f"((D)[3])     \
                 : "r"((A)[0]), "r"((A)[1]), "r"((A)[2]), "r"((A)[3]),        \
                   "r"((B)[0]), "r"((B)[1]))
#define CP16(dst, src)                                                        \
    asm volatile("cp.async.cg.shared.global [%0],[%1],16;" :: "r"(dst), "l"(src))
#define CPCOMMIT() asm volatile("cp.async.commit_group;")
#define CPWAIT(n)  asm volatile("cp.async.wait_group %0;" :: "n"(n))

__device__ __forceinline__ uint32_t smem_u32(const void* p) {
    uint32_t a;
    asm("{ .reg .u64 t; cvta.to.shared.u64 t, %1; cvt.u32.u64 %0, t; }" : "=r"(a) : "l"(p));
    return a;
}

// pack two fp32 into fp16x2 hi and residual lo
__device__ __forceinline__ void split2h(float a, float b, uint32_t& hi, uint32_t& lo) {
    __half2 h, l;
    h.x = __float2half_rn(a);
    h.y = __float2half_rn(b);
    l.x = __float2half_rn(a - __half2float(h.x));
    l.y = __float2half_rn(b - __half2float(h.y));
    hi = *(uint32_t*)&h;
    lo = *(uint32_t*)&l;
}

// ---------------- setup kernels ----------------
__global__ void k_make_qkv_bias(const float* __restrict__ qb,
                                const float* __restrict__ vb) {
    int i = blockIdx.x * blockDim.x + threadIdx.x;
    if (i < QKVC) {
        float v = 0.f;
        if (i < DIMC)            v = qb[i];
        else if (i >= 2 * DIMC)  v = vb[i - 2 * DIMC];
        g_qkv_bias[i] = v;
    }
}

__device__ __forceinline__ float cpb_coord(int u) {
    float t = (float)u * (8.0f / 7.0f);
    float s = (t > 0.f) ? 1.f : ((t < 0.f) ? -1.f : 0.f);
    return s * log2f(fabsf(t) + 1.0f) * (1.0f / 3.0f);
}

__global__ void k_cpb(const float* __restrict__ w1, const float* __restrict__ b1,
                      const float* __restrict__ w2) {
    __shared__ float hid[CPBH];
    int m = blockIdx.x;
    int k = threadIdx.x;
    float c0 = cpb_coord(m % 15 - 7);
    float c1 = cpb_coord(m / 15 - 7);
    hid[k] = fmaxf(fmaf(c0, w1[k], fmaf(c1, w1[CPBH + k], b1[k])), 0.f);
    __syncthreads();
    int warp = k >> 5, lane = k & 31;
    float s = 0.f;
    for (int kk = lane; kk < CPBH; kk += 32)
        s = fmaf(hid[kk], w2[kk * NHEADS + warp], s);
#pragma unroll
    for (int o = 16; o > 0; o >>= 1) s += __shfl_xor_sync(0xffffffffu, s, o);
    if (lane == 0) g_bias_table[m * NHEADS + warp] = s;
}

__global__ void k_rpb() {
    int id = blockIdx.x * blockDim.x + threadIdx.x;
    int h = id >> 12;
    int p = (id >> 6) & 63;
    int q = id & 63;
    int idx = (((p & 7) - (q & 7)) + 7) * 15 + (((p >> 3) - (q >> 3)) + 7);
    float v = g_bias_table[idx * NHEADS + h];
    g_rpb[id] = 16.0f / (1.0f + expf(-v));
}

// convert fp32 -> fp16, vectorized by 4
__global__ void k_cvt(const float* __restrict__ s, __half* __restrict__ o, int n4) {
    int i = blockIdx.x * blockDim.x + threadIdx.x;
    if (i < n4) {
        float4 v = *(const float4*)(s + i * 4);
        __half2 a, b;
        a.x = __float2half_rn(v.x); a.y = __float2half_rn(v.y);
        b.x = __float2half_rn(v.z); b.y = __float2half_rn(v.w);
        *(__half2*)(o + i * 4)     = a;
        *(__half2*)(o + i * 4 + 2) = b;
    }
}

// transpose weights to single fp16: w [K,N] fp32 -> [N,K] fp16
__global__ void k_w_t(const float* __restrict__ w, __half* __restrict__ o,
                      int K, int N) {
    int i = blockIdx.x * blockDim.x + threadIdx.x;
    if (i < K * N) {
        int n = i / K, k = i - n * K;
        o[i] = __float2half_rn(w[(size_t)k * N + n]);
    }
}

// ---------------- fp16 HMMA GEMM, 3-stage cp.async ----------------
// C = A @ B^T ; A [M,K] fp16, B [N,K] fp16. 128x128x32 tile, 256 thr.
// smem: 3 stages x 2 arrays x 8KB = 48KB.
// fuse=1 (QKV): q/k normalized (+logit scale for q) -> bf16 hi/lo; v -> fp16.
#define GSMEM (3 * 2 * 8192)

__global__ __launch_bounds__(256) void gemm_mma(
    const __half* __restrict__ A, const __half* __restrict__ B,
    const float* __restrict__ bias, float* __restrict__ C,
    __nv_bfloat16* __restrict__ qh, __nv_bfloat16* __restrict__ ql,
    __nv_bfloat16* __restrict__ kh, __nv_bfloat16* __restrict__ kl,
    __half* __restrict__ vout, const float* __restrict__ lsc,
    int fuse, int M, int N, int K) {
    extern __shared__ char gsm[];
    const uint32_t sb = smem_u32(gsm);

    const int tid  = threadIdx.x;
    const int lane = tid & 31;
    const int warp = tid >> 5;
    const int wm = (warp >> 2) << 6;
    const int wn = (warp & 3) << 5;
    const int row0 = blockIdx.y * 128;
    const int col0 = blockIdx.x * 128;

    const __half* src[2] = {A + (size_t)row0 * K, B + (size_t)col0 * K};

    const int r_g  = tid >> 2;
    const int r_g2 = r_g + 64;
    const int c_g  = tid & 3;
    const uint32_t dst1 = (uint32_t)((r_g  << 6) + ((c_g ^ ((r_g  >> 1) & 3)) << 4));
    const uint32_t dst2 = (uint32_t)((r_g2 << 6) + ((c_g ^ ((r_g2 >> 1) & 3)) << 4));

    uint32_t offA[4][2], offB[4][2];
#pragma unroll
    for (int mf = 0; mf < 4; mf++) {
        int r = wm + (mf << 4) + (lane & 15);
#pragma unroll
        for (int k2 = 0; k2 < 2; k2++) {
            int c16 = (lane >> 4) + (k2 << 1);
            offA[mf][k2] = (uint32_t)((r << 6) + ((c16 ^ ((r >> 1) & 3)) << 4));
        }
    }
#pragma unroll
    for (int nf = 0; nf < 4; nf++) {
        int r = wn + (nf << 3) + (lane & 7);
#pragma unroll
        for (int k2 = 0; k2 < 2; k2++) {
            int c16 = ((lane >> 3) & 1) + (k2 << 1);
            offB[nf][k2] = (uint32_t)((r << 6) + ((c16 ^ ((r >> 1) & 3)) << 4));
        }
    }

    float acc[4][4][4];
#pragma unroll
    for (int mf = 0; mf < 4; mf++)
#pragma unroll
        for (int nf = 0; nf < 4; nf++)
#pragma unroll
            for (int e = 0; e < 4; e++) acc[mf][nf][e] = 0.f;

    const int nchunks = K >> 5;     // 16

    auto issue = [&](int stage, int kc) {
#pragma unroll
        for (int a = 0; a < 2; a++) {
            uint32_t base = sb + (uint32_t)(((stage << 1) + a) << 13);
            const char* g1 = (const char*)(src[a] + (size_t)r_g  * K + (kc << 5) + (c_g << 3));
            const char* g2 = (const char*)(src[a] + (size_t)r_g2 * K + (kc << 5) + (c_g << 3));
            CP16(base + dst1, g1);
            CP16(base + dst2, g2);
        }
        CPCOMMIT();
    };

    issue(0, 0);
    issue(1, 1);
    int stage = 0;
    for (int kc = 0; kc < nchunks; kc++) {
        if (kc == nchunks - 1) { CPWAIT(0); } else { CPWAIT(1); }
        __syncthreads();

        const uint32_t st = sb + (uint32_t)(stage * 16384);
#pragma unroll
        for (int k2 = 0; k2 < 2; k2++) {
            uint32_t ah[4][4], bh[4][2];
#pragma unroll
            for (int mf = 0; mf < 4; mf++)
                LDSM4(ah[mf], st + offA[mf][k2]);
#pragma unroll
            for (int nf = 0; nf < 4; nf++)
                LDSM2(bh[nf], st + 8192 + offB[nf][k2]);
#pragma unroll
            for (int mf = 0; mf < 4; mf++)
#pragma unroll
                for (int nf = 0; nf < 4; nf++)
                    MMAH16816(acc[mf][nf], ah[mf], bh[nf]);
        }
        if (kc + 2 < nchunks) {
            int tgt = stage + 2;
            if (tgt >= 3) tgt -= 3;
            issue(tgt, kc + 2);
        }
        stage = (stage == 2) ? 0 : stage + 1;
    }

    const int qr = lane >> 2;
    const int qc = (lane & 3) << 1;

#pragma unroll
    for (int nf = 0; nf < 4; nf++) {
        float2 bi = *(const float2*)(bias + col0 + wn + (nf << 3) + qc);
#pragma unroll
        for (int mf = 0; mf < 4; mf++) {
            acc[mf][nf][0] += bi.x; acc[mf][nf][1] += bi.y;
            acc[mf][nf][2] += bi.x; acc[mf][nf][3] += bi.y;
        }
    }

    if (!fuse) {
#pragma unroll
        for (int mf = 0; mf < 4; mf++)
#pragma unroll
            for (int nf = 0; nf < 4; nf++) {
                int row = row0 + wm + (mf << 4) + qr;
                int col = col0 + wn + (nf << 3) + qc;
                *(float2*)(C + (size_t)row * N + col) =
                    make_float2(acc[mf][nf][0], acc[mf][nf][1]);
                *(float2*)(C + (size_t)(row + 8) * N + col) =
                    make_float2(acc[mf][nf][2], acc[mf][nf][3]);
            }
        return;
    }

    const int sec = blockIdx.x >> 2;          // 0=q, 1=k, 2=v
    if (sec < 2) {
        float scale = 1.f;
        if (sec == 0) {
            int h = (col0 + wn) >> 5;          // warp covers exactly one head
            scale = expf(fminf(lsc[h], 4.6051701860f));
        }
#pragma unroll
        for (int mf = 0; mf < 4; mf++) {
#pragma unroll
            for (int e = 0; e < 2; e++) {
                float ss = 0.f;
#pragma unroll
                for (int nf = 0; nf < 4; nf++) {
                    float a0 = acc[mf][nf][e * 2], a1 = acc[mf][nf][e * 2 + 1];
                    ss = fmaf(a0, a0, fmaf(a1, a1, ss));
                }
                ss += __shfl_xor_sync(0xffffffffu, ss, 1);
                ss += __shfl_xor_sync(0xffffffffu, ss, 2);
                float inv = rsqrtf(ss) * scale;
                int row = row0 + wm + (mf << 4) + (e << 3) + qr;
#pragma unroll
                for (int nf = 0; nf < 4; nf++) {
                    int col = col0 + wn + (nf << 3) + qc - sec * 512;
                    float v0 = acc[mf][nf][e * 2] * inv;
                    float v1 = acc[mf][nf][e * 2 + 1] * inv;
                    __nv_bfloat162 hh, ll;
                    hh.x = __float2bfloat16(v0);
                    hh.y = __float2bfloat16(v1);
                    ll.x = __float2bfloat16(v0 - __bfloat162float(hh.x));
                    ll.y = __float2bfloat16(v1 - __bfloat162float(hh.y));
                    size_t idx = (size_t)row * DIMC + col;
                    if (sec == 0) {
                        *(__nv_bfloat162*)(qh + idx) = hh;
                        *(__nv_bfloat162*)(ql + idx) = ll;
                    } else {
                        *(__nv_bfloat162*)(kh + idx) = hh;
                        *(__nv_bfloat162*)(kl + idx) = ll;
                    }
                }
            }
        }
    } else {
#pragma unroll
        for (int mf = 0; mf < 4; mf++)
#pragma unroll
            for (int nf = 0; nf < 4; nf++) {
                int row = row0 + wm + (mf << 4) + qr;
                int col = col0 + wn + (nf << 3) + qc - 1024;
                __half2 a0, a1;
                a0.x = __float2half_rn(acc[mf][nf][0]);
                a0.y = __float2half_rn(acc[mf][nf][1]);
                a1.x = __float2half_rn(acc[mf][nf][2]);
                a1.y = __float2half_rn(acc[mf][nf][3]);
                *(__half2*)(vout + (size_t)row * DIMC + col)       = a0;
                *(__half2*)(vout + (size_t)(row + 8) * DIMC + col) = a1;
            }
    }
}

// ---------------- fused attention: register-resident softmax + P ----------------
// smem: QK bf16 hi/lo tiles 16KB + Vt fp16 4KB + V fp16 staging 5KB = 25.6KB.
// After the V transpose there are NO barriers: warp w owns S/P/O rows [16w,16w+16).
#define OQH 0
#define OQL 4096
#define OKH 8192
#define OKL 12288
#define OVT 16384                   /* Vt fp16 [32][64], 4KB */
#define OVV 20480                   /* V fp16 staging [64 tok][40 halves] */
#define ATT_SMEM (20480 + 64 * 80)  /* 25600 */

__global__ __launch_bounds__(128) void k_attn(const float* __restrict__ mask,
                                              const float* __restrict__ logit_scale) {
    extern __shared__ char sm[];
    const int h = blockIdx.x;
    const int b = blockIdx.y;
    const int tid = threadIdx.x, lane = tid & 31, warp = tid >> 5;
    const uint32_t sbase = smem_u32(sm);
    (void)logit_scale;

    const size_t rowbase = (size_t)(b * NTOK) * DIMC + (size_t)h * HD;

    // ---- cp.async: q/k (bf16 hi/lo, pre-normalized) into swizzled tiles
#pragma unroll
    for (int i = tid; i < 256; i += 128) {
        int tok = i >> 2, c = i & 3;
        int swz = (tok >> 1) & 3;
        uint32_t d = (uint32_t)((tok << 6) + ((c ^ swz) << 4));
        size_t g = rowbase + (size_t)tok * DIMC + (c << 3);
        CP16(sbase + OQH + d, (const char*)(g_q_hi + g));
        CP16(sbase + OQL + d, (const char*)(g_q_lo + g));
        CP16(sbase + OKH + d, (const char*)(g_k_hi + g));
        CP16(sbase + OKL + d, (const char*)(g_k_lo + g));
    }
    // ---- cp.async: V fp16 staged [tok][40 halves] (80B stride)
#pragma unroll
    for (int i = tid; i < 256; i += 128) {
        int tok = i >> 2, c = i & 3;
        CP16(sbase + OVV + tok * 80 + (c << 4),
             (const char*)(g_v + rowbase + (size_t)tok * DIMC + (c << 3)));
    }
    CPCOMMIT(); CPWAIT(0);
    __syncthreads();

    // ---- transpose V: [64 tok][32 d] fp16 -> Vt [32 d][64 tok] fp16
    {
        int d = tid >> 2, jc = (tid & 3) << 4;
        const __half* vv = (const __half*)(sm + OVV);
        int swz = d & 7;
#pragma unroll
        for (int c2 = 0; c2 < 2; c2++) {
            __half2 t[4];
#pragma unroll
            for (int e = 0; e < 4; e++) {
                t[e].x = vv[(jc + c2 * 8 + 2 * e) * 40 + d];
                t[e].y = vv[(jc + c2 * 8 + 2 * e + 1) * 40 + d];
            }
            int c = (jc >> 3) + c2;
            *(uint4*)(sm + OVT + (d << 7) + ((c ^ swz) << 4)) = *(uint4*)t;
        }
    }
    __syncthreads();   // last barrier: Vt ready for all warps

    const int qr = lane >> 2;
    const int qc = (lane & 3) << 1;

    // ---- S = qn kn^T (bf16 3-product), fragments stay in registers
    float acc[8][4];
    {
        uint32_t ah[2][4], al[2][4];
        int ra = (warp << 4) + (lane & 15);
        int ca = lane >> 4;
        int swa = (ra >> 1) & 3;
#pragma unroll
        for (int k2 = 0; k2 < 2; k2++) {
            uint32_t off = (uint32_t)((ra << 6) + (((ca + (k2 << 1)) ^ swa) << 4));
            LDSM4(ah[k2], sbase + OQH + off);
            LDSM4(al[k2], sbase + OQL + off);
        }
#pragma unroll
        for (int nf = 0; nf < 8; nf++) {
            acc[nf][0] = acc[nf][1] = acc[nf][2] = acc[nf][3] = 0.f;
            int rb = (nf << 3) + (lane & 7);
            int swb = (rb >> 1) & 3;
#pragma unroll
            for (int k2 = 0; k2 < 2; k2++) {
                uint32_t off = (uint32_t)((rb << 6) +
                    (((((lane >> 3) & 1) + (k2 << 1)) ^ swb) << 4));
                uint32_t bh[2], bl[2];
                LDSM2(bh, sbase + OKH + off);
                LDSM2(bl, sbase + OKL + off);
                MMA16816(acc[nf], ah[k2], bh);
                MMA16816(acc[nf], ah[k2], bl);
                MMA16816(acc[nf], al[k2], bh);
            }
        }
    }

    // ---- add rpb + mask per fragment (gmem, L2-resident)
    {
        const float* rrow = g_rpb + (size_t)h * NTOK * NTOK;
        const float* mrow = mask + (size_t)(b & (NWIN - 1)) * NTOK * NTOK;
        int r0 = (warp << 4) + qr;
#pragma unroll
        for (int nf = 0; nf < 8; nf++) {
            int col = (nf << 3) + qc;
            float2 rb0 = *(const float2*)(rrow + r0 * 64 + col);
            float2 mk0 = *(const float2*)(mrow + r0 * 64 + col);
            float2 rb1 = *(const float2*)(rrow + (r0 + 8) * 64 + col);
            float2 mk1 = *(const float2*)(mrow + (r0 + 8) * 64 + col);
            acc[nf][0] += rb0.x + mk0.x;
            acc[nf][1] += rb0.y + mk0.y;
            acc[nf][2] += rb1.x + mk1.x;
            acc[nf][3] += rb1.y + mk1.y;
        }
    }

    // ---- softmax in registers: rows r0 (elems 0,1) and r0+8 (elems 2,3),
    //      each row spread over 4 lanes (quad) -> 2 shfl reductions
    {
        float mx0 = -1e30f, mx1 = -1e30f;
#pragma unroll
        for (int nf = 0; nf < 8; nf++) {
            mx0 = fmaxf(mx0, fmaxf(acc[nf][0], acc[nf][1]));
            mx1 = fmaxf(mx1, fmaxf(acc[nf][2], acc[nf][3]));
        }
        mx0 = fmaxf(mx0, __shfl_xor_sync(0xffffffffu, mx0, 1));
        mx0 = fmaxf(mx0, __shfl_xor_sync(0xffffffffu, mx0, 2));
        mx1 = fmaxf(mx1, __shfl_xor_sync(0xffffffffu, mx1, 1));
        mx1 = fmaxf(mx1, __shfl_xor_sync(0xffffffffu, mx1, 2));
        float s0 = 0.f, s1 = 0.f;
#pragma unroll
        for (int nf = 0; nf < 8; nf++) {
            acc[nf][0] = expf(acc[nf][0] - mx0);
            acc[nf][1] = expf(acc[nf][1] - mx0);
            acc[nf][2] = expf(acc[nf][2] - mx1);
            acc[nf][3] = expf(acc[nf][3] - mx1);
            s0 += acc[nf][0] + acc[nf][1];
            s1 += acc[nf][2] + acc[nf][3];
        }
        s0 += __shfl_xor_sync(0xffffffffu, s0, 1);
        s0 += __shfl_xor_sync(0xffffffffu, s0, 2);
        s1 += __shfl_xor_sync(0xffffffffu, s1, 1);
        s1 += __shfl_xor_sync(0xffffffffu, s1, 2);
        float i0 = 1.0f / s0, i1 = 1.0f / s1;
#pragma unroll
        for (int nf = 0; nf < 8; nf++) {
            acc[nf][0] *= i0; acc[nf][1] *= i0;
            acc[nf][2] *= i1; acc[nf][3] *= i1;
        }
    }

    // ---- O = (Ph+Pl) Vh: S-accumulator fragments ARE P A-fragments
    {
        float oacc[4][4];
#pragma unroll
        for (int nf = 0; nf < 4; nf++)
#pragma unroll
            for (int e = 0; e < 4; e++) oacc[nf][e] = 0.f;
#pragma unroll
        for (int ks = 0; ks < 4; ks++) {
            uint32_t pah[4], pal[4];
            split2h(acc[2 * ks][0],     acc[2 * ks][1],     pah[0], pal[0]);
            split2h(acc[2 * ks][2],     acc[2 * ks][3],     pah[1], pal[1]);
            split2h(acc[2 * ks + 1][0], acc[2 * ks + 1][1], pah[2], pal[2]);
            split2h(acc[2 * ks + 1][2], acc[2 * ks + 1][3], pah[3], pal[3]);
#pragma unroll
            for (int nf = 0; nf < 4; nf++) {
                int rv = (nf << 3) + (lane & 7);
                int swv = rv & 7;
                uint32_t offv = (uint32_t)((rv << 7) +
                    (((((lane >> 3) & 1) + (ks << 1)) ^ swv) << 4));
                uint32_t vh[2];
                LDSM2(vh, sbase + OVT + offv);
                MMAH16816(oacc[nf], pah, vh);
                MMAH16816(oacc[nf], pal, vh);
            }
        }
#pragma unroll
        for (int nf = 0; nf < 4; nf++) {
#pragma unroll
            for (int e = 0; e < 2; e++) {
                int row = (warp << 4) + qr + (e << 3);
                int col = (nf << 3) + qc;
                size_t idx = (size_t)(b * NTOK + row) * DIMC + h * HD + col;
                __half2 hh;
                hh.x = __float2half_rn(oacc[nf][e * 2]);
                hh.y = __float2half_rn(oacc[nf][e * 2 + 1]);
                *(__half2*)(g_attn + idx) = hh;
            }
        }
    }
}

// ---------------- launcher ----------------
extern "C" void kernel_launch(void* const* d_in, const int* in_sizes, int n_in,
                              void* d_out, int out_size) {
    (void)in_sizes; (void)n_in; (void)out_size;
    const float* x           = (const float*)d_in[0];
    const float* mask        = (const float*)d_in[1];
    const float* qkv_w       = (const float*)d_in[2];
    const float* q_bias      = (const float*)d_in[3];
    const float* v_bias      = (const float*)d_in[4];
    const float* logit_scale = (const float*)d_in[5];
    const float* cpb_w1      = (const float*)d_in[6];
    const float* cpb_b1      = (const float*)d_in[7];
    const float* cpb_w2      = (const float*)d_in[8];
    const float* proj_w      = (const float*)d_in[9];
    const float* proj_b      = (const float*)d_in[10];
    float* out = (float*)d_out;

    float* p_qkvb;
    __half *p_v, *p_x, *p_attn, *p_wq, *p_wp;
    __nv_bfloat16 *p_qh, *p_ql, *p_kh, *p_kl;
    cudaGetSymbolAddress((void**)&p_qkvb, g_qkv_bias);
    cudaGetSymbolAddress((void**)&p_v,    g_v);
    cudaGetSymbolAddress((void**)&p_x,    g_x);
    cudaGetSymbolAddress((void**)&p_attn, g_attn);
    cudaGetSymbolAddress((void**)&p_wq,   g_wqkv);
    cudaGetSymbolAddress((void**)&p_wp,   g_wproj);
    cudaGetSymbolAddress((void**)&p_qh,   g_q_hi);
    cudaGetSymbolAddress((void**)&p_ql,   g_q_lo);
    cudaGetSymbolAddress((void**)&p_kh,   g_k_hi);
    cudaGetSymbolAddress((void**)&p_kl,   g_k_lo);

    cudaFuncSetAttribute(gemm_mma, cudaFuncAttributeMaxDynamicSharedMemorySize, GSMEM);
    cudaFuncSetAttribute(k_attn,   cudaFuncAttributeMaxDynamicSharedMemorySize, ATT_SMEM);

    k_make_qkv_bias<<<3, 512>>>(q_bias, v_bias);
    k_cpb<<<225, CPBH>>>(cpb_w1, cpb_b1, cpb_w2);
    k_rpb<<<64, 1024>>>();

    k_cvt<<<(NROWS * DIMC / 4 + 255) / 256, 256>>>(x, p_x, NROWS * DIMC / 4);
    k_w_t<<<(QKVC * DIMC + 255) / 256, 256>>>(qkv_w, p_wq, DIMC, QKVC);
    k_w_t<<<(DIMC * DIMC + 255) / 256, 256>>>(proj_w, p_wp, DIMC, DIMC);

    // QKV GEMM (1-product fp16) with fused normalize/scale epilogue
    gemm_mma<<<dim3(QKVC / 128, NROWS / 128), 256, GSMEM>>>(
        p_x, p_wq, p_qkvb, nullptr,
        p_qh, p_ql, p_kh, p_kl, p_v, logit_scale, 1, NROWS, QKVC, DIMC);

    // fused attention (register-resident softmax/P, no post-load barriers)
    k_attn<<<dim3(NHEADS, BWIN), 128, ATT_SMEM>>>(mask, logit_scale);

    // proj GEMM (1-product fp16) -> d_out
    gemm_mma<<<dim3(DIMC / 128, NROWS / 128), 256, GSMEM>>>(
        p_attn, p_wp, proj_b, out,
        nullptr, nullptr, nullptr, nullptr, nullptr, nullptr, 0, NROWS, DIMC, DIMC);
}

// round 17
// speedup vs baseline: 5.3377x; 1.0208x over previous
#include <cuda_runtime.h>
#include <cuda_bf16.h>
#include <cuda_fp16.h>
#include <cstdint>
#include <math.h>

// ---------------- problem constants ----------------
#define DIMC   512
#define NHEADS 16
#define HD     32
#define NTOK   64
#define BWIN   1024
#define NWIN   64
#define CPBH   512
#define NROWS  (BWIN * NTOK)          /* 65536 */
#define QKVC   (3 * DIMC)             /* 1536  */

// ---------------- device scratch (no allocs allowed) ----------------
__device__ __nv_bfloat16 g_q_hi[NROWS * DIMC];   // normalized*scale q, bf16 hi/lo
__device__ __nv_bfloat16 g_q_lo[NROWS * DIMC];
__device__ __nv_bfloat16 g_k_hi[NROWS * DIMC];   // normalized k
__device__ __nv_bfloat16 g_k_lo[NROWS * DIMC];
__device__ __half g_v[NROWS * DIMC];             // v fp16 (single)
__device__ __half g_x[NROWS * DIMC];             // x fp16 (single)
__device__ __half g_attn[NROWS * DIMC];          // attention out fp16 (single)
__device__ __half g_wqkv[QKVC * DIMC];           // [N=1536, K=512] transposed, fp16
__device__ __half g_wproj[DIMC * DIMC];          // [N=512, K=512] transposed, fp16
__device__ float g_bias_table[225 * NHEADS];
__device__ float g_rpb[NHEADS * NTOK * NTOK];
__device__ float g_qkv_bias[QKVC];

// ---------------- mma.sync helpers (arch-agnostic PTX) ----------------
#define LDSM4(R, addr)                                                        \
    asm volatile("ldmatrix.sync.aligned.m8n8.x4.shared.b16 {%0,%1,%2,%3},[%4];" \
                 : "=r"((R)[0]), "=r"((R)[1]), "=r"((R)[2]), "=r"((R)[3])     \
                 : "r"(addr))
#define LDSM2(R, addr)                                                        \
    asm volatile("ldmatrix.sync.aligned.m8n8.x2.shared.b16 {%0,%1},[%2];"     \
                 : "=r"((R)[0]), "=r"((R)[1]) : "r"(addr))
#define LDSM2T(R, addr)                                                       \
    asm volatile("ldmatrix.sync.aligned.m8n8.x2.trans.shared.b16 {%0,%1},[%2];" \
                 : "=r"((R)[0]), "=r"((R)[1]) : "r"(addr))
#define MMA16816(D, A, B)                                                     \
    asm volatile("mma.sync.aligned.m16n8k16.row.col.f32.bf16.bf16.f32 "       \
                 "{%0,%1,%2,%3},{%4,%5,%6,%7},{%8,%9},{%0,%1,%2,%3};"         \
                 : "+f"((D)[0]), "+f"((D)[1]), "+f"((D)[2]), "+f"((D)[3])     \
                 : "r"((A)[0]), "r"((A)[1]), "r"((A)[2]), "r"((A)[3]),        \
                   "r"((B)[0]), "r"((B)[1]))
#define MMAH16816(D, A, B)                                                    \
    asm volatile("mma.sync.aligned.m16n8k16.row.col.f32.f16.f16.f32 "         \
                 "{%0,%1,%2,%3},{%4,%5,%6,%7},{%8,%9},{%0,%1,%2,%3};"         \
                 : "+f"((D)[0]), "+f"((D)[1]), "+f"((D)[2]), "+f"((D)[3])     \
                 : "r"((A)[0]), "r"((A)[1]), "r"((A)[2]), "r"((A)[3]),        \
                   "r"((B)[0]), "r"((B)[1]))
#define CP16(dst, src)                                                        \
    asm volatile("cp.async.cg.shared.global [%0],[%1],16;" :: "r"(dst), "l"(src))
#define CPCOMMIT() asm volatile("cp.async.commit_group;")
#define CPWAIT(n)  asm volatile("cp.async.wait_group %0;" :: "n"(n))

__device__ __forceinline__ uint32_t smem_u32(const void* p) {
    uint32_t a;
    asm("{ .reg .u64 t; cvta.to.shared.u64 t, %1; cvt.u32.u64 %0, t; }" : "=r"(a) : "l"(p));
    return a;
}

// pack two fp32 into fp16x2 hi and residual lo
__device__ __forceinline__ void split2h(float a, float b, uint32_t& hi, uint32_t& lo) {
    __half2 h, l;
    h.x = __float2half_rn(a);
    h.y = __float2half_rn(b);
    l.x = __float2half_rn(a - __half2float(h.x));
    l.y = __float2half_rn(b - __half2float(h.y));
    hi = *(uint32_t*)&h;
    lo = *(uint32_t*)&l;
}

// ---------------- fused setup: x->fp16, weight transposes, qkv bias ----------------
// grid partition: [0,32768) cvt x ; [32768,35840) qkv_w^T ; [35840,36864) proj_w^T ;
// [36864,36870) bias
__global__ void k_setup(const float* __restrict__ x,
                        const float* __restrict__ qkv_w,
                        const float* __restrict__ proj_w,
                        const float* __restrict__ qb,
                        const float* __restrict__ vb) {
    int blk = blockIdx.x;
    if (blk < 32768) {
        int i = blk * 256 + threadIdx.x;           // n4 = 8388608, exact
        float4 v = *(const float4*)(x + (size_t)i * 4);
        __half2 a, b;
        a.x = __float2half_rn(v.x); a.y = __float2half_rn(v.y);
        b.x = __float2half_rn(v.z); b.y = __float2half_rn(v.w);
        *(__half2*)(g_x + (size_t)i * 4)     = a;
        *(__half2*)(g_x + (size_t)i * 4 + 2) = b;
    } else if (blk < 35840) {
        int i = (blk - 32768) * 256 + threadIdx.x; // 786432, exact
        int n = i / DIMC, k = i - n * DIMC;
        g_wqkv[i] = __float2half_rn(qkv_w[(size_t)k * QKVC + n]);
    } else if (blk < 36864) {
        int i = (blk - 35840) * 256 + threadIdx.x; // 262144, exact
        int n = i / DIMC, k = i - n * DIMC;
        g_wproj[i] = __float2half_rn(proj_w[(size_t)k * DIMC + n]);
    } else {
        int i = (blk - 36864) * 256 + threadIdx.x;
        if (i < QKVC) {
            float v = 0.f;
            if (i < DIMC)            v = qb[i];
            else if (i >= 2 * DIMC)  v = vb[i - 2 * DIMC];
            g_qkv_bias[i] = v;
        }
    }
}

// ---------------- CPB / RPB ----------------
__device__ __forceinline__ float cpb_coord(int u) {
    float t = (float)u * (8.0f / 7.0f);
    float s = (t > 0.f) ? 1.f : ((t < 0.f) ? -1.f : 0.f);
    return s * log2f(fabsf(t) + 1.0f) * (1.0f / 3.0f);
}

__global__ void k_cpb(const float* __restrict__ w1, const float* __restrict__ b1,
                      const float* __restrict__ w2) {
    __shared__ float hid[CPBH];
    int m = blockIdx.x;
    int k = threadIdx.x;
    float c0 = cpb_coord(m % 15 - 7);
    float c1 = cpb_coord(m / 15 - 7);
    hid[k] = fmaxf(fmaf(c0, w1[k], fmaf(c1, w1[CPBH + k], b1[k])), 0.f);
    __syncthreads();
    int warp = k >> 5, lane = k & 31;
    float s = 0.f;
    for (int kk = lane; kk < CPBH; kk += 32)
        s = fmaf(hid[kk], w2[kk * NHEADS + warp], s);
#pragma unroll
    for (int o = 16; o > 0; o >>= 1) s += __shfl_xor_sync(0xffffffffu, s, o);
    if (lane == 0) g_bias_table[m * NHEADS + warp] = s;
}

__global__ void k_rpb() {
    int id = blockIdx.x * blockDim.x + threadIdx.x;
    int h = id >> 12;
    int p = (id >> 6) & 63;
    int q = id & 63;
    int idx = (((p & 7) - (q & 7)) + 7) * 15 + (((p >> 3) - (q >> 3)) + 7);
    float v = g_bias_table[idx * NHEADS + h];
    g_rpb[id] = 16.0f / (1.0f + expf(-v));
}

// ---------------- fp16 HMMA GEMM, 3-stage cp.async ----------------
#define GSMEM (3 * 2 * 8192)

__global__ __launch_bounds__(256) void gemm_mma(
    const __half* __restrict__ A, const __half* __restrict__ B,
    const float* __restrict__ bias, float* __restrict__ C,
    __nv_bfloat16* __restrict__ qh, __nv_bfloat16* __restrict__ ql,
    __nv_bfloat16* __restrict__ kh, __nv_bfloat16* __restrict__ kl,
    __half* __restrict__ vout, const float* __restrict__ lsc,
    int fuse, int M, int N, int K) {
    extern __shared__ char gsm[];
    const uint32_t sb = smem_u32(gsm);

    const int tid  = threadIdx.x;
    const int lane = tid & 31;
    const int warp = tid >> 5;
    const int wm = (warp >> 2) << 6;
    const int wn = (warp & 3) << 5;
    const int row0 = blockIdx.y * 128;
    const int col0 = blockIdx.x * 128;

    const __half* src[2] = {A + (size_t)row0 * K, B + (size_t)col0 * K};

    const int r_g  = tid >> 2;
    const int r_g2 = r_g + 64;
    const int c_g  = tid & 3;
    const uint32_t dst1 = (uint32_t)((r_g  << 6) + ((c_g ^ ((r_g  >> 1) & 3)) << 4));
    const uint32_t dst2 = (uint32_t)((r_g2 << 6) + ((c_g ^ ((r_g2 >> 1) & 3)) << 4));

    uint32_t offA[4][2], offB[4][2];
#pragma unroll
    for (int mf = 0; mf < 4; mf++) {
        int r = wm + (mf << 4) + (lane & 15);
#pragma unroll
        for (int k2 = 0; k2 < 2; k2++) {
            int c16 = (lane >> 4) + (k2 << 1);
            offA[mf][k2] = (uint32_t)((r << 6) + ((c16 ^ ((r >> 1) & 3)) << 4));
        }
    }
#pragma unroll
    for (int nf = 0; nf < 4; nf++) {
        int r = wn + (nf << 3) + (lane & 7);
#pragma unroll
        for (int k2 = 0; k2 < 2; k2++) {
            int c16 = ((lane >> 3) & 1) + (k2 << 1);
            offB[nf][k2] = (uint32_t)((r << 6) + ((c16 ^ ((r >> 1) & 3)) << 4));
        }
    }

    float acc[4][4][4];
#pragma unroll
    for (int mf = 0; mf < 4; mf++)
#pragma unroll
        for (int nf = 0; nf < 4; nf++)
#pragma unroll
            for (int e = 0; e < 4; e++) acc[mf][nf][e] = 0.f;

    const int nchunks = K >> 5;     // 16

    auto issue = [&](int stage, int kc) {
#pragma unroll
        for (int a = 0; a < 2; a++) {
            uint32_t base = sb + (uint32_t)(((stage << 1) + a) << 13);
            const char* g1 = (const char*)(src[a] + (size_t)r_g  * K + (kc << 5) + (c_g << 3));
            const char* g2 = (const char*)(src[a] + (size_t)r_g2 * K + (kc << 5) + (c_g << 3));
            CP16(base + dst1, g1);
            CP16(base + dst2, g2);
        }
        CPCOMMIT();
    };

    issue(0, 0);
    issue(1, 1);
    int stage = 0;
    for (int kc = 0; kc < nchunks; kc++) {
        if (kc == nchunks - 1) { CPWAIT(0); } else { CPWAIT(1); }
        __syncthreads();

        const uint32_t st = sb + (uint32_t)(stage * 16384);
#pragma unroll
        for (int k2 = 0; k2 < 2; k2++) {
            uint32_t ah[4][4], bh[4][2];
#pragma unroll
            for (int mf = 0; mf < 4; mf++)
                LDSM4(ah[mf], st + offA[mf][k2]);
#pragma unroll
            for (int nf = 0; nf < 4; nf++)
                LDSM2(bh[nf], st + 8192 + offB[nf][k2]);
#pragma unroll
            for (int mf = 0; mf < 4; mf++)
#pragma unroll
                for (int nf = 0; nf < 4; nf++)
                    MMAH16816(acc[mf][nf], ah[mf], bh[nf]);
        }
        if (kc + 2 < nchunks) {
            int tgt = stage + 2;
            if (tgt >= 3) tgt -= 3;
            issue(tgt, kc + 2);
        }
        stage = (stage == 2) ? 0 : stage + 1;
    }

    const int qr = lane >> 2;
    const int qc = (lane & 3) << 1;

#pragma unroll
    for (int nf = 0; nf < 4; nf++) {
        float2 bi = *(const float2*)(bias + col0 + wn + (nf << 3) + qc);
#pragma unroll
        for (int mf = 0; mf < 4; mf++) {
            acc[mf][nf][0] += bi.x; acc[mf][nf][1] += bi.y;
            acc[mf][nf][2] += bi.x; acc[mf][nf][3] += bi.y;
        }
    }

    if (!fuse) {
#pragma unroll
        for (int mf = 0; mf < 4; mf++)
#pragma unroll
            for (int nf = 0; nf < 4; nf++) {
                int row = row0 + wm + (mf << 4) + qr;
                int col = col0 + wn + (nf << 3) + qc;
                *(float2*)(C + (size_t)row * N + col) =
                    make_float2(acc[mf][nf][0], acc[mf][nf][1]);
                *(float2*)(C + (size_t)(row + 8) * N + col) =
                    make_float2(acc[mf][nf][2], acc[mf][nf][3]);
            }
        return;
    }

    const int sec = blockIdx.x >> 2;          // 0=q, 1=k, 2=v
    if (sec < 2) {
        float scale = 1.f;
        if (sec == 0) {
            int h = (col0 + wn) >> 5;          // warp covers exactly one head
            scale = expf(fminf(lsc[h], 4.6051701860f));
        }
#pragma unroll
        for (int mf = 0; mf < 4; mf++) {
#pragma unroll
            for (int e = 0; e < 2; e++) {
                float ss = 0.f;
#pragma unroll
                for (int nf = 0; nf < 4; nf++) {
                    float a0 = acc[mf][nf][e * 2], a1 = acc[mf][nf][e * 2 + 1];
                    ss = fmaf(a0, a0, fmaf(a1, a1, ss));
                }
                ss += __shfl_xor_sync(0xffffffffu, ss, 1);
                ss += __shfl_xor_sync(0xffffffffu, ss, 2);
                float inv = rsqrtf(ss) * scale;
                int row = row0 + wm + (mf << 4) + (e << 3) + qr;
#pragma unroll
                for (int nf = 0; nf < 4; nf++) {
                    int col = col0 + wn + (nf << 3) + qc - sec * 512;
                    float v0 = acc[mf][nf][e * 2] * inv;
                    float v1 = acc[mf][nf][e * 2 + 1] * inv;
                    __nv_bfloat162 hh, ll;
                    hh.x = __float2bfloat16(v0);
                    hh.y = __float2bfloat16(v1);
                    ll.x = __float2bfloat16(v0 - __bfloat162float(hh.x));
                    ll.y = __float2bfloat16(v1 - __bfloat162float(hh.y));
                    size_t idx = (size_t)row * DIMC + col;
                    if (sec == 0) {
                        *(__nv_bfloat162*)(qh + idx) = hh;
                        *(__nv_bfloat162*)(ql + idx) = ll;
                    } else {
                        *(__nv_bfloat162*)(kh + idx) = hh;
                        *(__nv_bfloat162*)(kl + idx) = ll;
                    }
                }
            }
        }
    } else {
#pragma unroll
        for (int mf = 0; mf < 4; mf++)
#pragma unroll
            for (int nf = 0; nf < 4; nf++) {
                int row = row0 + wm + (mf << 4) + qr;
                int col = col0 + wn + (nf << 3) + qc - 1024;
                __half2 a0, a1;
                a0.x = __float2half_rn(acc[mf][nf][0]);
                a0.y = __float2half_rn(acc[mf][nf][1]);
                a1.x = __float2half_rn(acc[mf][nf][2]);
                a1.y = __float2half_rn(acc[mf][nf][3]);
                *(__half2*)(vout + (size_t)row * DIMC + col)       = a0;
                *(__half2*)(vout + (size_t)(row + 8) * DIMC + col) = a1;
            }
    }
}

// ---------------- fused attention: register softmax + trans-ldmatrix V ----------------
// smem: QK bf16 hi/lo tiles 16KB + V fp16 [64 tok][40 halves] 5KB = 21.1KB.
// ONE barrier total; V B-fragments loaded directly via ldmatrix.x2.trans.
#define OQH 0
#define OQL 4096
#define OKH 8192
#define OKL 12288
#define OVV 16384                   /* V fp16 staging [64 tok][40 halves] */
#define ATT_SMEM (16384 + 64 * 80)  /* 21504 */

__global__ __launch_bounds__(128) void k_attn(const float* __restrict__ mask,
                                              const float* __restrict__ logit_scale) {
    extern __shared__ char sm[];
    const int h = blockIdx.x;
    const int b = blockIdx.y;
    const int tid = threadIdx.x, lane = tid & 31, warp = tid >> 5;
    const uint32_t sbase = smem_u32(sm);
    (void)logit_scale;

    const size_t rowbase = (size_t)(b * NTOK) * DIMC + (size_t)h * HD;

    // ---- cp.async: q/k (bf16 hi/lo, pre-normalized) into swizzled tiles
#pragma unroll
    for (int i = tid; i < 256; i += 128) {
        int tok = i >> 2, c = i & 3;
        int swz = (tok >> 1) & 3;
        uint32_t d = (uint32_t)((tok << 6) + ((c ^ swz) << 4));
        size_t g = rowbase + (size_t)tok * DIMC + (c << 3);
        CP16(sbase + OQH + d, (const char*)(g_q_hi + g));
        CP16(sbase + OQL + d, (const char*)(g_q_lo + g));
        CP16(sbase + OKH + d, (const char*)(g_k_hi + g));
        CP16(sbase + OKL + d, (const char*)(g_k_lo + g));
    }
    // ---- cp.async: V fp16 staged [tok][40 halves] (80B stride)
#pragma unroll
    for (int i = tid; i < 256; i += 128) {
        int tok = i >> 2, c = i & 3;
        CP16(sbase + OVV + tok * 80 + (c << 4),
             (const char*)(g_v + rowbase + (size_t)tok * DIMC + (c << 3)));
    }
    CPCOMMIT(); CPWAIT(0);
    __syncthreads();   // the only barrier

    const int qr = lane >> 2;
    const int qc = (lane & 3) << 1;

    // ---- S = qn kn^T (bf16 3-product), fragments stay in registers
    float acc[8][4];
    {
        uint32_t ah[2][4], al[2][4];
        int ra = (warp << 4) + (lane & 15);
        int ca = lane >> 4;
        int swa = (ra >> 1) & 3;
#pragma unroll
        for (int k2 = 0; k2 < 2; k2++) {
            uint32_t off = (uint32_t)((ra << 6) + (((ca + (k2 << 1)) ^ swa) << 4));
            LDSM4(ah[k2], sbase + OQH + off);
            LDSM4(al[k2], sbase + OQL + off);
        }
#pragma unroll
        for (int nf = 0; nf < 8; nf++) {
            acc[nf][0] = acc[nf][1] = acc[nf][2] = acc[nf][3] = 0.f;
            int rb = (nf << 3) + (lane & 7);
            int swb = (rb >> 1) & 3;
#pragma unroll
            for (int k2 = 0; k2 < 2; k2++) {
                uint32_t off = (uint32_t)((rb << 6) +
                    (((((lane >> 3) & 1) + (k2 << 1)) ^ swb) << 4));
                uint32_t bh[2], bl[2];
                LDSM2(bh, sbase + OKH + off);
                LDSM2(bl, sbase + OKL + off);
                MMA16816(acc[nf], ah[k2], bh);
                MMA16816(acc[nf], ah[k2], bl);
                MMA16816(acc[nf], al[k2], bh);
            }
        }
    }

    // ---- add rpb + mask per fragment (gmem, L2-resident)
    {
        const float* rrow = g_rpb + (size_t)h * NTOK * NTOK;
        const float* mrow = mask + (size_t)(b & (NWIN - 1)) * NTOK * NTOK;
        int r0 = (warp << 4) + qr;
#pragma unroll
        for (int nf = 0; nf < 8; nf++) {
            int col = (nf << 3) + qc;
            float2 rb0 = *(const float2*)(rrow + r0 * 64 + col);
            float2 mk0 = *(const float2*)(mrow + r0 * 64 + col);
            float2 rb1 = *(const float2*)(rrow + (r0 + 8) * 64 + col);
            float2 mk1 = *(const float2*)(mrow + (r0 + 8) * 64 + col);
            acc[nf][0] += rb0.x + mk0.x;
            acc[nf][1] += rb0.y + mk0.y;
            acc[nf][2] += rb1.x + mk1.x;
            acc[nf][3] += rb1.y + mk1.y;
        }
    }

    // ---- softmax in registers (quad shfl reductions)
    {
        float mx0 = -1e30f, mx1 = -1e30f;
#pragma unroll
        for (int nf = 0; nf < 8; nf++) {
            mx0 = fmaxf(mx0, fmaxf(acc[nf][0], acc[nf][1]));
            mx1 = fmaxf(mx1, fmaxf(acc[nf][2], acc[nf][3]));
        }
        mx0 = fmaxf(mx0, __shfl_xor_sync(0xffffffffu, mx0, 1));
        mx0 = fmaxf(mx0, __shfl_xor_sync(0xffffffffu, mx0, 2));
        mx1 = fmaxf(mx1, __shfl_xor_sync(0xffffffffu, mx1, 1));
        mx1 = fmaxf(mx1, __shfl_xor_sync(0xffffffffu, mx1, 2));
        float s0 = 0.f, s1 = 0.f;
#pragma unroll
        for (int nf = 0; nf < 8; nf++) {
            acc[nf][0] = expf(acc[nf][0] - mx0);
            acc[nf][1] = expf(acc[nf][1] - mx0);
            acc[nf][2] = expf(acc[nf][2] - mx1);
            acc[nf][3] = expf(acc[nf][3] - mx1);
            s0 += acc[nf][0] + acc[nf][1];
            s1 += acc[nf][2] + acc[nf][3];
        }
        s0 += __shfl_xor_sync(0xffffffffu, s0, 1);
        s0 += __shfl_xor_sync(0xffffffffu, s0, 2);
        s1 += __shfl_xor_sync(0xffffffffu, s1, 1);
        s1 += __shfl_xor_sync(0xffffffffu, s1, 2);
        float i0 = 1.0f / s0, i1 = 1.0f / s1;
#pragma unroll
        for (int nf = 0; nf < 8; nf++) {
            acc[nf][0] *= i0; acc[nf][1] *= i0;
            acc[nf][2] *= i1; acc[nf][3] *= i1;
        }
    }

    // ---- O = (Ph+Pl) V: P from S-fragments; V B-frags via ldmatrix.trans
    {
        float oacc[4][4];
#pragma unroll
        for (int nf = 0; nf < 4; nf++)
#pragma unroll
            for (int e = 0; e < 4; e++) oacc[nf][e] = 0.f;
#pragma unroll
        for (int ks = 0; ks < 4; ks++) {
            uint32_t pah[4], pal[4];
            split2h(acc[2 * ks][0],     acc[2 * ks][1],     pah[0], pal[0]);
            split2h(acc[2 * ks][2],     acc[2 * ks][3],     pah[1], pal[1]);
            split2h(acc[2 * ks + 1][0], acc[2 * ks + 1][1], pah[2], pal[2]);
            split2h(acc[2 * ks + 1][2], acc[2 * ks + 1][3], pah[3], pal[3]);
            // V rows tok = ks*16 + (lane&15), 16B row segment at col d0
            uint32_t vrow = sbase + OVV + (uint32_t)(((ks << 4) + (lane & 15)) * 80);
#pragma unroll
            for (int nf = 0; nf < 4; nf++) {
                uint32_t vh[2];
                LDSM2T(vh, vrow + (nf << 4));      // d0 = nf*8 halves = nf*16 bytes
                MMAH16816(oacc[nf], pah, vh);
                MMAH16816(oacc[nf], pal, vh);
            }
        }
#pragma unroll
        for (int nf = 0; nf < 4; nf++) {
#pragma unroll
            for (int e = 0; e < 2; e++) {
                int row = (warp << 4) + qr + (e << 3);
                int col = (nf << 3) + qc;
                size_t idx = (size_t)(b * NTOK + row) * DIMC + h * HD + col;
                __half2 hh;
                hh.x = __float2half_rn(oacc[nf][e * 2]);
                hh.y = __float2half_rn(oacc[nf][e * 2 + 1]);
                *(__half2*)(g_attn + idx) = hh;
            }
        }
    }
}

// ---------------- launcher ----------------
extern "C" void kernel_launch(void* const* d_in, const int* in_sizes, int n_in,
                              void* d_out, int out_size) {
    (void)in_sizes; (void)n_in; (void)out_size;
    const float* x           = (const float*)d_in[0];
    const float* mask        = (const float*)d_in[1];
    const float* qkv_w       = (const float*)d_in[2];
    const float* q_bias      = (const float*)d_in[3];
    const float* v_bias      = (const float*)d_in[4];
    const float* logit_scale = (const float*)d_in[5];
    const float* cpb_w1      = (const float*)d_in[6];
    const float* cpb_b1      = (const float*)d_in[7];
    const float* cpb_w2      = (const float*)d_in[8];
    const float* proj_w      = (const float*)d_in[9];
    const float* proj_b      = (const float*)d_in[10];
    float* out = (float*)d_out;

    float* p_qkvb;
    __half *p_v, *p_x, *p_attn, *p_wq, *p_wp;
    __nv_bfloat16 *p_qh, *p_ql, *p_kh, *p_kl;
    cudaGetSymbolAddress((void**)&p_qkvb, g_qkv_bias);
    cudaGetSymbolAddress((void**)&p_v,    g_v);
    cudaGetSymbolAddress((void**)&p_x,    g_x);
    cudaGetSymbolAddress((void**)&p_attn, g_attn);
    cudaGetSymbolAddress((void**)&p_wq,   g_wqkv);
    cudaGetSymbolAddress((void**)&p_wp,   g_wproj);
    cudaGetSymbolAddress((void**)&p_qh,   g_q_hi);
    cudaGetSymbolAddress((void**)&p_ql,   g_q_lo);
    cudaGetSymbolAddress((void**)&p_kh,   g_k_hi);
    cudaGetSymbolAddress((void**)&p_kl,   g_k_lo);

    cudaFuncSetAttribute(gemm_mma, cudaFuncAttributeMaxDynamicSharedMemorySize, GSMEM);
    cudaFuncSetAttribute(k_attn,   cudaFuncAttributeMaxDynamicSharedMemorySize, ATT_SMEM);

    // fused setup (x cvt + both weight transposes + bias), all concurrent
    k_setup<<<36870, 256>>>(x, qkv_w, proj_w, q_bias, v_bias);
    k_cpb<<<225, CPBH>>>(cpb_w1, cpb_b1, cpb_w2);
    k_rpb<<<64, 1024>>>();

    // QKV GEMM (1-product fp16) with fused normalize/scale epilogue
    gemm_mma<<<dim3(QKVC / 128, NROWS / 128), 256, GSMEM>>>(
        p_x, p_wq, p_qkvb, nullptr,
        p_qh, p_ql, p_kh, p_kl, p_v, logit_scale, 1, NROWS, QKVC, DIMC);

    // fused attention (register softmax/P, trans-ldmatrix V, 1 barrier)
    k_attn<<<dim3(NHEADS, BWIN), 128, ATT_SMEM>>>(mask, logit_scale);

    // proj GEMM (1-product fp16) -> d_out
    gemm_mma<<<dim3(DIMC / 128, NROWS / 128), 256, GSMEM>>>(
        p_attn, p_wp, proj_b, out,
        nullptr, nullptr, nullptr, nullptr, nullptr, nullptr, 0, NROWS, DIMC, DIMC);
}